// round 1
// baseline (speedup 1.0000x reference)
#include <cuda_runtime.h>
#include <cuda_bf16.h>
#include <math.h>

// ---------------- problem constants ----------------
#define BATCH 4
#define CDIM  384
#define HDIM  128
#define WDIM  128
#define HWPIX 16384            // HDIM*WDIM
#define NPIX  65536            // BATCH*HWPIX
#define HEADS 12
#define HD    32
#define WS    8
#define NTOK  64               // WS*WS
#define NWIN  1024             // BATCH * (H/WS) * (W/WS)
#define QKVC  1152             // 3*CDIM

// ---------------- device scratch (static, allowed) ----------------
__device__ float g_qkv[(size_t)NPIX * QKVC];   // ~302 MB : per-pixel [q(384) k(384) v(384)]
__device__ float g_ao [(size_t)NPIX * CDIM];   // ~100 MB : attention output, pixel-major
__device__ float g_bias[HEADS * 225];          // relative-position bias per (head, dy+7, dx+7)
__device__ float g_Wc  [CDIM * CDIM];          // w_proj @ w_po

// =================================================================
// Kernel: compose Wc = w_proj @ w_po   (384x384x384, trivial)
// =================================================================
__global__ void wc_kernel(const float* __restrict__ w_proj,
                          const float* __restrict__ w_po) {
    int o = blockIdx.x;          // 384 blocks
    int c = threadIdx.x;         // 384 threads
    const float* pr = w_proj + o * CDIM;
    float acc = 0.f;
    for (int t = 0; t < CDIM; t++)
        acc += pr[t] * w_po[t * CDIM + c];
    g_Wc[o * CDIM + c] = acc;
}

// =================================================================
// Kernel: relative-position bias, only 225 distinct (dy,dx) pairs
// =================================================================
__global__ void bias_kernel(const float* __restrict__ pcw,
                            const float* __restrict__ psc,
                            const float* __restrict__ mw1,
                            const float* __restrict__ mb1,
                            const float* __restrict__ mw2,
                            const float* __restrict__ mb2) {
    __shared__ float rel[CDIM];
    __shared__ float hid[128];
    int idx = blockIdx.x;                    // 0..224
    float dx = (float)((idx % 15) - 7) * (2.0f / 7.0f);
    float dy = (float)((idx / 15) - 7) * (2.0f / 7.0f);
    int t = threadIdx.x;                     // 128
    float sc = psc[0];
    for (int c = t; c < CDIM; c += 128)
        rel[c] = sc * (pcw[2 * c] * dx + pcw[2 * c + 1] * dy);
    __syncthreads();
    float s = mb1[t];
    const float* w = mw1 + t * CDIM;
    #pragma unroll 8
    for (int c = 0; c < CDIM; c++) s += rel[c] * w[c];
    // exact gelu
    hid[t] = 0.5f * s * (1.0f + erff(s * 0.70710678118654752f));
    __syncthreads();
    if (t < HEADS) {
        float a = mb2[t];
        const float* w2 = mw2 + t * 128;
        #pragma unroll 8
        for (int j = 0; j < 128; j++) a += hid[j] * w2[j];
        g_bias[t * 225 + idx] = a;
    }
}

// =================================================================
// Kernel: QKV projection GEMM
//   A^T layout: x is (B, C, H, W) -> per batch, (k=c) x (m=pixel) contiguous in m
//   B: rows o of [w_qk ; w_v], row-major in k
//   out: g_qkv[p][o]
// BM=128, BN=128, BK=8, 256 threads, 8x8 per thread
// =================================================================
__global__ void __launch_bounds__(256) qkv_gemm(
        const float* __restrict__ x,
        const float* __restrict__ w_qk, const float* __restrict__ b_qk,
        const float* __restrict__ w_v,  const float* __restrict__ b_v) {
    __shared__ float As[8][128];
    __shared__ float Bs[8][132];
    int m0 = blockIdx.x * 128;
    int n0 = blockIdx.y * 128;
    int b  = m0 >> 14;
    int pp = m0 & (HWPIX - 1);
    const float* xb = x + (size_t)b * CDIM * HWPIX + pp;
    int tid = threadIdx.x;
    int tx = tid & 15, ty = tid >> 4;
    float acc[8][8];
    #pragma unroll
    for (int i = 0; i < 8; i++)
        #pragma unroll
        for (int j = 0; j < 8; j++) acc[i][j] = 0.f;

    for (int k0 = 0; k0 < CDIM; k0 += 8) {
        #pragma unroll
        for (int t = 0; t < 4; t++) {
            int idx = tid + t * 256;
            int kk = idx >> 7, mm = idx & 127;
            As[kk][mm] = xb[(size_t)(k0 + kk) * HWPIX + mm];
        }
        #pragma unroll
        for (int t = 0; t < 4; t++) {
            int idx = tid + t * 256;
            int kk = idx & 7, nn = idx >> 3;
            int o = n0 + nn;
            float wv = (o < 2 * CDIM) ? w_qk[o * CDIM + k0 + kk]
                                      : w_v[(o - 2 * CDIM) * CDIM + k0 + kk];
            Bs[kk][nn] = wv;
        }
        __syncthreads();
        #pragma unroll
        for (int kk = 0; kk < 8; kk++) {
            float a[8], bb[8];
            #pragma unroll
            for (int i = 0; i < 8; i++) a[i] = As[kk][ty * 8 + i];
            #pragma unroll
            for (int j = 0; j < 8; j++) bb[j] = Bs[kk][tx * 8 + j];
            #pragma unroll
            for (int i = 0; i < 8; i++)
                #pragma unroll
                for (int j = 0; j < 8; j++) acc[i][j] += a[i] * bb[j];
        }
        __syncthreads();
    }
    // epilogue: bias + store
    float biasv[8];
    #pragma unroll
    for (int j = 0; j < 8; j++) {
        int o = n0 + tx * 8 + j;
        biasv[j] = (o < 2 * CDIM) ? b_qk[o] : b_v[o - 2 * CDIM];
    }
    #pragma unroll
    for (int i = 0; i < 8; i++) {
        int p = m0 + ty * 8 + i;
        float* dst = g_qkv + (size_t)p * QKVC + n0 + tx * 8;
        float4 v0 = make_float4(acc[i][0] + biasv[0], acc[i][1] + biasv[1],
                                acc[i][2] + biasv[2], acc[i][3] + biasv[3]);
        float4 v1 = make_float4(acc[i][4] + biasv[4], acc[i][5] + biasv[5],
                                acc[i][6] + biasv[6], acc[i][7] + biasv[7]);
        *(float4*)dst       = v0;
        *(float4*)(dst + 4) = v1;
    }
}

// =================================================================
// PDSCA gate (in-place on xs, uses scr[2048] scratch + tiny smem)
// image mapping (torch raw reshape): channel c' = n>>1, spatial s = (n&1)*32 + d
// xs stride per token = 36 floats
// =================================================================
__device__ __forceinline__ void pdsca_gate(
        float* xs, float* scr, float* gap, float* hid, float* ca,
        const float* __restrict__ dw_w, const float* __restrict__ dw_b,
        const float* __restrict__ f1w,  const float* __restrict__ f1b,
        const float* __restrict__ f2w,  const float* __restrict__ f2b,
        int t) {
    // depthwise 3x3 (cross-correlation, zero pad)
    for (int idx = t; idx < 2048; idx += 128) {
        int c = idx >> 6, s = idx & 63, sy = s >> 3, sx = s & 7;
        float sum = dw_b[c];
        #pragma unroll
        for (int ky = 0; ky < 3; ky++) {
            int iy = sy + ky - 1;
            if (iy < 0 || iy > 7) continue;
            #pragma unroll
            for (int kx = 0; kx < 3; kx++) {
                int ix = sx + kx - 1;
                if (ix < 0 || ix > 7) continue;
                int s2 = iy * 8 + ix;
                sum += dw_w[c * 9 + ky * 3 + kx] *
                       xs[(2 * c + (s2 >> 5)) * 36 + (s2 & 31)];
            }
        }
        scr[idx] = sum;
    }
    // GAP per channel
    if (t < 32) {
        float s = 0.f;
        #pragma unroll
        for (int d = 0; d < 32; d++)
            s += xs[(2 * t) * 36 + d] + xs[(2 * t + 1) * 36 + d];
        gap[t] = s * (1.0f / 64.0f);
    }
    __syncthreads();
    if (t < 8) {
        float s = f1b[t];
        #pragma unroll
        for (int c = 0; c < 32; c++) s += gap[c] * f1w[t * 32 + c];
        hid[t] = fmaxf(s, 0.f);
    }
    __syncthreads();
    if (t < 32) {
        float s = f2b[t];
        #pragma unroll
        for (int j = 0; j < 8; j++) s += hid[j] * f2w[t * 8 + j];
        ca[t] = s;
    }
    __syncthreads();
    // sigmoid gate, in place
    for (int idx = t; idx < 2048; idx += 128) {
        int c = idx >> 6, s = idx & 63;
        float m = scr[idx] + ca[c];
        float g = 1.0f / (1.0f + expf(-m));
        xs[(2 * c + (s >> 5)) * 36 + (s & 31)] *= g;
    }
    __syncthreads();
}

// =================================================================
// Kernel: per-(window, head) PDSCA gating + attention
// 12288 blocks x 128 threads
// =================================================================
__global__ void __launch_bounds__(128) attn_kernel(
        const float* __restrict__ log_temp,
        const float* __restrict__ pqw,  const float* __restrict__ pqb,
        const float* __restrict__ pqf1w, const float* __restrict__ pqf1b,
        const float* __restrict__ pqf2w, const float* __restrict__ pqf2b,
        const float* __restrict__ pkw,  const float* __restrict__ pkb,
        const float* __restrict__ pkf1w, const float* __restrict__ pkf1b,
        const float* __restrict__ pkf2w, const float* __restrict__ pkf2b) {
    __shared__ __align__(16) float qs[NTOK * 36];
    __shared__ __align__(16) float ks[NTOK * 36];
    __shared__ __align__(16) float vs[NTOK * 36];
    __shared__ float at[NTOK * 65];   // attn scores; also reused as PDSCA scratch
    __shared__ float gap[32], hid[8], ca[32];

    int bi  = blockIdx.x;
    int win = bi / HEADS;
    int h   = bi - win * HEADS;
    int t   = threadIdx.x;
    int b   = win >> 8, hb = (win >> 4) & 15, wb = win & 15;
    int pbase = b * HWPIX + hb * 8 * WDIM + wb * 8;

    // ---- load q,k,v tiles (vectorized) ----
    for (int tt = t; tt < 512; tt += 128) {
        int n = tt >> 3, d4 = (tt & 7) * 4;
        int p = pbase + (n >> 3) * WDIM + (n & 7);
        const float* src = g_qkv + (size_t)p * QKVC + h * HD + d4;
        float4 qv = *(const float4*)(src);
        float4 kv = *(const float4*)(src + CDIM);
        float4 vv = *(const float4*)(src + 2 * CDIM);
        *(float4*)&qs[n * 36 + d4] = qv;
        *(float4*)&ks[n * 36 + d4] = kv;
        *(float4*)&vs[n * 36 + d4] = vv;
    }
    __syncthreads();

    // ---- PDSCA gates (scratch = at) ----
    pdsca_gate(qs, at, gap, hid, ca, pqw, pqb, pqf1w, pqf1b, pqf2w, pqf2b, t);
    pdsca_gate(ks, at, gap, hid, ca, pkw, pkb, pkf1w, pkf1b, pkf2w, pkf2b, t);

    // ---- attention scores ----
    float temp = expf(log_temp[0]);
    {
        int n = t >> 1, mb2 = (t & 1) * 32;
        float4 q[8];
        #pragma unroll
        for (int i = 0; i < 8; i++) q[i] = *(const float4*)&qs[n * 36 + 4 * i];
        const float* brow = g_bias + h * 225;
        int ny = n >> 3, nx = n & 7;
        for (int mm = 0; mm < 32; mm++) {
            int m = mb2 + mm;
            const float4* kp = (const float4*)&ks[m * 36];
            float dot = 0.f;
            #pragma unroll
            for (int i = 0; i < 8; i++) {
                float4 kk4 = kp[i];
                dot += q[i].x * kk4.x + q[i].y * kk4.y +
                       q[i].z * kk4.z + q[i].w * kk4.w;
            }
            int dy = ny - (m >> 3), dx = nx - (m & 7);
            at[n * 65 + m] = dot * temp + brow[(dy + 7) * 15 + (dx + 7)];
        }
    }
    __syncthreads();

    // ---- softmax (one row per thread) ----
    if (t < NTOK) {
        float* row = at + t * 65;
        float mx = -1e30f;
        #pragma unroll 8
        for (int m = 0; m < 64; m++) mx = fmaxf(mx, row[m]);
        float s = 0.f;
        #pragma unroll 8
        for (int m = 0; m < 64; m++) { float e = expf(row[m] - mx); row[m] = e; s += e; }
        float inv = 1.0f / s;
        #pragma unroll 8
        for (int m = 0; m < 64; m++) row[m] *= inv;
    }
    __syncthreads();

    // ---- out = attn @ v, write pixel-major g_ao ----
    for (int tt = t; tt < 512; tt += 128) {
        int n = tt >> 3, d4 = (tt & 7) * 4;
        const float* row = at + n * 65;
        float4 acc = make_float4(0.f, 0.f, 0.f, 0.f);
        #pragma unroll 8
        for (int m = 0; m < 64; m++) {
            float a = row[m];
            float4 vv = *(const float4*)&vs[m * 36 + d4];
            acc.x += a * vv.x; acc.y += a * vv.y;
            acc.z += a * vv.z; acc.w += a * vv.w;
        }
        int p = pbase + (n >> 3) * WDIM + (n & 7);
        *(float4*)(g_ao + (size_t)p * CDIM + h * HD + d4) = acc;
    }
}

// =================================================================
// Kernel: fused output projection GEMM
//   y[p][o] = sum_c g_ao[p][c] * Wc[o][c] + b_proj[o]
//   out layout (B, C, H, W)
// =================================================================
__global__ void __launch_bounds__(256) out_gemm(
        const float* __restrict__ b_proj, float* __restrict__ out) {
    __shared__ float As[8][132];
    __shared__ float Bs[8][132];
    int m0 = blockIdx.x * 128;
    int n0 = blockIdx.y * 128;
    int tid = threadIdx.x;
    int tx = tid & 15, ty = tid >> 4;
    float acc[8][8];
    #pragma unroll
    for (int i = 0; i < 8; i++)
        #pragma unroll
        for (int j = 0; j < 8; j++) acc[i][j] = 0.f;

    for (int k0 = 0; k0 < CDIM; k0 += 8) {
        #pragma unroll
        for (int t = 0; t < 4; t++) {
            int idx = tid + t * 256;
            int kk = idx & 7, mm = idx >> 3;
            As[kk][mm] = g_ao[(size_t)(m0 + mm) * CDIM + k0 + kk];
        }
        #pragma unroll
        for (int t = 0; t < 4; t++) {
            int idx = tid + t * 256;
            int kk = idx & 7, nn = idx >> 3;
            Bs[kk][nn] = g_Wc[(n0 + nn) * CDIM + k0 + kk];
        }
        __syncthreads();
        #pragma unroll
        for (int kk = 0; kk < 8; kk++) {
            float a[8], bb[8];
            #pragma unroll
            for (int i = 0; i < 8; i++) a[i] = As[kk][ty * 8 + i];
            #pragma unroll
            for (int j = 0; j < 8; j++) bb[j] = Bs[kk][tx * 8 + j];
            #pragma unroll
            for (int i = 0; i < 8; i++)
                #pragma unroll
                for (int j = 0; j < 8; j++) acc[i][j] += a[i] * bb[j];
        }
        __syncthreads();
    }
    int bb = m0 >> 14;
    int pp = m0 & (HWPIX - 1);
    #pragma unroll
    for (int j = 0; j < 8; j++) {
        int o = n0 + tx * 8 + j;
        float bp = b_proj[o];
        float* dst = out + ((size_t)(bb * CDIM + o)) * HWPIX + pp + ty * 8;
        float4 v0 = make_float4(acc[0][j] + bp, acc[1][j] + bp,
                                acc[2][j] + bp, acc[3][j] + bp);
        float4 v1 = make_float4(acc[4][j] + bp, acc[5][j] + bp,
                                acc[6][j] + bp, acc[7][j] + bp);
        *(float4*)dst       = v0;
        *(float4*)(dst + 4) = v1;
    }
}

// =================================================================
// launch
// =================================================================
extern "C" void kernel_launch(void* const* d_in, const int* in_sizes, int n_in,
                              void* d_out, int out_size) {
    const float* x        = (const float*)d_in[0];
    const float* w_qk     = (const float*)d_in[1];
    const float* b_qk     = (const float*)d_in[2];
    const float* w_v      = (const float*)d_in[3];
    const float* b_v      = (const float*)d_in[4];
    const float* log_temp = (const float*)d_in[5];
    const float* pq_dw_w  = (const float*)d_in[6];
    const float* pq_dw_b  = (const float*)d_in[7];
    const float* pq_f1w   = (const float*)d_in[8];
    const float* pq_f1b   = (const float*)d_in[9];
    const float* pq_f2w   = (const float*)d_in[10];
    const float* pq_f2b   = (const float*)d_in[11];
    const float* pk_dw_w  = (const float*)d_in[12];
    const float* pk_dw_b  = (const float*)d_in[13];
    const float* pk_f1w   = (const float*)d_in[14];
    const float* pk_f1b   = (const float*)d_in[15];
    const float* pk_f2w   = (const float*)d_in[16];
    const float* pk_f2b   = (const float*)d_in[17];
    const float* pos_w    = (const float*)d_in[18];
    // d_in[19] = pos_conv_b (cancels in the relative difference)
    const float* pos_sc   = (const float*)d_in[20];
    const float* meta_w1  = (const float*)d_in[21];
    const float* meta_b1  = (const float*)d_in[22];
    const float* meta_w2  = (const float*)d_in[23];
    const float* meta_b2  = (const float*)d_in[24];
    const float* w_po     = (const float*)d_in[25];
    const float* w_proj   = (const float*)d_in[26];
    const float* b_proj   = (const float*)d_in[27];
    float* out = (float*)d_out;

    wc_kernel<<<CDIM, CDIM>>>(w_proj, w_po);
    bias_kernel<<<225, 128>>>(pos_w, pos_sc, meta_w1, meta_b1, meta_w2, meta_b2);
    qkv_gemm<<<dim3(NPIX / 128, QKVC / 128), 256>>>(x, w_qk, b_qk, w_v, b_v);
    attn_kernel<<<NWIN * HEADS, 128>>>(log_temp,
        pq_dw_w, pq_dw_b, pq_f1w, pq_f1b, pq_f2w, pq_f2b,
        pk_dw_w, pk_dw_b, pk_f1w, pk_f1b, pk_f2w, pk_f2b);
    out_gemm<<<dim3(NPIX / 128, CDIM / 128), 256>>>(b_proj, out);
}

// round 3
// speedup vs baseline: 2.0713x; 2.0713x over previous
#include <cuda_runtime.h>
#include <cuda_bf16.h>
#include <cstdint>
#include <math.h>

// ---------------- problem constants ----------------
#define BATCH 4
#define CDIM  384
#define HDIM  128
#define WDIM  128
#define HWPIX 16384
#define NPIX  65536
#define HEADS 12
#define HD    32
#define WS    8
#define NTOK  64
#define NWIN  1024
#define QKVC  1152

// ---------------- device scratch ----------------
__device__ float g_qkv[(size_t)NPIX * QKVC];   // per-pixel [q k v]
__device__ float g_ao [(size_t)NPIX * CDIM];   // attention out, pixel-major (tf32-rounded)
__device__ float g_xT [(size_t)NPIX * CDIM];   // x transposed to [p][c], tf32-rounded
__device__ float g_wb [QKVC * CDIM];           // [w_qk ; w_v] rounded
__device__ float g_bqkv[QKVC];                 // [b_qk ; b_v]
__device__ float g_bias[HEADS * 225];
__device__ float g_Wc  [CDIM * CDIM];          // w_proj @ w_po, rounded

// ---------------- helpers ----------------
__device__ __forceinline__ uint32_t smem_u32(const void* p) {
    uint32_t a;
    asm("{ .reg .u64 t; cvta.to.shared.u64 t, %1; cvt.u32.u64 %0, t; }" : "=r"(a) : "l"(p));
    return a;
}
__device__ __forceinline__ float rn_tf32(float v) {
    uint32_t u;
    asm("cvt.rna.tf32.f32 %0, %1;" : "=r"(u) : "f"(v));
    return __uint_as_float(u);
}
__device__ __forceinline__ void cp16(uint32_t saddr, const float* g) {
    asm volatile("cp.async.cg.shared.global [%0], [%1], 16;" :: "r"(saddr), "l"(g));
}
#define CP_COMMIT() asm volatile("cp.async.commit_group;" ::: "memory")
#define CP_WAIT0()  asm volatile("cp.async.wait_group 0;" ::: "memory")
#define CP_WAIT1()  asm volatile("cp.async.wait_group 1;" ::: "memory")

// m16n8k8 tf32 mma (plain PTX, runs on tensor pipe)
__device__ __forceinline__ void mma8(float* c, const float* a, const float* b) {
    asm volatile(
        "mma.sync.aligned.m16n8k8.row.col.f32.tf32.tf32.f32 "
        "{%0,%1,%2,%3}, {%4,%5,%6,%7}, {%8,%9}, {%0,%1,%2,%3};"
        : "+f"(c[0]), "+f"(c[1]), "+f"(c[2]), "+f"(c[3])
        : "r"(__float_as_uint(a[0])), "r"(__float_as_uint(a[1])),
          "r"(__float_as_uint(a[2])), "r"(__float_as_uint(a[3])),
          "r"(__float_as_uint(b[0])), "r"(__float_as_uint(b[1])));
}

// =================================================================
// transpose + tf32 round: x (B,C,HW) -> g_xT[p][c]
// =================================================================
__global__ void __launch_bounds__(256) xpose_kernel(const float* __restrict__ x) {
    __shared__ float t[32][33];
    int bx = blockIdx.x, by = blockIdx.y, bz = blockIdx.z;
    int tx = threadIdx.x & 31, ty = threadIdx.x >> 5;
    const float* src = x + ((size_t)(bz * CDIM + by * 32)) * HWPIX + bx * 32;
    #pragma unroll
    for (int i = 0; i < 32; i += 8)
        t[ty + i][tx] = src[(size_t)(ty + i) * HWPIX + tx];
    __syncthreads();
    float* dst = g_xT + ((size_t)(bz * HWPIX + bx * 32)) * CDIM + by * 32;
    #pragma unroll
    for (int i = 0; i < 32; i += 8)
        dst[(size_t)(ty + i) * CDIM + tx] = rn_tf32(t[tx][ty + i]);
}

// =================================================================
// weight prep
// =================================================================
__global__ void wprep_kernel(const float* __restrict__ w_qk, const float* __restrict__ b_qk,
                             const float* __restrict__ w_v,  const float* __restrict__ b_v) {
    int i = blockIdx.x * 1024 + threadIdx.x;
    if (i < QKVC * CDIM) {
        float v = (i < 2 * CDIM * CDIM) ? w_qk[i] : w_v[i - 2 * CDIM * CDIM];
        g_wb[i] = rn_tf32(v);
    }
    if (i < QKVC)
        g_bqkv[i] = (i < 2 * CDIM) ? b_qk[i] : b_v[i - 2 * CDIM];
}

__global__ void wc_kernel(const float* __restrict__ w_proj,
                          const float* __restrict__ w_po) {
    int o = blockIdx.x;
    int c = threadIdx.x;
    const float* pr = w_proj + o * CDIM;
    float acc = 0.f;
    for (int t = 0; t < CDIM; t++)
        acc += pr[t] * w_po[t * CDIM + c];
    g_Wc[o * CDIM + c] = rn_tf32(acc);
}

// =================================================================
// relative-position bias (225 distinct deltas)
// =================================================================
__global__ void bias_kernel(const float* __restrict__ pcw,
                            const float* __restrict__ psc,
                            const float* __restrict__ mw1,
                            const float* __restrict__ mb1,
                            const float* __restrict__ mw2,
                            const float* __restrict__ mb2) {
    __shared__ float rel[CDIM];
    __shared__ float hid[128];
    int idx = blockIdx.x;
    float dx = (float)((idx % 15) - 7) * (2.0f / 7.0f);
    float dy = (float)((idx / 15) - 7) * (2.0f / 7.0f);
    int t = threadIdx.x;
    float sc = psc[0];
    for (int c = t; c < CDIM; c += 128)
        rel[c] = sc * (pcw[2 * c] * dx + pcw[2 * c + 1] * dy);
    __syncthreads();
    float s = mb1[t];
    const float* w = mw1 + t * CDIM;
    #pragma unroll 8
    for (int c = 0; c < CDIM; c++) s += rel[c] * w[c];
    hid[t] = 0.5f * s * (1.0f + erff(s * 0.70710678118654752f));
    __syncthreads();
    if (t < HEADS) {
        float a = mb2[t];
        const float* w2 = mw2 + t * 128;
        #pragma unroll 8
        for (int j = 0; j < 128; j++) a += hid[j] * w2[j];
        g_bias[t * 225 + idx] = a;
    }
}

// =================================================================
// tf32 mma.sync GEMM: C[m0:128, n0:128] = A[m,384] * B[n,384]^T (+bias)
// MODE 0: A=g_xT, B=g_wb, out=g_qkv[p][o] (stride 1152), bias=g_bqkv
// MODE 1: A=g_ao, B=g_Wc, out=channel-major (B,C,H,W), bias=b_proj
// 256 threads, 8 warps (4m x 2n), warp tile 32x64, BK=16, 24 chunks
// =================================================================
#define APITCH 20
#define NCHUNK 24

template <int MODE>
__global__ void __launch_bounds__(256) gemm_mma(
        const float* __restrict__ Aptr, const float* __restrict__ Bptr,
        const float* __restrict__ biasptr, float* __restrict__ outp) {
    __shared__ float As[2][128 * APITCH];
    __shared__ float Bs[2][128 * APITCH];

    int tid = threadIdx.x;
    int n0 = blockIdx.x * 128;
    int m0 = blockIdx.y * 128;
    int lane = tid & 31, wid = tid >> 5;
    int wm = (wid & 3) * 32;       // warp m offset
    int wn = (wid >> 2) * 64;      // warp n offset

    const float* Arow = Aptr + (size_t)m0 * CDIM;
    const float* Brow = Bptr + (size_t)n0 * CDIM;
    uint32_t aB[2] = { smem_u32(As[0]), smem_u32(As[1]) };
    uint32_t bB[2] = { smem_u32(Bs[0]), smem_u32(Bs[1]) };

    int ldrow = tid >> 2, ldseg = tid & 3;        // 64 rows per pass
    auto load_chunk = [&](int k0, int buf) {
        #pragma unroll
        for (int i = 0; i < 2; i++) {
            int row = ldrow + i * 64;
            uint32_t so = (uint32_t)(row * APITCH + ldseg * 4) * 4;
            cp16(aB[buf] + so, Arow + (size_t)row * CDIM + k0 + ldseg * 4);
            cp16(bB[buf] + so, Brow + (size_t)row * CDIM + k0 + ldseg * 4);
        }
        CP_COMMIT();
    };

    float acc[2][8][4];
    #pragma unroll
    for (int mt = 0; mt < 2; mt++)
        #pragma unroll
        for (int nt = 0; nt < 8; nt++)
            #pragma unroll
            for (int j = 0; j < 4; j++) acc[mt][nt][j] = 0.f;

    load_chunk(0, 0);

    int r4 = lane >> 2, c4 = lane & 3;
    for (int i = 0; i < NCHUNK; i++) {
        if (i + 1 < NCHUNK) { load_chunk((i + 1) * 16, (i + 1) & 1); CP_WAIT1(); }
        else                { CP_WAIT0(); }
        __syncthreads();
        const float* Ab = As[i & 1];
        const float* Bb = Bs[i & 1];
        #pragma unroll
        for (int kk = 0; kk < 2; kk++) {
            int kb = kk * 8;
            float a[2][4];
            #pragma unroll
            for (int mt = 0; mt < 2; mt++) {
                int row = wm + mt * 16 + r4;
                a[mt][0] = Ab[row * APITCH + kb + c4];
                a[mt][1] = Ab[(row + 8) * APITCH + kb + c4];
                a[mt][2] = Ab[row * APITCH + kb + 4 + c4];
                a[mt][3] = Ab[(row + 8) * APITCH + kb + 4 + c4];
            }
            float b[8][2];
            #pragma unroll
            for (int nt = 0; nt < 8; nt++) {
                int nrow = wn + nt * 8 + r4;
                b[nt][0] = Bb[nrow * APITCH + kb + c4];
                b[nt][1] = Bb[nrow * APITCH + kb + 4 + c4];
            }
            #pragma unroll
            for (int mt = 0; mt < 2; mt++)
                #pragma unroll
                for (int nt = 0; nt < 8; nt++)
                    mma8(acc[mt][nt], a[mt], b[nt]);
        }
        __syncthreads();
    }

    // ---- epilogue ----
    int cb = c4 * 2;
    if (MODE == 0) {
        #pragma unroll
        for (int mt = 0; mt < 2; mt++)
            #pragma unroll
            for (int half = 0; half < 2; half++) {
                int m = m0 + wm + mt * 16 + r4 + half * 8;
                float* dst = g_qkv + (size_t)m * QKVC + n0 + wn;
                #pragma unroll
                for (int nt = 0; nt < 8; nt++) {
                    int o = n0 + wn + nt * 8 + cb;
                    float2 v;
                    v.x = acc[mt][nt][half * 2 + 0] + biasptr[o];
                    v.y = acc[mt][nt][half * 2 + 1] + biasptr[o + 1];
                    *(float2*)(dst + nt * 8 + cb) = v;
                }
            }
    } else {
        int b = m0 >> 14;
        int ppb = m0 & (HWPIX - 1);
        #pragma unroll
        for (int mt = 0; mt < 2; mt++)
            #pragma unroll
            for (int half = 0; half < 2; half++) {
                int pp = ppb + wm + mt * 16 + r4 + half * 8;
                #pragma unroll
                for (int nt = 0; nt < 8; nt++)
                    #pragma unroll
                    for (int j = 0; j < 2; j++) {
                        int o = n0 + wn + nt * 8 + cb + j;
                        outp[((size_t)(b * CDIM + o)) * HWPIX + pp] =
                            acc[mt][nt][half * 2 + j] + biasptr[o];
                    }
            }
    }
}

// =================================================================
// PDSCA gate
// =================================================================
__device__ __forceinline__ void pdsca_gate(
        float* xs, float* scr, float* gap, float* hid, float* ca,
        const float* __restrict__ dw_w, const float* __restrict__ dw_b,
        const float* __restrict__ f1w,  const float* __restrict__ f1b,
        const float* __restrict__ f2w,  const float* __restrict__ f2b,
        int t) {
    for (int idx = t; idx < 2048; idx += 128) {
        int c = idx >> 6, s = idx & 63, sy = s >> 3, sx = s & 7;
        float sum = dw_b[c];
        #pragma unroll
        for (int ky = 0; ky < 3; ky++) {
            int iy = sy + ky - 1;
            if (iy < 0 || iy > 7) continue;
            #pragma unroll
            for (int kx = 0; kx < 3; kx++) {
                int ix = sx + kx - 1;
                if (ix < 0 || ix > 7) continue;
                int s2 = iy * 8 + ix;
                sum += dw_w[c * 9 + ky * 3 + kx] *
                       xs[(2 * c + (s2 >> 5)) * 36 + (s2 & 31)];
            }
        }
        scr[idx] = sum;
    }
    if (t < 32) {
        float s = 0.f;
        #pragma unroll
        for (int d = 0; d < 32; d++)
            s += xs[(2 * t) * 36 + d] + xs[(2 * t + 1) * 36 + d];
        gap[t] = s * (1.0f / 64.0f);
    }
    __syncthreads();
    if (t < 8) {
        float s = f1b[t];
        #pragma unroll
        for (int c = 0; c < 32; c++) s += gap[c] * f1w[t * 32 + c];
        hid[t] = fmaxf(s, 0.f);
    }
    __syncthreads();
    if (t < 32) {
        float s = f2b[t];
        #pragma unroll
        for (int j = 0; j < 8; j++) s += hid[j] * f2w[t * 8 + j];
        ca[t] = s;
    }
    __syncthreads();
    for (int idx = t; idx < 2048; idx += 128) {
        int c = idx >> 6, s = idx & 63;
        float m = scr[idx] + ca[c];
        float g = 1.0f / (1.0f + expf(-m));
        xs[(2 * c + (s >> 5)) * 36 + (s & 31)] *= g;
    }
    __syncthreads();
}

// =================================================================
// per-(window, head) PDSCA + attention; stores tf32-rounded g_ao
// =================================================================
__global__ void __launch_bounds__(128) attn_kernel(
        const float* __restrict__ log_temp,
        const float* __restrict__ pqw,  const float* __restrict__ pqb,
        const float* __restrict__ pqf1w, const float* __restrict__ pqf1b,
        const float* __restrict__ pqf2w, const float* __restrict__ pqf2b,
        const float* __restrict__ pkw,  const float* __restrict__ pkb,
        const float* __restrict__ pkf1w, const float* __restrict__ pkf1b,
        const float* __restrict__ pkf2w, const float* __restrict__ pkf2b) {
    __shared__ __align__(16) float qs[NTOK * 36];
    __shared__ __align__(16) float ks[NTOK * 36];
    __shared__ __align__(16) float vs[NTOK * 36];
    __shared__ float at[NTOK * 65];
    __shared__ float gap[32], hid[8], ca[32];

    int bi  = blockIdx.x;
    int win = bi / HEADS;
    int h   = bi - win * HEADS;
    int t   = threadIdx.x;
    int b   = win >> 8, hb = (win >> 4) & 15, wb = win & 15;
    int pbase = b * HWPIX + hb * 8 * WDIM + wb * 8;

    for (int tt = t; tt < 512; tt += 128) {
        int n = tt >> 3, d4 = (tt & 7) * 4;
        int p = pbase + (n >> 3) * WDIM + (n & 7);
        const float* src = g_qkv + (size_t)p * QKVC + h * HD + d4;
        float4 qv = *(const float4*)(src);
        float4 kv = *(const float4*)(src + CDIM);
        float4 vv = *(const float4*)(src + 2 * CDIM);
        *(float4*)&qs[n * 36 + d4] = qv;
        *(float4*)&ks[n * 36 + d4] = kv;
        *(float4*)&vs[n * 36 + d4] = vv;
    }
    __syncthreads();

    pdsca_gate(qs, at, gap, hid, ca, pqw, pqb, pqf1w, pqf1b, pqf2w, pqf2b, t);
    pdsca_gate(ks, at, gap, hid, ca, pkw, pkb, pkf1w, pkf1b, pkf2w, pkf2b, t);

    float temp = expf(log_temp[0]);
    {
        int n = t >> 1, mb2 = (t & 1) * 32;
        float4 q[8];
        #pragma unroll
        for (int i = 0; i < 8; i++) q[i] = *(const float4*)&qs[n * 36 + 4 * i];
        const float* brow = g_bias + h * 225;
        int ny = n >> 3, nx = n & 7;
        for (int mm = 0; mm < 32; mm++) {
            int m = mb2 + mm;
            const float4* kp = (const float4*)&ks[m * 36];
            float dot = 0.f;
            #pragma unroll
            for (int i = 0; i < 8; i++) {
                float4 kk4 = kp[i];
                dot += q[i].x * kk4.x + q[i].y * kk4.y +
                       q[i].z * kk4.z + q[i].w * kk4.w;
            }
            int dy = ny - (m >> 3), dx = nx - (m & 7);
            at[n * 65 + m] = dot * temp + brow[(dy + 7) * 15 + (dx + 7)];
        }
    }
    __syncthreads();

    if (t < NTOK) {
        float* row = at + t * 65;
        float mx = -1e30f;
        #pragma unroll 8
        for (int m = 0; m < 64; m++) mx = fmaxf(mx, row[m]);
        float s = 0.f;
        #pragma unroll 8
        for (int m = 0; m < 64; m++) { float e = expf(row[m] - mx); row[m] = e; s += e; }
        float inv = 1.0f / s;
        #pragma unroll 8
        for (int m = 0; m < 64; m++) row[m] *= inv;
    }
    __syncthreads();

    for (int tt = t; tt < 512; tt += 128) {
        int n = tt >> 3, d4 = (tt & 7) * 4;
        const float* row = at + n * 65;
        float4 acc = make_float4(0.f, 0.f, 0.f, 0.f);
        #pragma unroll 8
        for (int m = 0; m < 64; m++) {
            float a = row[m];
            float4 vv = *(const float4*)&vs[m * 36 + d4];
            acc.x += a * vv.x; acc.y += a * vv.y;
            acc.z += a * vv.z; acc.w += a * vv.w;
        }
        int p = pbase + (n >> 3) * WDIM + (n & 7);
        acc.x = rn_tf32(acc.x); acc.y = rn_tf32(acc.y);
        acc.z = rn_tf32(acc.z); acc.w = rn_tf32(acc.w);
        *(float4*)(g_ao + (size_t)p * CDIM + h * HD + d4) = acc;
    }
}

// =================================================================
// launch
// =================================================================
extern "C" void kernel_launch(void* const* d_in, const int* in_sizes, int n_in,
                              void* d_out, int out_size) {
    const float* x        = (const float*)d_in[0];
    const float* w_qk     = (const float*)d_in[1];
    const float* b_qk     = (const float*)d_in[2];
    const float* w_v      = (const float*)d_in[3];
    const float* b_v      = (const float*)d_in[4];
    const float* log_temp = (const float*)d_in[5];
    const float* pq_dw_w  = (const float*)d_in[6];
    const float* pq_dw_b  = (const float*)d_in[7];
    const float* pq_f1w   = (const float*)d_in[8];
    const float* pq_f1b   = (const float*)d_in[9];
    const float* pq_f2w   = (const float*)d_in[10];
    const float* pq_f2b   = (const float*)d_in[11];
    const float* pk_dw_w  = (const float*)d_in[12];
    const float* pk_dw_b  = (const float*)d_in[13];
    const float* pk_f1w   = (const float*)d_in[14];
    const float* pk_f1b   = (const float*)d_in[15];
    const float* pk_f2w   = (const float*)d_in[16];
    const float* pk_f2b   = (const float*)d_in[17];
    const float* pos_w    = (const float*)d_in[18];
    const float* pos_sc   = (const float*)d_in[20];
    const float* meta_w1  = (const float*)d_in[21];
    const float* meta_b1  = (const float*)d_in[22];
    const float* meta_w2  = (const float*)d_in[23];
    const float* meta_b2  = (const float*)d_in[24];
    const float* w_po     = (const float*)d_in[25];
    const float* w_proj   = (const float*)d_in[26];
    const float* b_proj   = (const float*)d_in[27];
    float* out = (float*)d_out;

    xpose_kernel<<<dim3(HWPIX / 32, CDIM / 32, BATCH), 256>>>(x);
    wprep_kernel<<<(QKVC * CDIM + 1023) / 1024, 1024>>>(w_qk, b_qk, w_v, b_v);
    wc_kernel<<<CDIM, CDIM>>>(w_proj, w_po);
    bias_kernel<<<225, 128>>>(pos_w, pos_sc, meta_w1, meta_b1, meta_w2, meta_b2);

    {
        const float* A; cudaGetSymbolAddress((void**)&A, g_xT);
        const float* Bp; cudaGetSymbolAddress((void**)&Bp, g_wb);
        const float* bb; cudaGetSymbolAddress((void**)&bb, g_bqkv);
        float* op; cudaGetSymbolAddress((void**)&op, g_qkv);
        gemm_mma<0><<<dim3(QKVC / 128, NPIX / 128), 256>>>(A, Bp, bb, op);
    }

    attn_kernel<<<NWIN * HEADS, 128>>>(log_temp,
        pq_dw_w, pq_dw_b, pq_f1w, pq_f1b, pq_f2w, pq_f2b,
        pk_dw_w, pk_dw_b, pk_f1w, pk_f1b, pk_f2w, pk_f2b);

    {
        const float* A; cudaGetSymbolAddress((void**)&A, g_ao);
        const float* Bp; cudaGetSymbolAddress((void**)&Bp, g_Wc);
        gemm_mma<1><<<dim3(CDIM / 128, NPIX / 128), 256>>>(A, Bp, b_proj, out);
    }
}

// round 5
// speedup vs baseline: 2.6863x; 1.2969x over previous
#include <cuda_runtime.h>
#include <cuda_bf16.h>
#include <cstdint>
#include <math.h>

// ---------------- problem constants ----------------
#define BATCH 4
#define CDIM  384
#define HDIM  128
#define WDIM  128
#define HWPIX 16384
#define NPIX  65536
#define HEADS 12
#define HD    32
#define WS    8
#define NTOK  64
#define NWIN  1024
#define QKVC  1152

// ---------------- device scratch ----------------
__device__ float g_qkv[(size_t)NPIX * QKVC];
__device__ float g_ao [(size_t)NPIX * CDIM];   // attn out, pixel-major, tf32-rounded
__device__ float g_xT [(size_t)NPIX * CDIM];   // x^T, tf32-rounded
__device__ float g_wb [QKVC * CDIM];
__device__ float g_bqkv[QKVC];
__device__ float g_bias[HEADS * 225];
__device__ float g_Wc  [CDIM * CDIM];

// ---------------- helpers ----------------
__device__ __forceinline__ uint32_t smem_u32(const void* p) {
    uint32_t a;
    asm("{ .reg .u64 t; cvta.to.shared.u64 t, %1; cvt.u32.u64 %0, t; }" : "=r"(a) : "l"(p));
    return a;
}
__device__ __forceinline__ float rn_tf32(float v) {
    uint32_t u;
    asm("cvt.rna.tf32.f32 %0, %1;" : "=r"(u) : "f"(v));
    return __uint_as_float(u);
}
__device__ __forceinline__ void cp16(uint32_t saddr, const float* g) {
    asm volatile("cp.async.cg.shared.global [%0], [%1], 16;" :: "r"(saddr), "l"(g));
}
#define CP_COMMIT() asm volatile("cp.async.commit_group;" ::: "memory")
#define CP_WAIT0()  asm volatile("cp.async.wait_group 0;" ::: "memory")
#define CP_WAIT1()  asm volatile("cp.async.wait_group 1;" ::: "memory")

__device__ __forceinline__ void mma8(float* c, const float* a, const float* b) {
    asm volatile(
        "mma.sync.aligned.m16n8k8.row.col.f32.tf32.tf32.f32 "
        "{%0,%1,%2,%3}, {%4,%5,%6,%7}, {%8,%9}, {%0,%1,%2,%3};"
        : "+f"(c[0]), "+f"(c[1]), "+f"(c[2]), "+f"(c[3])
        : "r"(__float_as_uint(a[0])), "r"(__float_as_uint(a[1])),
          "r"(__float_as_uint(a[2])), "r"(__float_as_uint(a[3])),
          "r"(__float_as_uint(b[0])), "r"(__float_as_uint(b[1])));
}

// =================================================================
// transpose + tf32 round
// =================================================================
__global__ void __launch_bounds__(256) xpose_kernel(const float* __restrict__ x) {
    __shared__ float t[32][33];
    int bx = blockIdx.x, by = blockIdx.y, bz = blockIdx.z;
    int tx = threadIdx.x & 31, ty = threadIdx.x >> 5;
    const float* src = x + ((size_t)(bz * CDIM + by * 32)) * HWPIX + bx * 32;
    #pragma unroll
    for (int i = 0; i < 32; i += 8)
        t[ty + i][tx] = src[(size_t)(ty + i) * HWPIX + tx];
    __syncthreads();
    float* dst = g_xT + ((size_t)(bz * HWPIX + bx * 32)) * CDIM + by * 32;
    #pragma unroll
    for (int i = 0; i < 32; i += 8)
        dst[(size_t)(ty + i) * CDIM + tx] = rn_tf32(t[tx][ty + i]);
}

// =================================================================
// weight prep
// =================================================================
__global__ void wprep_kernel(const float* __restrict__ w_qk, const float* __restrict__ b_qk,
                             const float* __restrict__ w_v,  const float* __restrict__ b_v) {
    int i = blockIdx.x * 1024 + threadIdx.x;
    if (i < QKVC * CDIM) {
        float v = (i < 2 * CDIM * CDIM) ? w_qk[i] : w_v[i - 2 * CDIM * CDIM];
        g_wb[i] = rn_tf32(v);
    }
    if (i < QKVC)
        g_bqkv[i] = (i < 2 * CDIM) ? b_qk[i] : b_v[i - 2 * CDIM];
}

__global__ void wc_kernel(const float* __restrict__ w_proj,
                          const float* __restrict__ w_po) {
    int o = blockIdx.x;
    int c = threadIdx.x;
    const float* pr = w_proj + o * CDIM;
    float a0 = 0.f, a1 = 0.f, a2 = 0.f, a3 = 0.f;
    for (int t = 0; t < CDIM; t += 4) {
        a0 += pr[t] * w_po[t * CDIM + c];
        a1 += pr[t + 1] * w_po[(t + 1) * CDIM + c];
        a2 += pr[t + 2] * w_po[(t + 2) * CDIM + c];
        a3 += pr[t + 3] * w_po[(t + 3) * CDIM + c];
    }
    g_Wc[o * CDIM + c] = rn_tf32((a0 + a1) + (a2 + a3));
}

// =================================================================
// relative-position bias (225 deltas) — ILP'd
// =================================================================
__global__ void bias_kernel(const float* __restrict__ pcw,
                            const float* __restrict__ psc,
                            const float* __restrict__ mw1,
                            const float* __restrict__ mb1,
                            const float* __restrict__ mw2,
                            const float* __restrict__ mb2) {
    __shared__ __align__(16) float rel[CDIM];
    __shared__ __align__(16) float hid[128];
    int idx = blockIdx.x;
    float dx = (float)((idx % 15) - 7) * (2.0f / 7.0f);
    float dy = (float)((idx / 15) - 7) * (2.0f / 7.0f);
    int t = threadIdx.x;
    float sc = psc[0];
    for (int c = t; c < CDIM; c += 128)
        rel[c] = sc * (pcw[2 * c] * dx + pcw[2 * c + 1] * dy);
    __syncthreads();
    {
        float a0 = 0.f, a1 = 0.f, a2 = 0.f, a3 = 0.f;
        const float4* w = (const float4*)(mw1 + t * CDIM);
        const float4* r = (const float4*)rel;
        #pragma unroll 4
        for (int c = 0; c < CDIM / 4; c++) {
            float4 wv = w[c], rv = r[c];
            a0 += wv.x * rv.x; a1 += wv.y * rv.y;
            a2 += wv.z * rv.z; a3 += wv.w * rv.w;
        }
        float s = mb1[t] + (a0 + a1) + (a2 + a3);
        hid[t] = 0.5f * s * (1.0f + erff(s * 0.70710678118654752f));
    }
    __syncthreads();
    if (t < HEADS) {
        float a0 = 0.f, a1 = 0.f, a2 = 0.f, a3 = 0.f;
        const float4* w2 = (const float4*)(mw2 + t * 128);
        const float4* hh = (const float4*)hid;
        #pragma unroll 4
        for (int j = 0; j < 32; j++) {
            float4 wv = w2[j], hv = hh[j];
            a0 += wv.x * hv.x; a1 += wv.y * hv.y;
            a2 += wv.z * hv.z; a3 += wv.w * hv.w;
        }
        g_bias[t * 225 + idx] = mb2[t] + (a0 + a1) + (a2 + a3);
    }
}

// =================================================================
// tf32 mma.sync GEMM: C[m0:128, n0:128] = A[m,384] * B[n,384]^T (+bias)
// BK=32, dynamic smem, 256 threads, 8 warps (4m x 2n), warp 32x64
// =================================================================
#define GP 36
#define NCHUNK 12
#define GEMM_SMEM (4 * 128 * GP * 4)

template <int MODE>
__global__ void __launch_bounds__(256) gemm_mma(
        const float* __restrict__ Aptr, const float* __restrict__ Bptr,
        const float* __restrict__ biasptr, float* __restrict__ outp) {
    extern __shared__ __align__(16) float sm[];
    float* AsB[2] = { sm, sm + 128 * GP };
    float* BsB[2] = { sm + 2 * 128 * GP, sm + 3 * 128 * GP };

    int tid = threadIdx.x;
    int n0 = blockIdx.x * 128;
    int m0 = blockIdx.y * 128;
    int lane = tid & 31, wid = tid >> 5;
    int wm = (wid & 3) * 32;
    int wn = (wid >> 2) * 64;

    const float* Arow = Aptr + (size_t)m0 * CDIM;
    const float* Brow = Bptr + (size_t)n0 * CDIM;
    uint32_t aU[2] = { smem_u32(AsB[0]), smem_u32(AsB[1]) };
    uint32_t bU[2] = { smem_u32(BsB[0]), smem_u32(BsB[1]) };

    int ldrow = tid >> 3, ldseg = tid & 7;   // 32 rows / pass, 4 passes
    auto load_chunk = [&](int k0, int buf) {
        #pragma unroll
        for (int i = 0; i < 4; i++) {
            int row = ldrow + i * 32;
            uint32_t so = (uint32_t)(row * GP + ldseg * 4) * 4;
            cp16(aU[buf] + so, Arow + (size_t)row * CDIM + k0 + ldseg * 4);
            cp16(bU[buf] + so, Brow + (size_t)row * CDIM + k0 + ldseg * 4);
        }
        CP_COMMIT();
    };

    float acc[2][8][4];
    #pragma unroll
    for (int mt = 0; mt < 2; mt++)
        #pragma unroll
        for (int nt = 0; nt < 8; nt++)
            #pragma unroll
            for (int j = 0; j < 4; j++) acc[mt][nt][j] = 0.f;

    load_chunk(0, 0);

    int r4 = lane >> 2, c4 = lane & 3;
    for (int i = 0; i < NCHUNK; i++) {
        if (i + 1 < NCHUNK) { load_chunk((i + 1) * 32, (i + 1) & 1); CP_WAIT1(); }
        else                { CP_WAIT0(); }
        __syncthreads();
        const float* Ab = AsB[i & 1];
        const float* Bb = BsB[i & 1];
        #pragma unroll
        for (int kk = 0; kk < 4; kk++) {
            int kb = kk * 8;
            float a[2][4];
            #pragma unroll
            for (int mt = 0; mt < 2; mt++) {
                int row = wm + mt * 16 + r4;
                a[mt][0] = Ab[row * GP + kb + c4];
                a[mt][1] = Ab[(row + 8) * GP + kb + c4];
                a[mt][2] = Ab[row * GP + kb + 4 + c4];
                a[mt][3] = Ab[(row + 8) * GP + kb + 4 + c4];
            }
            float b[8][2];
            #pragma unroll
            for (int nt = 0; nt < 8; nt++) {
                int nrow = wn + nt * 8 + r4;
                b[nt][0] = Bb[nrow * GP + kb + c4];
                b[nt][1] = Bb[nrow * GP + kb + 4 + c4];
            }
            #pragma unroll
            for (int mt = 0; mt < 2; mt++)
                #pragma unroll
                for (int nt = 0; nt < 8; nt++)
                    mma8(acc[mt][nt], a[mt], b[nt]);
        }
        __syncthreads();
    }

    int cb = c4 * 2;
    if (MODE == 0) {
        #pragma unroll
        for (int mt = 0; mt < 2; mt++)
            #pragma unroll
            for (int half = 0; half < 2; half++) {
                int m = m0 + wm + mt * 16 + r4 + half * 8;
                float* dst = g_qkv + (size_t)m * QKVC + n0 + wn;
                #pragma unroll
                for (int nt = 0; nt < 8; nt++) {
                    int o = n0 + wn + nt * 8 + cb;
                    float2 v;
                    v.x = acc[mt][nt][half * 2 + 0] + biasptr[o];
                    v.y = acc[mt][nt][half * 2 + 1] + biasptr[o + 1];
                    *(float2*)(dst + nt * 8 + cb) = v;
                }
            }
    } else {
        int b = m0 >> 14;
        int ppb = m0 & (HWPIX - 1);
        #pragma unroll
        for (int mt = 0; mt < 2; mt++)
            #pragma unroll
            for (int half = 0; half < 2; half++) {
                int pp = ppb + wm + mt * 16 + r4 + half * 8;
                #pragma unroll
                for (int nt = 0; nt < 8; nt++)
                    #pragma unroll
                    for (int j = 0; j < 2; j++) {
                        int o = n0 + wn + nt * 8 + cb + j;
                        outp[((size_t)(b * CDIM + o)) * HWPIX + pp] =
                            acc[mt][nt][half * 2 + j] + biasptr[o];
                    }
            }
    }
}

// =================================================================
// PDSCA gate (rounds gated output to tf32)
// =================================================================
__device__ __forceinline__ void pdsca_gate(
        float* xs, float* scr, float* gap, float* hid, float* ca,
        const float* __restrict__ dw_w, const float* __restrict__ dw_b,
        const float* __restrict__ f1w,  const float* __restrict__ f1b,
        const float* __restrict__ f2w,  const float* __restrict__ f2b,
        int t) {
    for (int idx = t; idx < 2048; idx += 128) {
        int c = idx >> 6, s = idx & 63, sy = s >> 3, sx = s & 7;
        float sum = dw_b[c];
        #pragma unroll
        for (int ky = 0; ky < 3; ky++) {
            int iy = sy + ky - 1;
            if (iy < 0 || iy > 7) continue;
            #pragma unroll
            for (int kx = 0; kx < 3; kx++) {
                int ix = sx + kx - 1;
                if (ix < 0 || ix > 7) continue;
                int s2 = iy * 8 + ix;
                sum += dw_w[c * 9 + ky * 3 + kx] *
                       xs[(2 * c + (s2 >> 5)) * 36 + (s2 & 31)];
            }
        }
        scr[idx] = sum;
    }
    if (t < 32) {
        float s = 0.f;
        #pragma unroll
        for (int d = 0; d < 32; d++)
            s += xs[(2 * t) * 36 + d] + xs[(2 * t + 1) * 36 + d];
        gap[t] = s * (1.0f / 64.0f);
    }
    __syncthreads();
    if (t < 8) {
        float s = f1b[t];
        #pragma unroll
        for (int c = 0; c < 32; c++) s += gap[c] * f1w[t * 32 + c];
        hid[t] = fmaxf(s, 0.f);
    }
    __syncthreads();
    if (t < 32) {
        float s = f2b[t];
        #pragma unroll
        for (int j = 0; j < 8; j++) s += hid[j] * f2w[t * 8 + j];
        ca[t] = s;
    }
    __syncthreads();
    for (int idx = t; idx < 2048; idx += 128) {
        int c = idx >> 6, s = idx & 63;
        float m = scr[idx] + ca[c];
        float g = 1.0f / (1.0f + __expf(-m));
        int off = (2 * c + (s >> 5)) * 36 + (s & 31);
        xs[off] = rn_tf32(xs[off] * g);
    }
    __syncthreads();
}

// =================================================================
// per-(window, head) PDSCA + attention via mma.sync
// 128 threads = 4 warps; warp w owns query rows w*16 .. w*16+15
// =================================================================
#define ATP 68   // pitch for P staging (conflict-free A-frag reads)
#define VP  68   // pitch for V^T [32 dims][64 tokens]

__global__ void __launch_bounds__(128) attn_kernel(
        const float* __restrict__ log_temp,
        const float* __restrict__ pqw,  const float* __restrict__ pqb,
        const float* __restrict__ pqf1w, const float* __restrict__ pqf1b,
        const float* __restrict__ pqf2w, const float* __restrict__ pqf2b,
        const float* __restrict__ pkw,  const float* __restrict__ pkb,
        const float* __restrict__ pkf1w, const float* __restrict__ pkf1b,
        const float* __restrict__ pkf2w, const float* __restrict__ pkf2b) {
    __shared__ __align__(16) float qs[NTOK * 36];
    __shared__ __align__(16) float ks[NTOK * 36];
    __shared__ __align__(16) float vsT[HD * VP];   // V^T: [d][token], pitch 68
    __shared__ __align__(16) float at[NTOK * ATP]; // PDSCA scratch / P staging
    __shared__ float gap[32], hid[8], ca[32];

    int bi  = blockIdx.x;
    int win = bi / HEADS;
    int h   = bi - win * HEADS;
    int t   = threadIdx.x;
    int b   = win >> 8, hb = (win >> 4) & 15, wb = win & 15;
    int pbase = b * HWPIX + hb * 8 * WDIM + wb * 8;

    // ---- load q,k (row-major) and v transposed+rounded ----
    for (int tt = t; tt < 512; tt += 128) {
        int n = tt >> 3, d4 = (tt & 7) * 4;
        int p = pbase + (n >> 3) * WDIM + (n & 7);
        const float* src = g_qkv + (size_t)p * QKVC + h * HD + d4;
        float4 qv = *(const float4*)(src);
        float4 kv = *(const float4*)(src + CDIM);
        float4 vv = *(const float4*)(src + 2 * CDIM);
        *(float4*)&qs[n * 36 + d4] = qv;
        *(float4*)&ks[n * 36 + d4] = kv;
        vsT[(d4 + 0) * VP + n] = rn_tf32(vv.x);
        vsT[(d4 + 1) * VP + n] = rn_tf32(vv.y);
        vsT[(d4 + 2) * VP + n] = rn_tf32(vv.z);
        vsT[(d4 + 3) * VP + n] = rn_tf32(vv.w);
    }
    __syncthreads();

    pdsca_gate(qs, at, gap, hid, ca, pqw, pqb, pqf1w, pqf1b, pqf2w, pqf2b, t);
    pdsca_gate(ks, at, gap, hid, ca, pkw, pkb, pkf1w, pkf1b, pkf2w, pkf2b, t);

    int lane = t & 31, w = t >> 5;
    int r4 = lane >> 2, c4 = lane & 3;
    int m0 = w * 16;

    // ---- S = Q K^T via mma ----
    float sacc[8][4];
    #pragma unroll
    for (int nt = 0; nt < 8; nt++)
        #pragma unroll
        for (int j = 0; j < 4; j++) sacc[nt][j] = 0.f;

    #pragma unroll
    for (int kt = 0; kt < 4; kt++) {
        int kb = kt * 8;
        float a[4];
        a[0] = qs[(m0 + r4) * 36 + kb + c4];
        a[1] = qs[(m0 + r4 + 8) * 36 + kb + c4];
        a[2] = qs[(m0 + r4) * 36 + kb + 4 + c4];
        a[3] = qs[(m0 + r4 + 8) * 36 + kb + 4 + c4];
        #pragma unroll
        for (int nt = 0; nt < 8; nt++) {
            float bfr[2];
            bfr[0] = ks[(nt * 8 + r4) * 36 + kb + c4];
            bfr[1] = ks[(nt * 8 + r4) * 36 + kb + 4 + c4];
            mma8(sacc[nt], a, bfr);
        }
    }

    // ---- bias + temp + softmax (registers + 4-lane shfl) ----
    float temp = __expf(log_temp[0]);
    const float* brow = g_bias + h * 225;
    int r_lo = m0 + r4, r_hi = r_lo + 8;
    int ylo = r_lo >> 3, xlo = r_lo & 7;
    int yhi = r_hi >> 3, xhi = r_hi & 7;

    float mlo = -1e30f, mhi = -1e30f;
    #pragma unroll
    for (int nt = 0; nt < 8; nt++)
        #pragma unroll
        for (int j = 0; j < 2; j++) {
            int col = nt * 8 + 2 * c4 + j;
            int cy = col >> 3, cx = col & 7;
            float blo = brow[(ylo - cy + 7) * 15 + (xlo - cx + 7)];
            float bhi = brow[(yhi - cy + 7) * 15 + (xhi - cx + 7)];
            sacc[nt][j]     = sacc[nt][j] * temp + blo;
            sacc[nt][2 + j] = sacc[nt][2 + j] * temp + bhi;
            mlo = fmaxf(mlo, sacc[nt][j]);
            mhi = fmaxf(mhi, sacc[nt][2 + j]);
        }
    mlo = fmaxf(mlo, __shfl_xor_sync(0xffffffffu, mlo, 1));
    mlo = fmaxf(mlo, __shfl_xor_sync(0xffffffffu, mlo, 2));
    mhi = fmaxf(mhi, __shfl_xor_sync(0xffffffffu, mhi, 1));
    mhi = fmaxf(mhi, __shfl_xor_sync(0xffffffffu, mhi, 2));

    float slo = 0.f, shi = 0.f;
    #pragma unroll
    for (int nt = 0; nt < 8; nt++)
        #pragma unroll
        for (int j = 0; j < 2; j++) {
            float e0 = __expf(sacc[nt][j] - mlo);
            float e1 = __expf(sacc[nt][2 + j] - mhi);
            sacc[nt][j] = e0; sacc[nt][2 + j] = e1;
            slo += e0; shi += e1;
        }
    slo += __shfl_xor_sync(0xffffffffu, slo, 1);
    slo += __shfl_xor_sync(0xffffffffu, slo, 2);
    shi += __shfl_xor_sync(0xffffffffu, shi, 1);
    shi += __shfl_xor_sync(0xffffffffu, shi, 2);
    float ilo = 1.0f / slo, ihi = 1.0f / shi;

    // ---- stage P (tf32-rounded) into at[64][ATP] ----
    #pragma unroll
    for (int nt = 0; nt < 8; nt++) {
        int col = nt * 8 + 2 * c4;
        float2 vlo, vhi;
        vlo.x = rn_tf32(sacc[nt][0] * ilo);
        vlo.y = rn_tf32(sacc[nt][1] * ilo);
        vhi.x = rn_tf32(sacc[nt][2] * ihi);
        vhi.y = rn_tf32(sacc[nt][3] * ihi);
        *(float2*)&at[r_lo * ATP + col] = vlo;
        *(float2*)&at[r_hi * ATP + col] = vhi;
    }
    __syncwarp();   // warp-local: A-frags read only this warp's rows

    // ---- O = P V via mma ----
    float oacc[4][4];
    #pragma unroll
    for (int nt = 0; nt < 4; nt++)
        #pragma unroll
        for (int j = 0; j < 4; j++) oacc[nt][j] = 0.f;

    #pragma unroll
    for (int k8 = 0; k8 < 8; k8++) {
        int kb = k8 * 8;
        float a[4];
        a[0] = at[(m0 + r4) * ATP + kb + c4];
        a[1] = at[(m0 + r4 + 8) * ATP + kb + c4];
        a[2] = at[(m0 + r4) * ATP + kb + 4 + c4];
        a[3] = at[(m0 + r4 + 8) * ATP + kb + 4 + c4];
        #pragma unroll
        for (int nt = 0; nt < 4; nt++) {
            float bfr[2];
            bfr[0] = vsT[(nt * 8 + r4) * VP + kb + c4];
            bfr[1] = vsT[(nt * 8 + r4) * VP + kb + 4 + c4];
            mma8(oacc[nt], a, bfr);
        }
    }

    // ---- store to g_ao (pixel-major), tf32-rounded ----
    #pragma unroll
    for (int half = 0; half < 2; half++) {
        int row = (half == 0) ? r_lo : r_hi;
        int p = pbase + (row >> 3) * WDIM + (row & 7);
        float* dst = g_ao + (size_t)p * CDIM + h * HD;
        #pragma unroll
        for (int nt = 0; nt < 4; nt++) {
            float2 v;
            v.x = rn_tf32(oacc[nt][half * 2 + 0]);
            v.y = rn_tf32(oacc[nt][half * 2 + 1]);
            *(float2*)(dst + nt * 8 + 2 * c4) = v;
        }
    }
}

// =================================================================
// launch
// =================================================================
extern "C" void kernel_launch(void* const* d_in, const int* in_sizes, int n_in,
                              void* d_out, int out_size) {
    const float* x        = (const float*)d_in[0];
    const float* w_qk     = (const float*)d_in[1];
    const float* b_qk     = (const float*)d_in[2];
    const float* w_v      = (const float*)d_in[3];
    const float* b_v      = (const float*)d_in[4];
    const float* log_temp = (const float*)d_in[5];
    const float* pq_dw_w  = (const float*)d_in[6];
    const float* pq_dw_b  = (const float*)d_in[7];
    const float* pq_f1w   = (const float*)d_in[8];
    const float* pq_f1b   = (const float*)d_in[9];
    const float* pq_f2w   = (const float*)d_in[10];
    const float* pq_f2b   = (const float*)d_in[11];
    const float* pk_dw_w  = (const float*)d_in[12];
    const float* pk_dw_b  = (const float*)d_in[13];
    const float* pk_f1w   = (const float*)d_in[14];
    const float* pk_f1b   = (const float*)d_in[15];
    const float* pk_f2w   = (const float*)d_in[16];
    const float* pk_f2b   = (const float*)d_in[17];
    const float* pos_w    = (const float*)d_in[18];
    const float* pos_sc   = (const float*)d_in[20];
    const float* meta_w1  = (const float*)d_in[21];
    const float* meta_b1  = (const float*)d_in[22];
    const float* meta_w2  = (const float*)d_in[23];
    const float* meta_b2  = (const float*)d_in[24];
    const float* w_po     = (const float*)d_in[25];
    const float* w_proj   = (const float*)d_in[26];
    const float* b_proj   = (const float*)d_in[27];
    float* out = (float*)d_out;

    cudaFuncSetAttribute(gemm_mma<0>, cudaFuncAttributeMaxDynamicSharedMemorySize, GEMM_SMEM);
    cudaFuncSetAttribute(gemm_mma<1>, cudaFuncAttributeMaxDynamicSharedMemorySize, GEMM_SMEM);

    xpose_kernel<<<dim3(HWPIX / 32, CDIM / 32, BATCH), 256>>>(x);
    wprep_kernel<<<(QKVC * CDIM + 1023) / 1024, 1024>>>(w_qk, b_qk, w_v, b_v);
    wc_kernel<<<CDIM, CDIM>>>(w_proj, w_po);
    bias_kernel<<<225, 128>>>(pos_w, pos_sc, meta_w1, meta_b1, meta_w2, meta_b2);

    {
        const float* A; cudaGetSymbolAddress((void**)&A, g_xT);
        const float* Bp; cudaGetSymbolAddress((void**)&Bp, g_wb);
        const float* bb; cudaGetSymbolAddress((void**)&bb, g_bqkv);
        float* op; cudaGetSymbolAddress((void**)&op, g_qkv);
        gemm_mma<0><<<dim3(QKVC / 128, NPIX / 128), 256, GEMM_SMEM>>>(A, Bp, bb, op);
    }

    attn_kernel<<<NWIN * HEADS, 128>>>(log_temp,
        pq_dw_w, pq_dw_b, pq_f1w, pq_f1b, pq_f2w, pq_f2b,
        pk_dw_w, pk_dw_b, pk_f1w, pk_f1b, pk_f2w, pk_f2b);

    {
        const float* A; cudaGetSymbolAddress((void**)&A, g_ao);
        const float* Bp; cudaGetSymbolAddress((void**)&Bp, g_Wc);
        gemm_mma<1><<<dim3(CDIM / 128, NPIX / 128), 256, GEMM_SMEM>>>(A, Bp, b_proj, out);
    }
}

// round 6
// speedup vs baseline: 3.5907x; 1.3367x over previous
#include <cuda_runtime.h>
#include <cuda_fp16.h>
#include <cstdint>
#include <math.h>

// ---------------- problem constants ----------------
#define BATCH 4
#define CDIM  384
#define HDIM  128
#define WDIM  128
#define HWPIX 16384
#define NPIX  65536
#define HEADS 12
#define HD    32
#define WS    8
#define NTOK  64
#define NWIN  1024
#define QKVC  1152

// ---------------- device scratch ----------------
__device__ float  g_qkv[(size_t)NPIX * QKVC];   // per-pixel [q k v], fp32
__device__ __half g_aoh[(size_t)NPIX * CDIM];   // attn out, pixel-major, half
__device__ __half g_xTh[(size_t)NPIX * CDIM];   // x^T, half
__device__ __half g_wbh[QKVC * CDIM];           // [w_qk ; w_v], half
__device__ float  g_bqkv[QKVC];
__device__ float  g_bias[HEADS * 225];
__device__ __half g_Wch[CDIM * CDIM];           // w_proj @ w_po, half

// ---------------- helpers ----------------
__device__ __forceinline__ uint32_t smem_u32(const void* p) {
    uint32_t a;
    asm("{ .reg .u64 t; cvta.to.shared.u64 t, %1; cvt.u32.u64 %0, t; }" : "=r"(a) : "l"(p));
    return a;
}
__device__ __forceinline__ float rn_tf32(float v) {
    uint32_t u;
    asm("cvt.rna.tf32.f32 %0, %1;" : "=r"(u) : "f"(v));
    return __uint_as_float(u);
}
__device__ __forceinline__ void cp16(uint32_t saddr, const void* g) {
    asm volatile("cp.async.cg.shared.global [%0], [%1], 16;" :: "r"(saddr), "l"(g));
}
#define CP_COMMIT() asm volatile("cp.async.commit_group;" ::: "memory")
#define CP_WAIT0()  asm volatile("cp.async.wait_group 0;" ::: "memory")
#define CP_WAIT1()  asm volatile("cp.async.wait_group 1;" ::: "memory")

// fp16 m16n8k16 mma, fp32 accumulate
__device__ __forceinline__ void mma16(float* c, const uint32_t* a, const uint32_t* b) {
    asm volatile(
        "mma.sync.aligned.m16n8k16.row.col.f32.f16.f16.f32 "
        "{%0,%1,%2,%3}, {%4,%5,%6,%7}, {%8,%9}, {%0,%1,%2,%3};"
        : "+f"(c[0]), "+f"(c[1]), "+f"(c[2]), "+f"(c[3])
        : "r"(a[0]), "r"(a[1]), "r"(a[2]), "r"(a[3]),
          "r"(b[0]), "r"(b[1]));
}

// tf32 m16n8k8 mma (attention)
__device__ __forceinline__ void mma8(float* c, const float* a, const float* b) {
    asm volatile(
        "mma.sync.aligned.m16n8k8.row.col.f32.tf32.tf32.f32 "
        "{%0,%1,%2,%3}, {%4,%5,%6,%7}, {%8,%9}, {%0,%1,%2,%3};"
        : "+f"(c[0]), "+f"(c[1]), "+f"(c[2]), "+f"(c[3])
        : "r"(__float_as_uint(a[0])), "r"(__float_as_uint(a[1])),
          "r"(__float_as_uint(a[2])), "r"(__float_as_uint(a[3])),
          "r"(__float_as_uint(b[0])), "r"(__float_as_uint(b[1])));
}

// =================================================================
// transpose + fp16 convert: x (B,C,HW) -> g_xTh[p][c]
// =================================================================
__global__ void __launch_bounds__(256) xpose_kernel(const float* __restrict__ x) {
    __shared__ float t[32][33];
    int bx = blockIdx.x, by = blockIdx.y, bz = blockIdx.z;
    int tx = threadIdx.x & 31, ty = threadIdx.x >> 5;
    const float* src = x + ((size_t)(bz * CDIM + by * 32)) * HWPIX + bx * 32;
    #pragma unroll
    for (int i = 0; i < 32; i += 8)
        t[ty + i][tx] = src[(size_t)(ty + i) * HWPIX + tx];
    __syncthreads();
    __half* dst = g_xTh + ((size_t)(bz * HWPIX + bx * 32)) * CDIM + by * 32;
    #pragma unroll
    for (int i = 0; i < 32; i += 8)
        dst[(size_t)(ty + i) * CDIM + tx] = __float2half_rn(t[tx][ty + i]);
}

// =================================================================
// weight prep (fp16)
// =================================================================
__global__ void wprep_kernel(const float* __restrict__ w_qk, const float* __restrict__ b_qk,
                             const float* __restrict__ w_v,  const float* __restrict__ b_v) {
    int i = blockIdx.x * 1024 + threadIdx.x;
    if (i < QKVC * CDIM) {
        float v = (i < 2 * CDIM * CDIM) ? w_qk[i] : w_v[i - 2 * CDIM * CDIM];
        g_wbh[i] = __float2half_rn(v);
    }
    if (i < QKVC)
        g_bqkv[i] = (i < 2 * CDIM) ? b_qk[i] : b_v[i - 2 * CDIM];
}

__global__ void wc_kernel(const float* __restrict__ w_proj,
                          const float* __restrict__ w_po) {
    int o = blockIdx.x;
    int c = threadIdx.x;
    const float* pr = w_proj + o * CDIM;
    float a0 = 0.f, a1 = 0.f, a2 = 0.f, a3 = 0.f;
    for (int t = 0; t < CDIM; t += 4) {
        a0 += pr[t] * w_po[t * CDIM + c];
        a1 += pr[t + 1] * w_po[(t + 1) * CDIM + c];
        a2 += pr[t + 2] * w_po[(t + 2) * CDIM + c];
        a3 += pr[t + 3] * w_po[(t + 3) * CDIM + c];
    }
    g_Wch[o * CDIM + c] = __float2half_rn((a0 + a1) + (a2 + a3));
}

// =================================================================
// relative-position bias (225 deltas)
// =================================================================
__global__ void bias_kernel(const float* __restrict__ pcw,
                            const float* __restrict__ psc,
                            const float* __restrict__ mw1,
                            const float* __restrict__ mb1,
                            const float* __restrict__ mw2,
                            const float* __restrict__ mb2) {
    __shared__ __align__(16) float rel[CDIM];
    __shared__ __align__(16) float hid[128];
    int idx = blockIdx.x;
    float dx = (float)((idx % 15) - 7) * (2.0f / 7.0f);
    float dy = (float)((idx / 15) - 7) * (2.0f / 7.0f);
    int t = threadIdx.x;
    float sc = psc[0];
    for (int c = t; c < CDIM; c += 128)
        rel[c] = sc * (pcw[2 * c] * dx + pcw[2 * c + 1] * dy);
    __syncthreads();
    {
        float a0 = 0.f, a1 = 0.f, a2 = 0.f, a3 = 0.f;
        const float4* w = (const float4*)(mw1 + t * CDIM);
        const float4* r = (const float4*)rel;
        #pragma unroll 4
        for (int c = 0; c < CDIM / 4; c++) {
            float4 wv = w[c], rv = r[c];
            a0 += wv.x * rv.x; a1 += wv.y * rv.y;
            a2 += wv.z * rv.z; a3 += wv.w * rv.w;
        }
        float s = mb1[t] + (a0 + a1) + (a2 + a3);
        hid[t] = 0.5f * s * (1.0f + erff(s * 0.70710678118654752f));
    }
    __syncthreads();
    if (t < HEADS) {
        float a0 = 0.f, a1 = 0.f, a2 = 0.f, a3 = 0.f;
        const float4* w2 = (const float4*)(mw2 + t * 128);
        const float4* hh = (const float4*)hid;
        #pragma unroll 4
        for (int j = 0; j < 32; j++) {
            float4 wv = w2[j], hv = hh[j];
            a0 += wv.x * hv.x; a1 += wv.y * hv.y;
            a2 += wv.z * hv.z; a3 += wv.w * hv.w;
        }
        g_bias[t * 225 + idx] = mb2[t] + (a0 + a1) + (a2 + a3);
    }
}

// =================================================================
// fp16 mma.sync GEMM: C[m0:128, n0:128] = A[m,384] * B[n,384]^T (+bias)
// BK=64, pitch 72 halves, 256 threads, 8 warps (4m x 2n), warp 32x64
// MODE 0: A=g_xTh, B=g_wbh, out=g_qkv[p][o] fp32, bias=g_bqkv
// MODE 1: A=g_aoh, B=g_Wch, out=channel-major (B,C,H,W) fp32, bias=b_proj
// =================================================================
#define HP   72                    // smem pitch in halves
#define KCH  64                    // K per chunk
#define NCH  6                     // 384/64
#define GEMM_SMEM (4 * 128 * HP * 2)

template <int MODE>
__global__ void __launch_bounds__(256) gemm_mma(
        const __half* __restrict__ Aptr, const __half* __restrict__ Bptr,
        const float* __restrict__ biasptr, float* __restrict__ outp) {
    extern __shared__ __align__(16) __half smh[];
    __half* AsB[2] = { smh, smh + 128 * HP };
    __half* BsB[2] = { smh + 2 * 128 * HP, smh + 3 * 128 * HP };

    int tid = threadIdx.x;
    int n0 = blockIdx.x * 128;
    int m0 = blockIdx.y * 128;
    int lane = tid & 31, wid = tid >> 5;
    int wm = (wid & 3) * 32;
    int wn = (wid >> 2) * 64;

    const __half* Arow = Aptr + (size_t)m0 * CDIM;
    const __half* Brow = Bptr + (size_t)n0 * CDIM;
    uint32_t aU[2] = { smem_u32(AsB[0]), smem_u32(AsB[1]) };
    uint32_t bU[2] = { smem_u32(BsB[0]), smem_u32(BsB[1]) };

    int ldrow = tid >> 3, ldseg = tid & 7;   // 32 rows/pass, 4 passes, 8 segs of 8 halves
    auto load_chunk = [&](int k0, int buf) {
        #pragma unroll
        for (int i = 0; i < 4; i++) {
            int row = ldrow + i * 32;
            uint32_t so = (uint32_t)(row * HP + ldseg * 8) * 2;
            cp16(aU[buf] + so, Arow + (size_t)row * CDIM + k0 + ldseg * 8);
            cp16(bU[buf] + so, Brow + (size_t)row * CDIM + k0 + ldseg * 8);
        }
        CP_COMMIT();
    };

    float acc[2][8][4];
    #pragma unroll
    for (int mt = 0; mt < 2; mt++)
        #pragma unroll
        for (int nt = 0; nt < 8; nt++)
            #pragma unroll
            for (int j = 0; j < 4; j++) acc[mt][nt][j] = 0.f;

    load_chunk(0, 0);

    int r4 = lane >> 2, c4 = lane & 3;
    for (int i = 0; i < NCH; i++) {
        if (i + 1 < NCH) { load_chunk((i + 1) * KCH, (i + 1) & 1); CP_WAIT1(); }
        else             { CP_WAIT0(); }
        __syncthreads();
        const __half* Ab = AsB[i & 1];
        const __half* Bb = BsB[i & 1];
        #pragma unroll
        for (int kk = 0; kk < 4; kk++) {
            int kb = kk * 16;
            uint32_t a[2][4];
            #pragma unroll
            for (int mt = 0; mt < 2; mt++) {
                int row = wm + mt * 16 + r4;
                a[mt][0] = *(const uint32_t*)&Ab[row * HP + kb + 2 * c4];
                a[mt][1] = *(const uint32_t*)&Ab[(row + 8) * HP + kb + 2 * c4];
                a[mt][2] = *(const uint32_t*)&Ab[row * HP + kb + 2 * c4 + 8];
                a[mt][3] = *(const uint32_t*)&Ab[(row + 8) * HP + kb + 2 * c4 + 8];
            }
            uint32_t b[8][2];
            #pragma unroll
            for (int nt = 0; nt < 8; nt++) {
                int nrow = wn + nt * 8 + r4;
                b[nt][0] = *(const uint32_t*)&Bb[nrow * HP + kb + 2 * c4];
                b[nt][1] = *(const uint32_t*)&Bb[nrow * HP + kb + 2 * c4 + 8];
            }
            #pragma unroll
            for (int mt = 0; mt < 2; mt++)
                #pragma unroll
                for (int nt = 0; nt < 8; nt++)
                    mma16(acc[mt][nt], a[mt], b[nt]);
        }
        __syncthreads();
    }

    int cb = c4 * 2;
    if (MODE == 0) {
        #pragma unroll
        for (int mt = 0; mt < 2; mt++)
            #pragma unroll
            for (int half = 0; half < 2; half++) {
                int m = m0 + wm + mt * 16 + r4 + half * 8;
                float* dst = g_qkv + (size_t)m * QKVC + n0 + wn;
                #pragma unroll
                for (int nt = 0; nt < 8; nt++) {
                    int o = n0 + wn + nt * 8 + cb;
                    float2 v;
                    v.x = acc[mt][nt][half * 2 + 0] + biasptr[o];
                    v.y = acc[mt][nt][half * 2 + 1] + biasptr[o + 1];
                    *(float2*)(dst + nt * 8 + cb) = v;
                }
            }
    } else {
        int b = m0 >> 14;
        int ppb = m0 & (HWPIX - 1);
        #pragma unroll
        for (int mt = 0; mt < 2; mt++)
            #pragma unroll
            for (int half = 0; half < 2; half++) {
                int pp = ppb + wm + mt * 16 + r4 + half * 8;
                #pragma unroll
                for (int nt = 0; nt < 8; nt++)
                    #pragma unroll
                    for (int j = 0; j < 2; j++) {
                        int o = n0 + wn + nt * 8 + cb + j;
                        outp[((size_t)(b * CDIM + o)) * HWPIX + pp] =
                            acc[mt][nt][half * 2 + j] + biasptr[o];
                    }
            }
    }
}

// =================================================================
// PDSCA gate (rounds gated output to tf32)
// =================================================================
__device__ __forceinline__ void pdsca_gate(
        float* xs, float* scr, float* gap, float* hid, float* ca,
        const float* __restrict__ dw_w, const float* __restrict__ dw_b,
        const float* __restrict__ f1w,  const float* __restrict__ f1b,
        const float* __restrict__ f2w,  const float* __restrict__ f2b,
        int t) {
    for (int idx = t; idx < 2048; idx += 128) {
        int c = idx >> 6, s = idx & 63, sy = s >> 3, sx = s & 7;
        float sum = dw_b[c];
        #pragma unroll
        for (int ky = 0; ky < 3; ky++) {
            int iy = sy + ky - 1;
            if (iy < 0 || iy > 7) continue;
            #pragma unroll
            for (int kx = 0; kx < 3; kx++) {
                int ix = sx + kx - 1;
                if (ix < 0 || ix > 7) continue;
                int s2 = iy * 8 + ix;
                sum += dw_w[c * 9 + ky * 3 + kx] *
                       xs[(2 * c + (s2 >> 5)) * 36 + (s2 & 31)];
            }
        }
        scr[idx] = sum;
    }
    if (t < 32) {
        float s = 0.f;
        #pragma unroll
        for (int d = 0; d < 32; d++)
            s += xs[(2 * t) * 36 + d] + xs[(2 * t + 1) * 36 + d];
        gap[t] = s * (1.0f / 64.0f);
    }
    __syncthreads();
    if (t < 8) {
        float s = f1b[t];
        #pragma unroll
        for (int c = 0; c < 32; c++) s += gap[c] * f1w[t * 32 + c];
        hid[t] = fmaxf(s, 0.f);
    }
    __syncthreads();
    if (t < 32) {
        float s = f2b[t];
        #pragma unroll
        for (int j = 0; j < 8; j++) s += hid[j] * f2w[t * 8 + j];
        ca[t] = s;
    }
    __syncthreads();
    for (int idx = t; idx < 2048; idx += 128) {
        int c = idx >> 6, s = idx & 63;
        float m = scr[idx] + ca[c];
        float g = 1.0f / (1.0f + __expf(-m));
        int off = (2 * c + (s >> 5)) * 36 + (s & 31);
        xs[off] = rn_tf32(xs[off] * g);
    }
    __syncthreads();
}

// =================================================================
// per-(window, head) PDSCA + attention via tf32 mma; writes half g_aoh
// =================================================================
#define ATP 68
#define VP  68

__global__ void __launch_bounds__(128) attn_kernel(
        const float* __restrict__ log_temp,
        const float* __restrict__ pqw,  const float* __restrict__ pqb,
        const float* __restrict__ pqf1w, const float* __restrict__ pqf1b,
        const float* __restrict__ pqf2w, const float* __restrict__ pqf2b,
        const float* __restrict__ pkw,  const float* __restrict__ pkb,
        const float* __restrict__ pkf1w, const float* __restrict__ pkf1b,
        const float* __restrict__ pkf2w, const float* __restrict__ pkf2b) {
    __shared__ __align__(16) float qs[NTOK * 36];
    __shared__ __align__(16) float ks[NTOK * 36];
    __shared__ __align__(16) float vsT[HD * VP];
    __shared__ __align__(16) float at[NTOK * ATP];
    __shared__ float gap[32], hid[8], ca[32];

    int bi  = blockIdx.x;
    int win = bi / HEADS;
    int h   = bi - win * HEADS;
    int t   = threadIdx.x;
    int b   = win >> 8, hb = (win >> 4) & 15, wb = win & 15;
    int pbase = b * HWPIX + hb * 8 * WDIM + wb * 8;

    for (int tt = t; tt < 512; tt += 128) {
        int n = tt >> 3, d4 = (tt & 7) * 4;
        int p = pbase + (n >> 3) * WDIM + (n & 7);
        const float* src = g_qkv + (size_t)p * QKVC + h * HD + d4;
        float4 qv = *(const float4*)(src);
        float4 kv = *(const float4*)(src + CDIM);
        float4 vv = *(const float4*)(src + 2 * CDIM);
        *(float4*)&qs[n * 36 + d4] = qv;
        *(float4*)&ks[n * 36 + d4] = kv;
        vsT[(d4 + 0) * VP + n] = rn_tf32(vv.x);
        vsT[(d4 + 1) * VP + n] = rn_tf32(vv.y);
        vsT[(d4 + 2) * VP + n] = rn_tf32(vv.z);
        vsT[(d4 + 3) * VP + n] = rn_tf32(vv.w);
    }
    __syncthreads();

    pdsca_gate(qs, at, gap, hid, ca, pqw, pqb, pqf1w, pqf1b, pqf2w, pqf2b, t);
    pdsca_gate(ks, at, gap, hid, ca, pkw, pkb, pkf1w, pkf1b, pkf2w, pkf2b, t);

    int lane = t & 31, w = t >> 5;
    int r4 = lane >> 2, c4 = lane & 3;
    int m0 = w * 16;

    float sacc[8][4];
    #pragma unroll
    for (int nt = 0; nt < 8; nt++)
        #pragma unroll
        for (int j = 0; j < 4; j++) sacc[nt][j] = 0.f;

    #pragma unroll
    for (int kt = 0; kt < 4; kt++) {
        int kb = kt * 8;
        float a[4];
        a[0] = qs[(m0 + r4) * 36 + kb + c4];
        a[1] = qs[(m0 + r4 + 8) * 36 + kb + c4];
        a[2] = qs[(m0 + r4) * 36 + kb + 4 + c4];
        a[3] = qs[(m0 + r4 + 8) * 36 + kb + 4 + c4];
        #pragma unroll
        for (int nt = 0; nt < 8; nt++) {
            float bfr[2];
            bfr[0] = ks[(nt * 8 + r4) * 36 + kb + c4];
            bfr[1] = ks[(nt * 8 + r4) * 36 + kb + 4 + c4];
            mma8(sacc[nt], a, bfr);
        }
    }

    float temp = __expf(log_temp[0]);
    const float* brow = g_bias + h * 225;
    int r_lo = m0 + r4, r_hi = r_lo + 8;
    int ylo = r_lo >> 3, xlo = r_lo & 7;
    int yhi = r_hi >> 3, xhi = r_hi & 7;

    float mlo = -1e30f, mhi = -1e30f;
    #pragma unroll
    for (int nt = 0; nt < 8; nt++)
        #pragma unroll
        for (int j = 0; j < 2; j++) {
            int col = nt * 8 + 2 * c4 + j;
            int cy = col >> 3, cx = col & 7;
            float blo = brow[(ylo - cy + 7) * 15 + (xlo - cx + 7)];
            float bhi = brow[(yhi - cy + 7) * 15 + (xhi - cx + 7)];
            sacc[nt][j]     = sacc[nt][j] * temp + blo;
            sacc[nt][2 + j] = sacc[nt][2 + j] * temp + bhi;
            mlo = fmaxf(mlo, sacc[nt][j]);
            mhi = fmaxf(mhi, sacc[nt][2 + j]);
        }
    mlo = fmaxf(mlo, __shfl_xor_sync(0xffffffffu, mlo, 1));
    mlo = fmaxf(mlo, __shfl_xor_sync(0xffffffffu, mlo, 2));
    mhi = fmaxf(mhi, __shfl_xor_sync(0xffffffffu, mhi, 1));
    mhi = fmaxf(mhi, __shfl_xor_sync(0xffffffffu, mhi, 2));

    float slo = 0.f, shi = 0.f;
    #pragma unroll
    for (int nt = 0; nt < 8; nt++)
        #pragma unroll
        for (int j = 0; j < 2; j++) {
            float e0 = __expf(sacc[nt][j] - mlo);
            float e1 = __expf(sacc[nt][2 + j] - mhi);
            sacc[nt][j] = e0; sacc[nt][2 + j] = e1;
            slo += e0; shi += e1;
        }
    slo += __shfl_xor_sync(0xffffffffu, slo, 1);
    slo += __shfl_xor_sync(0xffffffffu, slo, 2);
    shi += __shfl_xor_sync(0xffffffffu, shi, 1);
    shi += __shfl_xor_sync(0xffffffffu, shi, 2);
    float ilo = 1.0f / slo, ihi = 1.0f / shi;

    #pragma unroll
    for (int nt = 0; nt < 8; nt++) {
        int col = nt * 8 + 2 * c4;
        float2 vlo, vhi;
        vlo.x = rn_tf32(sacc[nt][0] * ilo);
        vlo.y = rn_tf32(sacc[nt][1] * ilo);
        vhi.x = rn_tf32(sacc[nt][2] * ihi);
        vhi.y = rn_tf32(sacc[nt][3] * ihi);
        *(float2*)&at[r_lo * ATP + col] = vlo;
        *(float2*)&at[r_hi * ATP + col] = vhi;
    }
    __syncwarp();

    float oacc[4][4];
    #pragma unroll
    for (int nt = 0; nt < 4; nt++)
        #pragma unroll
        for (int j = 0; j < 4; j++) oacc[nt][j] = 0.f;

    #pragma unroll
    for (int k8 = 0; k8 < 8; k8++) {
        int kb = k8 * 8;
        float a[4];
        a[0] = at[(m0 + r4) * ATP + kb + c4];
        a[1] = at[(m0 + r4 + 8) * ATP + kb + c4];
        a[2] = at[(m0 + r4) * ATP + kb + 4 + c4];
        a[3] = at[(m0 + r4 + 8) * ATP + kb + 4 + c4];
        #pragma unroll
        for (int nt = 0; nt < 4; nt++) {
            float bfr[2];
            bfr[0] = vsT[(nt * 8 + r4) * VP + kb + c4];
            bfr[1] = vsT[(nt * 8 + r4) * VP + kb + 4 + c4];
            mma8(oacc[nt], a, bfr);
        }
    }

    // ---- store to g_aoh (pixel-major, half2) ----
    #pragma unroll
    for (int half = 0; half < 2; half++) {
        int row = (half == 0) ? r_lo : r_hi;
        int p = pbase + (row >> 3) * WDIM + (row & 7);
        __half2* dst = (__half2*)(g_aoh + (size_t)p * CDIM + h * HD);
        #pragma unroll
        for (int nt = 0; nt < 4; nt++)
            dst[(nt * 8 + 2 * c4) >> 1] =
                __floats2half2_rn(oacc[nt][half * 2 + 0], oacc[nt][half * 2 + 1]);
    }
}

// =================================================================
// launch
// =================================================================
extern "C" void kernel_launch(void* const* d_in, const int* in_sizes, int n_in,
                              void* d_out, int out_size) {
    const float* x        = (const float*)d_in[0];
    const float* w_qk     = (const float*)d_in[1];
    const float* b_qk     = (const float*)d_in[2];
    const float* w_v      = (const float*)d_in[3];
    const float* b_v      = (const float*)d_in[4];
    const float* log_temp = (const float*)d_in[5];
    const float* pq_dw_w  = (const float*)d_in[6];
    const float* pq_dw_b  = (const float*)d_in[7];
    const float* pq_f1w   = (const float*)d_in[8];
    const float* pq_f1b   = (const float*)d_in[9];
    const float* pq_f2w   = (const float*)d_in[10];
    const float* pq_f2b   = (const float*)d_in[11];
    const float* pk_dw_w  = (const float*)d_in[12];
    const float* pk_dw_b  = (const float*)d_in[13];
    const float* pk_f1w   = (const float*)d_in[14];
    const float* pk_f1b   = (const float*)d_in[15];
    const float* pk_f2w   = (const float*)d_in[16];
    const float* pk_f2b   = (const float*)d_in[17];
    const float* pos_w    = (const float*)d_in[18];
    const float* pos_sc   = (const float*)d_in[20];
    const float* meta_w1  = (const float*)d_in[21];
    const float* meta_b1  = (const float*)d_in[22];
    const float* meta_w2  = (const float*)d_in[23];
    const float* meta_b2  = (const float*)d_in[24];
    const float* w_po     = (const float*)d_in[25];
    const float* w_proj   = (const float*)d_in[26];
    const float* b_proj   = (const float*)d_in[27];
    float* out = (float*)d_out;

    cudaFuncSetAttribute(gemm_mma<0>, cudaFuncAttributeMaxDynamicSharedMemorySize, GEMM_SMEM);
    cudaFuncSetAttribute(gemm_mma<1>, cudaFuncAttributeMaxDynamicSharedMemorySize, GEMM_SMEM);

    xpose_kernel<<<dim3(HWPIX / 32, CDIM / 32, BATCH), 256>>>(x);
    wprep_kernel<<<(QKVC * CDIM + 1023) / 1024, 1024>>>(w_qk, b_qk, w_v, b_v);
    wc_kernel<<<CDIM, CDIM>>>(w_proj, w_po);
    bias_kernel<<<225, 128>>>(pos_w, pos_sc, meta_w1, meta_b1, meta_w2, meta_b2);

    {
        const __half* A; cudaGetSymbolAddress((void**)&A, g_xTh);
        const __half* Bp; cudaGetSymbolAddress((void**)&Bp, g_wbh);
        const float* bb; cudaGetSymbolAddress((void**)&bb, g_bqkv);
        float* op; cudaGetSymbolAddress((void**)&op, g_qkv);
        gemm_mma<0><<<dim3(QKVC / 128, NPIX / 128), 256, GEMM_SMEM>>>(A, Bp, bb, op);
    }

    attn_kernel<<<NWIN * HEADS, 128>>>(log_temp,
        pq_dw_w, pq_dw_b, pq_f1w, pq_f1b, pq_f2w, pq_f2b,
        pk_dw_w, pk_dw_b, pk_f1w, pk_f1b, pk_f2w, pk_f2b);

    {
        const __half* A; cudaGetSymbolAddress((void**)&A, g_aoh);
        const __half* Bp; cudaGetSymbolAddress((void**)&Bp, g_Wch);
        gemm_mma<1><<<dim3(CDIM / 128, NPIX / 128), 256, GEMM_SMEM>>>(A, Bp, b_proj, out);
    }
}

// round 7
// speedup vs baseline: 3.6475x; 1.0158x over previous
#include <cuda_runtime.h>
#include <cuda_fp16.h>
#include <cstdint>
#include <math.h>

// ---------------- problem constants ----------------
#define BATCH 4
#define CDIM  384
#define HDIM  128
#define WDIM  128
#define HWPIX 16384
#define NPIX  65536
#define HEADS 12
#define HD    32
#define WS    8
#define NTOK  64
#define NWIN  1024
#define QKVC  1152

// ---------------- device scratch ----------------
__device__ __half g_qkvh[(size_t)NPIX * QKVC];  // per-pixel [q k v], half
__device__ __half g_aoh[(size_t)NPIX * CDIM];   // attn out, pixel-major, half
__device__ __half g_xTh[(size_t)NPIX * CDIM];   // x^T, half
__device__ __half g_wbh[QKVC * CDIM];           // [w_qk ; w_v], half
__device__ float  g_bqkv[QKVC];
__device__ float  g_bias[HEADS * 225];
__device__ __half g_Wch[CDIM * CDIM];           // w_proj @ w_po, half

// ---------------- helpers ----------------
__device__ __forceinline__ uint32_t smem_u32(const void* p) {
    uint32_t a;
    asm("{ .reg .u64 t; cvta.to.shared.u64 t, %1; cvt.u32.u64 %0, t; }" : "=r"(a) : "l"(p));
    return a;
}
__device__ __forceinline__ float rn_tf32(float v) {
    uint32_t u;
    asm("cvt.rna.tf32.f32 %0, %1;" : "=r"(u) : "f"(v));
    return __uint_as_float(u);
}
__device__ __forceinline__ void cp16(uint32_t saddr, const void* g) {
    asm volatile("cp.async.cg.shared.global [%0], [%1], 16;" :: "r"(saddr), "l"(g));
}
#define CP_COMMIT() asm volatile("cp.async.commit_group;" ::: "memory")
#define CP_WAIT0()  asm volatile("cp.async.wait_group 0;" ::: "memory")
#define CP_WAIT1()  asm volatile("cp.async.wait_group 1;" ::: "memory")

// fp16 m16n8k16 mma, fp32 accumulate
__device__ __forceinline__ void mma16(float* c, const uint32_t* a, const uint32_t* b) {
    asm volatile(
        "mma.sync.aligned.m16n8k16.row.col.f32.f16.f16.f32 "
        "{%0,%1,%2,%3}, {%4,%5,%6,%7}, {%8,%9}, {%0,%1,%2,%3};"
        : "+f"(c[0]), "+f"(c[1]), "+f"(c[2]), "+f"(c[3])
        : "r"(a[0]), "r"(a[1]), "r"(a[2]), "r"(a[3]),
          "r"(b[0]), "r"(b[1]));
}

// tf32 m16n8k8 mma (attention)
__device__ __forceinline__ void mma8(float* c, const float* a, const float* b) {
    asm volatile(
        "mma.sync.aligned.m16n8k8.row.col.f32.tf32.tf32.f32 "
        "{%0,%1,%2,%3}, {%4,%5,%6,%7}, {%8,%9}, {%0,%1,%2,%3};"
        : "+f"(c[0]), "+f"(c[1]), "+f"(c[2]), "+f"(c[3])
        : "r"(__float_as_uint(a[0])), "r"(__float_as_uint(a[1])),
          "r"(__float_as_uint(a[2])), "r"(__float_as_uint(a[3])),
          "r"(__float_as_uint(b[0])), "r"(__float_as_uint(b[1])));
}

// =================================================================
// transpose + fp16 convert: x (B,C,HW) -> g_xTh[p][c]
// =================================================================
__global__ void __launch_bounds__(256) xpose_kernel(const float* __restrict__ x) {
    __shared__ float t[32][33];
    int bx = blockIdx.x, by = blockIdx.y, bz = blockIdx.z;
    int tx = threadIdx.x & 31, ty = threadIdx.x >> 5;
    const float* src = x + ((size_t)(bz * CDIM + by * 32)) * HWPIX + bx * 32;
    #pragma unroll
    for (int i = 0; i < 32; i += 8)
        t[ty + i][tx] = src[(size_t)(ty + i) * HWPIX + tx];
    __syncthreads();
    __half* dst = g_xTh + ((size_t)(bz * HWPIX + bx * 32)) * CDIM + by * 32;
    #pragma unroll
    for (int i = 0; i < 32; i += 8)
        dst[(size_t)(ty + i) * CDIM + tx] = __float2half_rn(t[tx][ty + i]);
}

// =================================================================
// weight prep (fp16)
// =================================================================
__global__ void wprep_kernel(const float* __restrict__ w_qk, const float* __restrict__ b_qk,
                             const float* __restrict__ w_v,  const float* __restrict__ b_v) {
    int i = blockIdx.x * 1024 + threadIdx.x;
    if (i < QKVC * CDIM) {
        float v = (i < 2 * CDIM * CDIM) ? w_qk[i] : w_v[i - 2 * CDIM * CDIM];
        g_wbh[i] = __float2half_rn(v);
    }
    if (i < QKVC)
        g_bqkv[i] = (i < 2 * CDIM) ? b_qk[i] : b_v[i - 2 * CDIM];
}

__global__ void wc_kernel(const float* __restrict__ w_proj,
                          const float* __restrict__ w_po) {
    int o = blockIdx.x;
    int c = threadIdx.x;
    const float* pr = w_proj + o * CDIM;
    float a0 = 0.f, a1 = 0.f, a2 = 0.f, a3 = 0.f;
    for (int t = 0; t < CDIM; t += 4) {
        a0 += pr[t] * w_po[t * CDIM + c];
        a1 += pr[t + 1] * w_po[(t + 1) * CDIM + c];
        a2 += pr[t + 2] * w_po[(t + 2) * CDIM + c];
        a3 += pr[t + 3] * w_po[(t + 3) * CDIM + c];
    }
    g_Wch[o * CDIM + c] = __float2half_rn((a0 + a1) + (a2 + a3));
}

// =================================================================
// relative-position bias (225 deltas) — split-dot, 256 threads
// =================================================================
__global__ void __launch_bounds__(256) bias_kernel(
        const float* __restrict__ pcw,
        const float* __restrict__ psc,
        const float* __restrict__ mw1,
        const float* __restrict__ mb1,
        const float* __restrict__ mw2,
        const float* __restrict__ mb2) {
    __shared__ __align__(16) float rel[CDIM];
    __shared__ __align__(16) float hid[128];
    __shared__ float part[256];
    int idx = blockIdx.x;
    float dx = (float)((idx % 15) - 7) * (2.0f / 7.0f);
    float dy = (float)((idx / 15) - 7) * (2.0f / 7.0f);
    int t = threadIdx.x;
    int u = t & 127, hv2 = t >> 7;          // hidden unit, which half of CDIM
    float sc = psc[0];
    for (int c = t; c < CDIM; c += 256)
        rel[c] = sc * (pcw[2 * c] * dx + pcw[2 * c + 1] * dy);
    __syncthreads();
    {
        float a0 = 0.f, a1 = 0.f, a2 = 0.f, a3 = 0.f;
        const float4* w = (const float4*)(mw1 + u * CDIM + hv2 * 192);
        const float4* r = (const float4*)(rel + hv2 * 192);
        #pragma unroll 4
        for (int c = 0; c < 48; c++) {
            float4 wv = w[c], rv = r[c];
            a0 += wv.x * rv.x; a1 += wv.y * rv.y;
            a2 += wv.z * rv.z; a3 += wv.w * rv.w;
        }
        part[t] = (a0 + a1) + (a2 + a3);
    }
    __syncthreads();
    if (t < 128) {
        float s = mb1[t] + part[t] + part[t + 128];
        hid[t] = 0.5f * s * (1.0f + erff(s * 0.70710678118654752f));
    }
    __syncthreads();
    if (t < HEADS) {
        float a0 = 0.f, a1 = 0.f, a2 = 0.f, a3 = 0.f;
        const float4* w2 = (const float4*)(mw2 + t * 128);
        const float4* hh = (const float4*)hid;
        #pragma unroll 4
        for (int j = 0; j < 32; j++) {
            float4 wv = w2[j], hvv = hh[j];
            a0 += wv.x * hvv.x; a1 += wv.y * hvv.y;
            a2 += wv.z * hvv.z; a3 += wv.w * hvv.w;
        }
        g_bias[t * 225 + idx] = mb2[t] + (a0 + a1) + (a2 + a3);
    }
}

// =================================================================
// fp16 mma.sync GEMM: C[m0:128, n0:128] = A[m,384] * B[n,384]^T (+bias)
// BK=64, pitch 72 halves, 256 threads, 8 warps (4m x 2n), warp 32x64
// MODE 0: A=g_xTh, B=g_wbh, out=g_qkvh (half, stride 1152), bias=g_bqkv
// MODE 1: A=g_aoh, B=g_Wch, out=channel-major (B,C,H,W) fp32, bias=b_proj
// =================================================================
#define HP   72
#define KCH  64
#define NCH  6
#define GEMM_SMEM (4 * 128 * HP * 2)

template <int MODE>
__global__ void __launch_bounds__(256) gemm_mma(
        const __half* __restrict__ Aptr, const __half* __restrict__ Bptr,
        const float* __restrict__ biasptr, void* __restrict__ outp) {
    extern __shared__ __align__(16) __half smh[];
    __half* AsB[2] = { smh, smh + 128 * HP };
    __half* BsB[2] = { smh + 2 * 128 * HP, smh + 3 * 128 * HP };

    int tid = threadIdx.x;
    int n0 = blockIdx.x * 128;
    int m0 = blockIdx.y * 128;
    int lane = tid & 31, wid = tid >> 5;
    int wm = (wid & 3) * 32;
    int wn = (wid >> 2) * 64;

    const __half* Arow = Aptr + (size_t)m0 * CDIM;
    const __half* Brow = Bptr + (size_t)n0 * CDIM;
    uint32_t aU[2] = { smem_u32(AsB[0]), smem_u32(AsB[1]) };
    uint32_t bU[2] = { smem_u32(BsB[0]), smem_u32(BsB[1]) };

    int ldrow = tid >> 3, ldseg = tid & 7;
    auto load_chunk = [&](int k0, int buf) {
        #pragma unroll
        for (int i = 0; i < 4; i++) {
            int row = ldrow + i * 32;
            uint32_t so = (uint32_t)(row * HP + ldseg * 8) * 2;
            cp16(aU[buf] + so, Arow + (size_t)row * CDIM + k0 + ldseg * 8);
            cp16(bU[buf] + so, Brow + (size_t)row * CDIM + k0 + ldseg * 8);
        }
        CP_COMMIT();
    };

    float acc[2][8][4];
    #pragma unroll
    for (int mt = 0; mt < 2; mt++)
        #pragma unroll
        for (int nt = 0; nt < 8; nt++)
            #pragma unroll
            for (int j = 0; j < 4; j++) acc[mt][nt][j] = 0.f;

    load_chunk(0, 0);

    int r4 = lane >> 2, c4 = lane & 3;
    for (int i = 0; i < NCH; i++) {
        if (i + 1 < NCH) { load_chunk((i + 1) * KCH, (i + 1) & 1); CP_WAIT1(); }
        else             { CP_WAIT0(); }
        __syncthreads();
        const __half* Ab = AsB[i & 1];
        const __half* Bb = BsB[i & 1];
        #pragma unroll
        for (int kk = 0; kk < 4; kk++) {
            int kb = kk * 16;
            uint32_t a[2][4];
            #pragma unroll
            for (int mt = 0; mt < 2; mt++) {
                int row = wm + mt * 16 + r4;
                a[mt][0] = *(const uint32_t*)&Ab[row * HP + kb + 2 * c4];
                a[mt][1] = *(const uint32_t*)&Ab[(row + 8) * HP + kb + 2 * c4];
                a[mt][2] = *(const uint32_t*)&Ab[row * HP + kb + 2 * c4 + 8];
                a[mt][3] = *(const uint32_t*)&Ab[(row + 8) * HP + kb + 2 * c4 + 8];
            }
            uint32_t b[8][2];
            #pragma unroll
            for (int nt = 0; nt < 8; nt++) {
                int nrow = wn + nt * 8 + r4;
                b[nt][0] = *(const uint32_t*)&Bb[nrow * HP + kb + 2 * c4];
                b[nt][1] = *(const uint32_t*)&Bb[nrow * HP + kb + 2 * c4 + 8];
            }
            #pragma unroll
            for (int mt = 0; mt < 2; mt++)
                #pragma unroll
                for (int nt = 0; nt < 8; nt++)
                    mma16(acc[mt][nt], a[mt], b[nt]);
        }
        __syncthreads();
    }

    int cb = c4 * 2;
    if (MODE == 0) {
        __half* oph = (__half*)outp;
        #pragma unroll
        for (int mt = 0; mt < 2; mt++)
            #pragma unroll
            for (int half = 0; half < 2; half++) {
                int m = m0 + wm + mt * 16 + r4 + half * 8;
                __half* dst = oph + (size_t)m * QKVC + n0 + wn;
                #pragma unroll
                for (int nt = 0; nt < 8; nt++) {
                    int o = n0 + wn + nt * 8 + cb;
                    *(__half2*)(dst + nt * 8 + cb) = __floats2half2_rn(
                        acc[mt][nt][half * 2 + 0] + biasptr[o],
                        acc[mt][nt][half * 2 + 1] + biasptr[o + 1]);
                }
            }
    } else {
        float* opf = (float*)outp;
        int b = m0 >> 14;
        int ppb = m0 & (HWPIX - 1);
        #pragma unroll
        for (int mt = 0; mt < 2; mt++)
            #pragma unroll
            for (int half = 0; half < 2; half++) {
                int pp = ppb + wm + mt * 16 + r4 + half * 8;
                #pragma unroll
                for (int nt = 0; nt < 8; nt++)
                    #pragma unroll
                    for (int j = 0; j < 2; j++) {
                        int o = n0 + wn + nt * 8 + cb + j;
                        opf[((size_t)(b * CDIM + o)) * HWPIX + pp] =
                            acc[mt][nt][half * 2 + j] + biasptr[o];
                    }
            }
    }
}

// =================================================================
// PDSCA gate (rounds gated output to tf32)
// =================================================================
__device__ __forceinline__ void pdsca_gate(
        float* xs, float* scr, float* gap, float* hid, float* ca,
        const float* __restrict__ dw_w, const float* __restrict__ dw_b,
        const float* __restrict__ f1w,  const float* __restrict__ f1b,
        const float* __restrict__ f2w,  const float* __restrict__ f2b,
        int t) {
    for (int idx = t; idx < 2048; idx += 128) {
        int c = idx >> 6, s = idx & 63, sy = s >> 3, sx = s & 7;
        float sum = dw_b[c];
        #pragma unroll
        for (int ky = 0; ky < 3; ky++) {
            int iy = sy + ky - 1;
            if (iy < 0 || iy > 7) continue;
            #pragma unroll
            for (int kx = 0; kx < 3; kx++) {
                int ix = sx + kx - 1;
                if (ix < 0 || ix > 7) continue;
                int s2 = iy * 8 + ix;
                sum += dw_w[c * 9 + ky * 3 + kx] *
                       xs[(2 * c + (s2 >> 5)) * 36 + (s2 & 31)];
            }
        }
        scr[idx] = sum;
    }
    if (t < 32) {
        float s = 0.f;
        #pragma unroll
        for (int d = 0; d < 32; d++)
            s += xs[(2 * t) * 36 + d] + xs[(2 * t + 1) * 36 + d];
        gap[t] = s * (1.0f / 64.0f);
    }
    __syncthreads();
    if (t < 8) {
        float s = f1b[t];
        #pragma unroll
        for (int c = 0; c < 32; c++) s += gap[c] * f1w[t * 32 + c];
        hid[t] = fmaxf(s, 0.f);
    }
    __syncthreads();
    if (t < 32) {
        float s = f2b[t];
        #pragma unroll
        for (int j = 0; j < 8; j++) s += hid[j] * f2w[t * 8 + j];
        ca[t] = s;
    }
    __syncthreads();
    for (int idx = t; idx < 2048; idx += 128) {
        int c = idx >> 6, s = idx & 63;
        float m = scr[idx] + ca[c];
        float g = 1.0f / (1.0f + __expf(-m));
        int off = (2 * c + (s >> 5)) * 36 + (s & 31);
        xs[off] = rn_tf32(xs[off] * g);
    }
    __syncthreads();
}

// =================================================================
// per-(window, head) PDSCA + attention via tf32 mma; writes half g_aoh
// =================================================================
#define ATP 68
#define VP  68

__global__ void __launch_bounds__(128) attn_kernel(
        const float* __restrict__ log_temp,
        const float* __restrict__ pqw,  const float* __restrict__ pqb,
        const float* __restrict__ pqf1w, const float* __restrict__ pqf1b,
        const float* __restrict__ pqf2w, const float* __restrict__ pqf2b,
        const float* __restrict__ pkw,  const float* __restrict__ pkb,
        const float* __restrict__ pkf1w, const float* __restrict__ pkf1b,
        const float* __restrict__ pkf2w, const float* __restrict__ pkf2b) {
    __shared__ __align__(16) float qs[NTOK * 36];
    __shared__ __align__(16) float ks[NTOK * 36];
    __shared__ __align__(16) float vsT[HD * VP];
    __shared__ __align__(16) float at[NTOK * ATP];
    __shared__ float gap[32], hid[8], ca[32];

    int bi  = blockIdx.x;
    int win = bi / HEADS;
    int h   = bi - win * HEADS;
    int t   = threadIdx.x;
    int b   = win >> 8, hb = (win >> 4) & 15, wb = win & 15;
    int pbase = b * HWPIX + hb * 8 * WDIM + wb * 8;

    for (int tt = t; tt < 512; tt += 128) {
        int n = tt >> 3, d4 = (tt & 7) * 4;
        int p = pbase + (n >> 3) * WDIM + (n & 7);
        const __half* src = g_qkvh + (size_t)p * QKVC + h * HD + d4;
        __half2 q01 = *(const __half2*)(src);
        __half2 q23 = *(const __half2*)(src + 2);
        __half2 k01 = *(const __half2*)(src + CDIM);
        __half2 k23 = *(const __half2*)(src + CDIM + 2);
        __half2 v01 = *(const __half2*)(src + 2 * CDIM);
        __half2 v23 = *(const __half2*)(src + 2 * CDIM + 2);
        float2 qf0 = __half22float2(q01), qf1 = __half22float2(q23);
        float2 kf0 = __half22float2(k01), kf1 = __half22float2(k23);
        float2 vf0 = __half22float2(v01), vf1 = __half22float2(v23);
        *(float4*)&qs[n * 36 + d4] = make_float4(qf0.x, qf0.y, qf1.x, qf1.y);
        *(float4*)&ks[n * 36 + d4] = make_float4(kf0.x, kf0.y, kf1.x, kf1.y);
        vsT[(d4 + 0) * VP + n] = vf0.x;
        vsT[(d4 + 1) * VP + n] = vf0.y;
        vsT[(d4 + 2) * VP + n] = vf1.x;
        vsT[(d4 + 3) * VP + n] = vf1.y;
    }
    __syncthreads();

    pdsca_gate(qs, at, gap, hid, ca, pqw, pqb, pqf1w, pqf1b, pqf2w, pqf2b, t);
    pdsca_gate(ks, at, gap, hid, ca, pkw, pkb, pkf1w, pkf1b, pkf2w, pkf2b, t);

    int lane = t & 31, w = t >> 5;
    int r4 = lane >> 2, c4 = lane & 3;
    int m0 = w * 16;

    float sacc[8][4];
    #pragma unroll
    for (int nt = 0; nt < 8; nt++)
        #pragma unroll
        for (int j = 0; j < 4; j++) sacc[nt][j] = 0.f;

    #pragma unroll
    for (int kt = 0; kt < 4; kt++) {
        int kb = kt * 8;
        float a[4];
        a[0] = qs[(m0 + r4) * 36 + kb + c4];
        a[1] = qs[(m0 + r4 + 8) * 36 + kb + c4];
        a[2] = qs[(m0 + r4) * 36 + kb + 4 + c4];
        a[3] = qs[(m0 + r4 + 8) * 36 + kb + 4 + c4];
        #pragma unroll
        for (int nt = 0; nt < 8; nt++) {
            float bfr[2];
            bfr[0] = ks[(nt * 8 + r4) * 36 + kb + c4];
            bfr[1] = ks[(nt * 8 + r4) * 36 + kb + 4 + c4];
            mma8(sacc[nt], a, bfr);
        }
    }

    float temp = __expf(log_temp[0]);
    const float* brow = g_bias + h * 225;
    int r_lo = m0 + r4, r_hi = r_lo + 8;
    int ylo = r_lo >> 3, xlo = r_lo & 7;
    int yhi = r_hi >> 3, xhi = r_hi & 7;

    float mlo = -1e30f, mhi = -1e30f;
    #pragma unroll
    for (int nt = 0; nt < 8; nt++)
        #pragma unroll
        for (int j = 0; j < 2; j++) {
            int col = nt * 8 + 2 * c4 + j;
            int cy = col >> 3, cx = col & 7;
            float blo = brow[(ylo - cy + 7) * 15 + (xlo - cx + 7)];
            float bhi = brow[(yhi - cy + 7) * 15 + (xhi - cx + 7)];
            sacc[nt][j]     = sacc[nt][j] * temp + blo;
            sacc[nt][2 + j] = sacc[nt][2 + j] * temp + bhi;
            mlo = fmaxf(mlo, sacc[nt][j]);
            mhi = fmaxf(mhi, sacc[nt][2 + j]);
        }
    mlo = fmaxf(mlo, __shfl_xor_sync(0xffffffffu, mlo, 1));
    mlo = fmaxf(mlo, __shfl_xor_sync(0xffffffffu, mlo, 2));
    mhi = fmaxf(mhi, __shfl_xor_sync(0xffffffffu, mhi, 1));
    mhi = fmaxf(mhi, __shfl_xor_sync(0xffffffffu, mhi, 2));

    float slo = 0.f, shi = 0.f;
    #pragma unroll
    for (int nt = 0; nt < 8; nt++)
        #pragma unroll
        for (int j = 0; j < 2; j++) {
            float e0 = __expf(sacc[nt][j] - mlo);
            float e1 = __expf(sacc[nt][2 + j] - mhi);
            sacc[nt][j] = e0; sacc[nt][2 + j] = e1;
            slo += e0; shi += e1;
        }
    slo += __shfl_xor_sync(0xffffffffu, slo, 1);
    slo += __shfl_xor_sync(0xffffffffu, slo, 2);
    shi += __shfl_xor_sync(0xffffffffu, shi, 1);
    shi += __shfl_xor_sync(0xffffffffu, shi, 2);
    float ilo = 1.0f / slo, ihi = 1.0f / shi;

    #pragma unroll
    for (int nt = 0; nt < 8; nt++) {
        int col = nt * 8 + 2 * c4;
        float2 vlo, vhi;
        vlo.x = rn_tf32(sacc[nt][0] * ilo);
        vlo.y = rn_tf32(sacc[nt][1] * ilo);
        vhi.x = rn_tf32(sacc[nt][2] * ihi);
        vhi.y = rn_tf32(sacc[nt][3] * ihi);
        *(float2*)&at[r_lo * ATP + col] = vlo;
        *(float2*)&at[r_hi * ATP + col] = vhi;
    }
    __syncwarp();

    float oacc[4][4];
    #pragma unroll
    for (int nt = 0; nt < 4; nt++)
        #pragma unroll
        for (int j = 0; j < 4; j++) oacc[nt][j] = 0.f;

    #pragma unroll
    for (int k8 = 0; k8 < 8; k8++) {
        int kb = k8 * 8;
        float a[4];
        a[0] = at[(m0 + r4) * ATP + kb + c4];
        a[1] = at[(m0 + r4 + 8) * ATP + kb + c4];
        a[2] = at[(m0 + r4) * ATP + kb + 4 + c4];
        a[3] = at[(m0 + r4 + 8) * ATP + kb + 4 + c4];
        #pragma unroll
        for (int nt = 0; nt < 4; nt++) {
            float bfr[2];
            bfr[0] = vsT[(nt * 8 + r4) * VP + kb + c4];
            bfr[1] = vsT[(nt * 8 + r4) * VP + kb + 4 + c4];
            mma8(oacc[nt], a, bfr);
        }
    }

    #pragma unroll
    for (int half = 0; half < 2; half++) {
        int row = (half == 0) ? r_lo : r_hi;
        int p = pbase + (row >> 3) * WDIM + (row & 7);
        __half2* dst = (__half2*)(g_aoh + (size_t)p * CDIM + h * HD);
        #pragma unroll
        for (int nt = 0; nt < 4; nt++)
            dst[(nt * 8 + 2 * c4) >> 1] =
                __floats2half2_rn(oacc[nt][half * 2 + 0], oacc[nt][half * 2 + 1]);
    }
}

// =================================================================
// launch
// =================================================================
extern "C" void kernel_launch(void* const* d_in, const int* in_sizes, int n_in,
                              void* d_out, int out_size) {
    const float* x        = (const float*)d_in[0];
    const float* w_qk     = (const float*)d_in[1];
    const float* b_qk     = (const float*)d_in[2];
    const float* w_v      = (const float*)d_in[3];
    const float* b_v      = (const float*)d_in[4];
    const float* log_temp = (const float*)d_in[5];
    const float* pq_dw_w  = (const float*)d_in[6];
    const float* pq_dw_b  = (const float*)d_in[7];
    const float* pq_f1w   = (const float*)d_in[8];
    const float* pq_f1b   = (const float*)d_in[9];
    const float* pq_f2w   = (const float*)d_in[10];
    const float* pq_f2b   = (const float*)d_in[11];
    const float* pk_dw_w  = (const float*)d_in[12];
    const float* pk_dw_b  = (const float*)d_in[13];
    const float* pk_f1w   = (const float*)d_in[14];
    const float* pk_f1b   = (const float*)d_in[15];
    const float* pk_f2w   = (const float*)d_in[16];
    const float* pk_f2b   = (const float*)d_in[17];
    const float* pos_w    = (const float*)d_in[18];
    const float* pos_sc   = (const float*)d_in[20];
    const float* meta_w1  = (const float*)d_in[21];
    const float* meta_b1  = (const float*)d_in[22];
    const float* meta_w2  = (const float*)d_in[23];
    const float* meta_b2  = (const float*)d_in[24];
    const float* w_po     = (const float*)d_in[25];
    const float* w_proj   = (const float*)d_in[26];
    const float* b_proj   = (const float*)d_in[27];
    float* out = (float*)d_out;

    cudaFuncSetAttribute(gemm_mma<0>, cudaFuncAttributeMaxDynamicSharedMemorySize, GEMM_SMEM);
    cudaFuncSetAttribute(gemm_mma<1>, cudaFuncAttributeMaxDynamicSharedMemorySize, GEMM_SMEM);

    xpose_kernel<<<dim3(HWPIX / 32, CDIM / 32, BATCH), 256>>>(x);
    wprep_kernel<<<(QKVC * CDIM + 1023) / 1024, 1024>>>(w_qk, b_qk, w_v, b_v);
    wc_kernel<<<CDIM, CDIM>>>(w_proj, w_po);
    bias_kernel<<<225, 256>>>(pos_w, pos_sc, meta_w1, meta_b1, meta_w2, meta_b2);

    {
        const __half* A; cudaGetSymbolAddress((void**)&A, g_xTh);
        const __half* Bp; cudaGetSymbolAddress((void**)&Bp, g_wbh);
        const float* bb; cudaGetSymbolAddress((void**)&bb, g_bqkv);
        void* op; cudaGetSymbolAddress(&op, g_qkvh);
        gemm_mma<0><<<dim3(QKVC / 128, NPIX / 128), 256, GEMM_SMEM>>>(A, Bp, bb, op);
    }

    attn_kernel<<<NWIN * HEADS, 128>>>(log_temp,
        pq_dw_w, pq_dw_b, pq_f1w, pq_f1b, pq_f2w, pq_f2b,
        pk_dw_w, pk_dw_b, pk_f1w, pk_f1b, pk_f2w, pk_f2b);

    {
        const __half* A; cudaGetSymbolAddress((void**)&A, g_aoh);
        const __half* Bp; cudaGetSymbolAddress((void**)&Bp, g_Wch);
        gemm_mma<1><<<dim3(CDIM / 128, NPIX / 128), 256, GEMM_SMEM>>>(A, Bp, b_proj, (void*)out);
    }
}

// round 8
// speedup vs baseline: 4.6306x; 1.2695x over previous
#include <cuda_runtime.h>
#include <cuda_fp16.h>
#include <cstdint>
#include <math.h>

// ---------------- problem constants ----------------
#define BATCH 4
#define CDIM  384
#define HDIM  128
#define WDIM  128
#define HWPIX 16384
#define NPIX  65536
#define HEADS 12
#define HD    32
#define WS    8
#define NTOK  64
#define NWIN  1024
#define QKVC  1152

// ---------------- device scratch ----------------
__device__ __half g_qkvh[(size_t)NPIX * QKVC];  // per-pixel [q k v], half
__device__ __half g_aoh[(size_t)NPIX * CDIM];   // attn out, pixel-major, half
__device__ __half g_xTh[(size_t)NPIX * CDIM];   // x^T, half
__device__ __half g_wbh[QKVC * CDIM];           // [w_qk ; w_v], half
__device__ float  g_bqkv[QKVC];
__device__ float  g_bias[HEADS * 225];
__device__ __half g_Wch[CDIM * CDIM];           // w_proj @ w_po, half

// ---------------- helpers ----------------
__device__ __forceinline__ uint32_t smem_u32(const void* p) {
    uint32_t a;
    asm("{ .reg .u64 t; cvta.to.shared.u64 t, %1; cvt.u32.u64 %0, t; }" : "=r"(a) : "l"(p));
    return a;
}
__device__ __forceinline__ float rn_tf32(float v) {
    uint32_t u;
    asm("cvt.rna.tf32.f32 %0, %1;" : "=r"(u) : "f"(v));
    return __uint_as_float(u);
}
__device__ __forceinline__ void cp16(uint32_t saddr, const void* g) {
    asm volatile("cp.async.cg.shared.global [%0], [%1], 16;" :: "r"(saddr), "l"(g));
}
#define CP_COMMIT() asm volatile("cp.async.commit_group;" ::: "memory")
#define CP_WAIT0()  asm volatile("cp.async.wait_group 0;" ::: "memory")
#define CP_WAIT1()  asm volatile("cp.async.wait_group 1;" ::: "memory")

// fp16 m16n8k16 mma, fp32 accumulate
__device__ __forceinline__ void mma16(float* c, const uint32_t* a, const uint32_t* b) {
    asm volatile(
        "mma.sync.aligned.m16n8k16.row.col.f32.f16.f16.f32 "
        "{%0,%1,%2,%3}, {%4,%5,%6,%7}, {%8,%9}, {%0,%1,%2,%3};"
        : "+f"(c[0]), "+f"(c[1]), "+f"(c[2]), "+f"(c[3])
        : "r"(a[0]), "r"(a[1]), "r"(a[2]), "r"(a[3]),
          "r"(b[0]), "r"(b[1]));
}

// tf32 m16n8k8 mma (attention)
__device__ __forceinline__ void mma8(float* c, const float* a, const float* b) {
    asm volatile(
        "mma.sync.aligned.m16n8k8.row.col.f32.tf32.tf32.f32 "
        "{%0,%1,%2,%3}, {%4,%5,%6,%7}, {%8,%9}, {%0,%1,%2,%3};"
        : "+f"(c[0]), "+f"(c[1]), "+f"(c[2]), "+f"(c[3])
        : "r"(__float_as_uint(a[0])), "r"(__float_as_uint(a[1])),
          "r"(__float_as_uint(a[2])), "r"(__float_as_uint(a[3])),
          "r"(__float_as_uint(b[0])), "r"(__float_as_uint(b[1])));
}

// =================================================================
// transpose + fp16 convert: x (B,C,HW) -> g_xTh[p][c]
// =================================================================
__global__ void __launch_bounds__(256) xpose_kernel(const float* __restrict__ x) {
    __shared__ float t[32][33];
    int bx = blockIdx.x, by = blockIdx.y, bz = blockIdx.z;
    int tx = threadIdx.x & 31, ty = threadIdx.x >> 5;
    const float* src = x + ((size_t)(bz * CDIM + by * 32)) * HWPIX + bx * 32;
    #pragma unroll
    for (int i = 0; i < 32; i += 8)
        t[ty + i][tx] = src[(size_t)(ty + i) * HWPIX + tx];
    __syncthreads();
    __half* dst = g_xTh + ((size_t)(bz * HWPIX + bx * 32)) * CDIM + by * 32;
    #pragma unroll
    for (int i = 0; i < 32; i += 8)
        dst[(size_t)(ty + i) * CDIM + tx] = __float2half_rn(t[tx][ty + i]);
}

// =================================================================
// weight prep (fp16)
// =================================================================
__global__ void wprep_kernel(const float* __restrict__ w_qk, const float* __restrict__ b_qk,
                             const float* __restrict__ w_v,  const float* __restrict__ b_v) {
    int i = blockIdx.x * 1024 + threadIdx.x;
    if (i < QKVC * CDIM) {
        float v = (i < 2 * CDIM * CDIM) ? w_qk[i] : w_v[i - 2 * CDIM * CDIM];
        g_wbh[i] = __float2half_rn(v);
    }
    if (i < QKVC)
        g_bqkv[i] = (i < 2 * CDIM) ? b_qk[i] : b_v[i - 2 * CDIM];
}

__global__ void wc_kernel(const float* __restrict__ w_proj,
                          const float* __restrict__ w_po) {
    int o = blockIdx.x;
    int c = threadIdx.x;
    const float* pr = w_proj + o * CDIM;
    float a0 = 0.f, a1 = 0.f, a2 = 0.f, a3 = 0.f;
    for (int t = 0; t < CDIM; t += 4) {
        a0 += pr[t] * w_po[t * CDIM + c];
        a1 += pr[t + 1] * w_po[(t + 1) * CDIM + c];
        a2 += pr[t + 2] * w_po[(t + 2) * CDIM + c];
        a3 += pr[t + 3] * w_po[(t + 3) * CDIM + c];
    }
    g_Wch[o * CDIM + c] = __float2half_rn((a0 + a1) + (a2 + a3));
}

// =================================================================
// relative-position bias (225 deltas) — split-dot, 256 threads
// =================================================================
__global__ void __launch_bounds__(256) bias_kernel(
        const float* __restrict__ pcw,
        const float* __restrict__ psc,
        const float* __restrict__ mw1,
        const float* __restrict__ mb1,
        const float* __restrict__ mw2,
        const float* __restrict__ mb2) {
    __shared__ __align__(16) float rel[CDIM];
    __shared__ __align__(16) float hid[128];
    __shared__ float part[256];
    int idx = blockIdx.x;
    float dx = (float)((idx % 15) - 7) * (2.0f / 7.0f);
    float dy = (float)((idx / 15) - 7) * (2.0f / 7.0f);
    int t = threadIdx.x;
    int u = t & 127, hv2 = t >> 7;
    float sc = psc[0];
    for (int c = t; c < CDIM; c += 256)
        rel[c] = sc * (pcw[2 * c] * dx + pcw[2 * c + 1] * dy);
    __syncthreads();
    {
        float a0 = 0.f, a1 = 0.f, a2 = 0.f, a3 = 0.f;
        const float4* w = (const float4*)(mw1 + u * CDIM + hv2 * 192);
        const float4* r = (const float4*)(rel + hv2 * 192);
        #pragma unroll 4
        for (int c = 0; c < 48; c++) {
            float4 wv = w[c], rv = r[c];
            a0 += wv.x * rv.x; a1 += wv.y * rv.y;
            a2 += wv.z * rv.z; a3 += wv.w * rv.w;
        }
        part[t] = (a0 + a1) + (a2 + a3);
    }
    __syncthreads();
    if (t < 128) {
        float s = mb1[t] + part[t] + part[t + 128];
        hid[t] = 0.5f * s * (1.0f + erff(s * 0.70710678118654752f));
    }
    __syncthreads();
    if (t < HEADS) {
        float a0 = 0.f, a1 = 0.f, a2 = 0.f, a3 = 0.f;
        const float4* w2 = (const float4*)(mw2 + t * 128);
        const float4* hh = (const float4*)hid;
        #pragma unroll 4
        for (int j = 0; j < 32; j++) {
            float4 wv = w2[j], hvv = hh[j];
            a0 += wv.x * hvv.x; a1 += wv.y * hvv.y;
            a2 += wv.z * hvv.z; a3 += wv.w * hvv.w;
        }
        g_bias[t * 225 + idx] = mb2[t] + (a0 + a1) + (a2 + a3);
    }
}

// =================================================================
// fp16 mma.sync GEMM (unchanged from round 7)
// =================================================================
#define HP   72
#define KCH  64
#define NCH  6
#define GEMM_SMEM (4 * 128 * HP * 2)

template <int MODE>
__global__ void __launch_bounds__(256) gemm_mma(
        const __half* __restrict__ Aptr, const __half* __restrict__ Bptr,
        const float* __restrict__ biasptr, void* __restrict__ outp) {
    extern __shared__ __align__(16) __half smh[];
    __half* AsB[2] = { smh, smh + 128 * HP };
    __half* BsB[2] = { smh + 2 * 128 * HP, smh + 3 * 128 * HP };

    int tid = threadIdx.x;
    int n0 = blockIdx.x * 128;
    int m0 = blockIdx.y * 128;
    int lane = tid & 31, wid = tid >> 5;
    int wm = (wid & 3) * 32;
    int wn = (wid >> 2) * 64;

    const __half* Arow = Aptr + (size_t)m0 * CDIM;
    const __half* Brow = Bptr + (size_t)n0 * CDIM;
    uint32_t aU[2] = { smem_u32(AsB[0]), smem_u32(AsB[1]) };
    uint32_t bU[2] = { smem_u32(BsB[0]), smem_u32(BsB[1]) };

    int ldrow = tid >> 3, ldseg = tid & 7;
    auto load_chunk = [&](int k0, int buf) {
        #pragma unroll
        for (int i = 0; i < 4; i++) {
            int row = ldrow + i * 32;
            uint32_t so = (uint32_t)(row * HP + ldseg * 8) * 2;
            cp16(aU[buf] + so, Arow + (size_t)row * CDIM + k0 + ldseg * 8);
            cp16(bU[buf] + so, Brow + (size_t)row * CDIM + k0 + ldseg * 8);
        }
        CP_COMMIT();
    };

    float acc[2][8][4];
    #pragma unroll
    for (int mt = 0; mt < 2; mt++)
        #pragma unroll
        for (int nt = 0; nt < 8; nt++)
            #pragma unroll
            for (int j = 0; j < 4; j++) acc[mt][nt][j] = 0.f;

    load_chunk(0, 0);

    int r4 = lane >> 2, c4 = lane & 3;
    for (int i = 0; i < NCH; i++) {
        if (i + 1 < NCH) { load_chunk((i + 1) * KCH, (i + 1) & 1); CP_WAIT1(); }
        else             { CP_WAIT0(); }
        __syncthreads();
        const __half* Ab = AsB[i & 1];
        const __half* Bb = BsB[i & 1];
        #pragma unroll
        for (int kk = 0; kk < 4; kk++) {
            int kb = kk * 16;
            uint32_t a[2][4];
            #pragma unroll
            for (int mt = 0; mt < 2; mt++) {
                int row = wm + mt * 16 + r4;
                a[mt][0] = *(const uint32_t*)&Ab[row * HP + kb + 2 * c4];
                a[mt][1] = *(const uint32_t*)&Ab[(row + 8) * HP + kb + 2 * c4];
                a[mt][2] = *(const uint32_t*)&Ab[row * HP + kb + 2 * c4 + 8];
                a[mt][3] = *(const uint32_t*)&Ab[(row + 8) * HP + kb + 2 * c4 + 8];
            }
            uint32_t b[8][2];
            #pragma unroll
            for (int nt = 0; nt < 8; nt++) {
                int nrow = wn + nt * 8 + r4;
                b[nt][0] = *(const uint32_t*)&Bb[nrow * HP + kb + 2 * c4];
                b[nt][1] = *(const uint32_t*)&Bb[nrow * HP + kb + 2 * c4 + 8];
            }
            #pragma unroll
            for (int mt = 0; mt < 2; mt++)
                #pragma unroll
                for (int nt = 0; nt < 8; nt++)
                    mma16(acc[mt][nt], a[mt], b[nt]);
        }
        __syncthreads();
    }

    int cb = c4 * 2;
    if (MODE == 0) {
        __half* oph = (__half*)outp;
        #pragma unroll
        for (int mt = 0; mt < 2; mt++)
            #pragma unroll
            for (int half = 0; half < 2; half++) {
                int m = m0 + wm + mt * 16 + r4 + half * 8;
                __half* dst = oph + (size_t)m * QKVC + n0 + wn;
                #pragma unroll
                for (int nt = 0; nt < 8; nt++) {
                    int o = n0 + wn + nt * 8 + cb;
                    *(__half2*)(dst + nt * 8 + cb) = __floats2half2_rn(
                        acc[mt][nt][half * 2 + 0] + biasptr[o],
                        acc[mt][nt][half * 2 + 1] + biasptr[o + 1]);
                }
            }
    } else {
        float* opf = (float*)outp;
        int b = m0 >> 14;
        int ppb = m0 & (HWPIX - 1);
        #pragma unroll
        for (int mt = 0; mt < 2; mt++)
            #pragma unroll
            for (int half = 0; half < 2; half++) {
                int pp = ppb + wm + mt * 16 + r4 + half * 8;
                #pragma unroll
                for (int nt = 0; nt < 8; nt++)
                    #pragma unroll
                    for (int j = 0; j < 2; j++) {
                        int o = n0 + wn + nt * 8 + cb + j;
                        opf[((size_t)(b * CDIM + o)) * HWPIX + pp] =
                            acc[mt][nt][half * 2 + j] + biasptr[o];
                    }
            }
    }
}

// =================================================================
// PDSCA gate — row-register conv, conv outputs live in registers.
// work item = (channel c, image row sy): 256 items, 2 per thread.
// token layout: element (c, s) at xs[(2c + (s>>5))*36 + (s&31)];
// row sy = 8 contiguous floats at (2c + (sy>>2))*36 + (sy&3)*8.
// =================================================================
__device__ __forceinline__ void pdsca_gate(
        float* xs, float* gap, float* hid, float* ca,
        const float* __restrict__ dw_w, const float* __restrict__ dw_b,
        const float* __restrict__ f1w,  const float* __restrict__ f1b,
        const float* __restrict__ f2w,  const float* __restrict__ f2b,
        int t) {
    float oc[2][8];
    // ---- depthwise 3x3 on row registers ----
    #pragma unroll
    for (int hh = 0; hh < 2; hh++) {
        int it = t + hh * 128;
        int c = it >> 3, sy = it & 7;
        float rm[10], rc[10], rp[10];
        #pragma unroll
        for (int i = 0; i < 10; i++) { rm[i] = 0.f; rc[i] = 0.f; rp[i] = 0.f; }
        {
            const float* base = xs + (2 * c + (sy >> 2)) * 36 + (sy & 3) * 8;
            float4 v0 = *(const float4*)base, v1 = *(const float4*)(base + 4);
            rc[1] = v0.x; rc[2] = v0.y; rc[3] = v0.z; rc[4] = v0.w;
            rc[5] = v1.x; rc[6] = v1.y; rc[7] = v1.z; rc[8] = v1.w;
        }
        if (sy > 0) {
            int r = sy - 1;
            const float* base = xs + (2 * c + (r >> 2)) * 36 + (r & 3) * 8;
            float4 v0 = *(const float4*)base, v1 = *(const float4*)(base + 4);
            rm[1] = v0.x; rm[2] = v0.y; rm[3] = v0.z; rm[4] = v0.w;
            rm[5] = v1.x; rm[6] = v1.y; rm[7] = v1.z; rm[8] = v1.w;
        }
        if (sy < 7) {
            int r = sy + 1;
            const float* base = xs + (2 * c + (r >> 2)) * 36 + (r & 3) * 8;
            float4 v0 = *(const float4*)base, v1 = *(const float4*)(base + 4);
            rp[1] = v0.x; rp[2] = v0.y; rp[3] = v0.z; rp[4] = v0.w;
            rp[5] = v1.x; rp[6] = v1.y; rp[7] = v1.z; rp[8] = v1.w;
        }
        const float* wp = dw_w + c * 9;
        float w0 = wp[0], w1 = wp[1], w2 = wp[2];
        float w3 = wp[3], w4 = wp[4], w5 = wp[5];
        float w6 = wp[6], w7 = wp[7], w8 = wp[8];
        float bias = dw_b[c];
        #pragma unroll
        for (int ix = 0; ix < 8; ix++) {
            float s = bias;
            s += w0 * rm[ix] + w1 * rm[ix + 1] + w2 * rm[ix + 2];
            s += w3 * rc[ix] + w4 * rc[ix + 1] + w5 * rc[ix + 2];
            s += w6 * rp[ix] + w7 * rp[ix + 1] + w8 * rp[ix + 2];
            oc[hh][ix] = s;
        }
    }
    // ---- GAP (reads xs, pre-sync) ----
    if (t < 32) {
        const float4* p0 = (const float4*)(xs + (2 * t) * 36);
        const float4* p1 = (const float4*)(xs + (2 * t + 1) * 36);
        float4 s4 = make_float4(0.f, 0.f, 0.f, 0.f);
        #pragma unroll
        for (int i = 0; i < 8; i++) {
            float4 a = p0[i], b = p1[i];
            s4.x += a.x + b.x; s4.y += a.y + b.y;
            s4.z += a.z + b.z; s4.w += a.w + b.w;
        }
        gap[t] = (s4.x + s4.y + s4.z + s4.w) * (1.0f / 64.0f);
    }
    __syncthreads();
    if (t < 8) {
        float s = f1b[t];
        #pragma unroll
        for (int c = 0; c < 32; c++) s += gap[c] * f1w[t * 32 + c];
        hid[t] = fmaxf(s, 0.f);
    }
    __syncthreads();
    if (t < 32) {
        float s = f2b[t];
        #pragma unroll
        for (int j = 0; j < 8; j++) s += hid[j] * f2w[t * 8 + j];
        ca[t] = s;
    }
    __syncthreads();
    // ---- gate apply (all conv reads done before syncs above) ----
    #pragma unroll
    for (int hh = 0; hh < 2; hh++) {
        int it = t + hh * 128;
        int c = it >> 3, sy = it & 7;
        float cav = ca[c];
        float* base = xs + (2 * c + (sy >> 2)) * 36 + (sy & 3) * 8;
        float4 x0 = *(float4*)base, x1 = *(float4*)(base + 4);
        x0.x = rn_tf32(x0.x / (1.0f + __expf(-(oc[hh][0] + cav))));
        x0.y = rn_tf32(x0.y / (1.0f + __expf(-(oc[hh][1] + cav))));
        x0.z = rn_tf32(x0.z / (1.0f + __expf(-(oc[hh][2] + cav))));
        x0.w = rn_tf32(x0.w / (1.0f + __expf(-(oc[hh][3] + cav))));
        x1.x = rn_tf32(x1.x / (1.0f + __expf(-(oc[hh][4] + cav))));
        x1.y = rn_tf32(x1.y / (1.0f + __expf(-(oc[hh][5] + cav))));
        x1.z = rn_tf32(x1.z / (1.0f + __expf(-(oc[hh][6] + cav))));
        x1.w = rn_tf32(x1.w / (1.0f + __expf(-(oc[hh][7] + cav))));
        *(float4*)base = x0;
        *(float4*)(base + 4) = x1;
    }
    __syncthreads();
}

// =================================================================
// per-(window, head) PDSCA + attention via tf32 mma; writes half g_aoh
// =================================================================
#define ATP 68
#define VP  68

__global__ void __launch_bounds__(128) attn_kernel(
        const float* __restrict__ log_temp,
        const float* __restrict__ pqw,  const float* __restrict__ pqb,
        const float* __restrict__ pqf1w, const float* __restrict__ pqf1b,
        const float* __restrict__ pqf2w, const float* __restrict__ pqf2b,
        const float* __restrict__ pkw,  const float* __restrict__ pkb,
        const float* __restrict__ pkf1w, const float* __restrict__ pkf1b,
        const float* __restrict__ pkf2w, const float* __restrict__ pkf2b) {
    __shared__ __align__(16) float qs[NTOK * 36];
    __shared__ __align__(16) float ks[NTOK * 36];
    __shared__ __align__(16) float vsT[HD * VP];
    __shared__ __align__(16) float at[NTOK * ATP];
    __shared__ float gap[32], hid[8], ca[32];

    int bi  = blockIdx.x;
    int win = bi / HEADS;
    int h   = bi - win * HEADS;
    int t   = threadIdx.x;
    int b   = win >> 8, hb = (win >> 4) & 15, wb = win & 15;
    int pbase = b * HWPIX + hb * 8 * WDIM + wb * 8;

    // ---- vectorized load: int4 = 8 halves per access ----
    for (int tt = t; tt < 256; tt += 128) {
        int n = tt >> 2, d8 = (tt & 3) * 8;
        int p = pbase + (n >> 3) * WDIM + (n & 7);
        const __half* src = g_qkvh + (size_t)p * QKVC + h * HD + d8;
        union { int4 i; __half2 h[4]; } uq, uk, uv;
        uq.i = *(const int4*)(src);
        uk.i = *(const int4*)(src + CDIM);
        uv.i = *(const int4*)(src + 2 * CDIM);
        float2 q0 = __half22float2(uq.h[0]), q1 = __half22float2(uq.h[1]);
        float2 q2 = __half22float2(uq.h[2]), q3 = __half22float2(uq.h[3]);
        float2 k0 = __half22float2(uk.h[0]), k1 = __half22float2(uk.h[1]);
        float2 k2 = __half22float2(uk.h[2]), k3 = __half22float2(uk.h[3]);
        float2 v0 = __half22float2(uv.h[0]), v1 = __half22float2(uv.h[1]);
        float2 v2 = __half22float2(uv.h[2]), v3 = __half22float2(uv.h[3]);
        *(float4*)&qs[n * 36 + d8]     = make_float4(q0.x, q0.y, q1.x, q1.y);
        *(float4*)&qs[n * 36 + d8 + 4] = make_float4(q2.x, q2.y, q3.x, q3.y);
        *(float4*)&ks[n * 36 + d8]     = make_float4(k0.x, k0.y, k1.x, k1.y);
        *(float4*)&ks[n * 36 + d8 + 4] = make_float4(k2.x, k2.y, k3.x, k3.y);
        vsT[(d8 + 0) * VP + n] = v0.x;
        vsT[(d8 + 1) * VP + n] = v0.y;
        vsT[(d8 + 2) * VP + n] = v1.x;
        vsT[(d8 + 3) * VP + n] = v1.y;
        vsT[(d8 + 4) * VP + n] = v2.x;
        vsT[(d8 + 5) * VP + n] = v2.y;
        vsT[(d8 + 6) * VP + n] = v3.x;
        vsT[(d8 + 7) * VP + n] = v3.y;
    }
    __syncthreads();

    pdsca_gate(qs, gap, hid, ca, pqw, pqb, pqf1w, pqf1b, pqf2w, pqf2b, t);
    pdsca_gate(ks, gap, hid, ca, pkw, pkb, pkf1w, pkf1b, pkf2w, pkf2b, t);

    int lane = t & 31, w = t >> 5;
    int r4 = lane >> 2, c4 = lane & 3;
    int m0 = w * 16;

    float sacc[8][4];
    #pragma unroll
    for (int nt = 0; nt < 8; nt++)
        #pragma unroll
        for (int j = 0; j < 4; j++) sacc[nt][j] = 0.f;

    #pragma unroll
    for (int kt = 0; kt < 4; kt++) {
        int kb = kt * 8;
        float a[4];
        a[0] = qs[(m0 + r4) * 36 + kb + c4];
        a[1] = qs[(m0 + r4 + 8) * 36 + kb + c4];
        a[2] = qs[(m0 + r4) * 36 + kb + 4 + c4];
        a[3] = qs[(m0 + r4 + 8) * 36 + kb + 4 + c4];
        #pragma unroll
        for (int nt = 0; nt < 8; nt++) {
            float bfr[2];
            bfr[0] = ks[(nt * 8 + r4) * 36 + kb + c4];
            bfr[1] = ks[(nt * 8 + r4) * 36 + kb + 4 + c4];
            mma8(sacc[nt], a, bfr);
        }
    }

    float temp = __expf(log_temp[0]);
    const float* brow = g_bias + h * 225;
    int r_lo = m0 + r4, r_hi = r_lo + 8;
    int ylo = r_lo >> 3, xlo = r_lo & 7;
    int yhi = r_hi >> 3, xhi = r_hi & 7;

    float mlo = -1e30f, mhi = -1e30f;
    #pragma unroll
    for (int nt = 0; nt < 8; nt++)
        #pragma unroll
        for (int j = 0; j < 2; j++) {
            int col = nt * 8 + 2 * c4 + j;
            int cy = col >> 3, cx = col & 7;
            float blo = brow[(ylo - cy + 7) * 15 + (xlo - cx + 7)];
            float bhi = brow[(yhi - cy + 7) * 15 + (xhi - cx + 7)];
            sacc[nt][j]     = sacc[nt][j] * temp + blo;
            sacc[nt][2 + j] = sacc[nt][2 + j] * temp + bhi;
            mlo = fmaxf(mlo, sacc[nt][j]);
            mhi = fmaxf(mhi, sacc[nt][2 + j]);
        }
    mlo = fmaxf(mlo, __shfl_xor_sync(0xffffffffu, mlo, 1));
    mlo = fmaxf(mlo, __shfl_xor_sync(0xffffffffu, mlo, 2));
    mhi = fmaxf(mhi, __shfl_xor_sync(0xffffffffu, mhi, 1));
    mhi = fmaxf(mhi, __shfl_xor_sync(0xffffffffu, mhi, 2));

    float slo = 0.f, shi = 0.f;
    #pragma unroll
    for (int nt = 0; nt < 8; nt++)
        #pragma unroll
        for (int j = 0; j < 2; j++) {
            float e0 = __expf(sacc[nt][j] - mlo);
            float e1 = __expf(sacc[nt][2 + j] - mhi);
            sacc[nt][j] = e0; sacc[nt][2 + j] = e1;
            slo += e0; shi += e1;
        }
    slo += __shfl_xor_sync(0xffffffffu, slo, 1);
    slo += __shfl_xor_sync(0xffffffffu, slo, 2);
    shi += __shfl_xor_sync(0xffffffffu, shi, 1);
    shi += __shfl_xor_sync(0xffffffffu, shi, 2);
    float ilo = 1.0f / slo, ihi = 1.0f / shi;

    #pragma unroll
    for (int nt = 0; nt < 8; nt++) {
        int col = nt * 8 + 2 * c4;
        float2 vlo, vhi;
        vlo.x = rn_tf32(sacc[nt][0] * ilo);
        vlo.y = rn_tf32(sacc[nt][1] * ilo);
        vhi.x = rn_tf32(sacc[nt][2] * ihi);
        vhi.y = rn_tf32(sacc[nt][3] * ihi);
        *(float2*)&at[r_lo * ATP + col] = vlo;
        *(float2*)&at[r_hi * ATP + col] = vhi;
    }
    __syncwarp();

    float oacc[4][4];
    #pragma unroll
    for (int nt = 0; nt < 4; nt++)
        #pragma unroll
        for (int j = 0; j < 4; j++) oacc[nt][j] = 0.f;

    #pragma unroll
    for (int k8 = 0; k8 < 8; k8++) {
        int kb = k8 * 8;
        float a[4];
        a[0] = at[(m0 + r4) * ATP + kb + c4];
        a[1] = at[(m0 + r4 + 8) * ATP + kb + c4];
        a[2] = at[(m0 + r4) * ATP + kb + 4 + c4];
        a[3] = at[(m0 + r4 + 8) * ATP + kb + 4 + c4];
        #pragma unroll
        for (int nt = 0; nt < 4; nt++) {
            float bfr[2];
            bfr[0] = vsT[(nt * 8 + r4) * VP + kb + c4];
            bfr[1] = vsT[(nt * 8 + r4) * VP + kb + 4 + c4];
            mma8(oacc[nt], a, bfr);
        }
    }

    #pragma unroll
    for (int half = 0; half < 2; half++) {
        int row = (half == 0) ? r_lo : r_hi;
        int p = pbase + (row >> 3) * WDIM + (row & 7);
        __half2* dst = (__half2*)(g_aoh + (size_t)p * CDIM + h * HD);
        #pragma unroll
        for (int nt = 0; nt < 4; nt++)
            dst[(nt * 8 + 2 * c4) >> 1] =
                __floats2half2_rn(oacc[nt][half * 2 + 0], oacc[nt][half * 2 + 1]);
    }
}

// =================================================================
// launch
// =================================================================
extern "C" void kernel_launch(void* const* d_in, const int* in_sizes, int n_in,
                              void* d_out, int out_size) {
    const float* x        = (const float*)d_in[0];
    const float* w_qk     = (const float*)d_in[1];
    const float* b_qk     = (const float*)d_in[2];
    const float* w_v      = (const float*)d_in[3];
    const float* b_v      = (const float*)d_in[4];
    const float* log_temp = (const float*)d_in[5];
    const float* pq_dw_w  = (const float*)d_in[6];
    const float* pq_dw_b  = (const float*)d_in[7];
    const float* pq_f1w   = (const float*)d_in[8];
    const float* pq_f1b   = (const float*)d_in[9];
    const float* pq_f2w   = (const float*)d_in[10];
    const float* pq_f2b   = (const float*)d_in[11];
    const float* pk_dw_w  = (const float*)d_in[12];
    const float* pk_dw_b  = (const float*)d_in[13];
    const float* pk_f1w   = (const float*)d_in[14];
    const float* pk_f1b   = (const float*)d_in[15];
    const float* pk_f2w   = (const float*)d_in[16];
    const float* pk_f2b   = (const float*)d_in[17];
    const float* pos_w    = (const float*)d_in[18];
    const float* pos_sc   = (const float*)d_in[20];
    const float* meta_w1  = (const float*)d_in[21];
    const float* meta_b1  = (const float*)d_in[22];
    const float* meta_w2  = (const float*)d_in[23];
    const float* meta_b2  = (const float*)d_in[24];
    const float* w_po     = (const float*)d_in[25];
    const float* w_proj   = (const float*)d_in[26];
    const float* b_proj   = (const float*)d_in[27];
    float* out = (float*)d_out;

    cudaFuncSetAttribute(gemm_mma<0>, cudaFuncAttributeMaxDynamicSharedMemorySize, GEMM_SMEM);
    cudaFuncSetAttribute(gemm_mma<1>, cudaFuncAttributeMaxDynamicSharedMemorySize, GEMM_SMEM);

    xpose_kernel<<<dim3(HWPIX / 32, CDIM / 32, BATCH), 256>>>(x);
    wprep_kernel<<<(QKVC * CDIM + 1023) / 1024, 1024>>>(w_qk, b_qk, w_v, b_v);
    wc_kernel<<<CDIM, CDIM>>>(w_proj, w_po);
    bias_kernel<<<225, 256>>>(pos_w, pos_sc, meta_w1, meta_b1, meta_w2, meta_b2);

    {
        const __half* A; cudaGetSymbolAddress((void**)&A, g_xTh);
        const __half* Bp; cudaGetSymbolAddress((void**)&Bp, g_wbh);
        const float* bb; cudaGetSymbolAddress((void**)&bb, g_bqkv);
        void* op; cudaGetSymbolAddress(&op, g_qkvh);
        gemm_mma<0><<<dim3(QKVC / 128, NPIX / 128), 256, GEMM_SMEM>>>(A, Bp, bb, op);
    }

    attn_kernel<<<NWIN * HEADS, 128>>>(log_temp,
        pq_dw_w, pq_dw_b, pq_f1w, pq_f1b, pq_f2w, pq_f2b,
        pk_dw_w, pk_dw_b, pk_f1w, pk_f1b, pk_f2w, pk_f2b);

    {
        const __half* A; cudaGetSymbolAddress((void**)&A, g_aoh);
        const __half* Bp; cudaGetSymbolAddress((void**)&Bp, g_Wch);
        gemm_mma<1><<<dim3(CDIM / 128, NPIX / 128), 256, GEMM_SMEM>>>(A, Bp, b_proj, (void*)out);
    }
}

// round 9
// speedup vs baseline: 4.7342x; 1.0224x over previous
#include <cuda_runtime.h>
#include <cuda_fp16.h>
#include <cstdint>
#include <math.h>

// ---------------- problem constants ----------------
#define BATCH 4
#define CDIM  384
#define HDIM  128
#define WDIM  128
#define HWPIX 16384
#define NPIX  65536
#define HEADS 12
#define HD    32
#define WS    8
#define NTOK  64
#define NWIN  1024
#define QKVC  1152

// ---------------- device scratch ----------------
__device__ __half g_qkvh[(size_t)NPIX * QKVC];
__device__ __half g_aoh[(size_t)NPIX * CDIM];
__device__ __half g_xTh[(size_t)NPIX * CDIM];
__device__ __half g_wbh[QKVC * CDIM];
__device__ float  g_bqkv[QKVC];
__device__ float  g_bias[HEADS * 225];
__device__ __half g_Wch[CDIM * CDIM];

// ---------------- helpers ----------------
__device__ __forceinline__ uint32_t smem_u32(const void* p) {
    uint32_t a;
    asm("{ .reg .u64 t; cvta.to.shared.u64 t, %1; cvt.u32.u64 %0, t; }" : "=r"(a) : "l"(p));
    return a;
}
__device__ __forceinline__ float rn_tf32(float v) {
    uint32_t u;
    asm("cvt.rna.tf32.f32 %0, %1;" : "=r"(u) : "f"(v));
    return __uint_as_float(u);
}
__device__ __forceinline__ void cp16(uint32_t saddr, const void* g) {
    asm volatile("cp.async.cg.shared.global [%0], [%1], 16;" :: "r"(saddr), "l"(g));
}
#define CP_COMMIT() asm volatile("cp.async.commit_group;" ::: "memory")
#define CP_WAIT0()  asm volatile("cp.async.wait_group 0;" ::: "memory")
#define CP_WAIT1()  asm volatile("cp.async.wait_group 1;" ::: "memory")

__device__ __forceinline__ void mma16(float* c, const uint32_t* a, const uint32_t* b) {
    asm volatile(
        "mma.sync.aligned.m16n8k16.row.col.f32.f16.f16.f32 "
        "{%0,%1,%2,%3}, {%4,%5,%6,%7}, {%8,%9}, {%0,%1,%2,%3};"
        : "+f"(c[0]), "+f"(c[1]), "+f"(c[2]), "+f"(c[3])
        : "r"(a[0]), "r"(a[1]), "r"(a[2]), "r"(a[3]),
          "r"(b[0]), "r"(b[1]));
}

__device__ __forceinline__ void mma8(float* c, const float* a, const float* b) {
    asm volatile(
        "mma.sync.aligned.m16n8k8.row.col.f32.tf32.tf32.f32 "
        "{%0,%1,%2,%3}, {%4,%5,%6,%7}, {%8,%9}, {%0,%1,%2,%3};"
        : "+f"(c[0]), "+f"(c[1]), "+f"(c[2]), "+f"(c[3])
        : "r"(__float_as_uint(a[0])), "r"(__float_as_uint(a[1])),
          "r"(__float_as_uint(a[2])), "r"(__float_as_uint(a[3])),
          "r"(__float_as_uint(b[0])), "r"(__float_as_uint(b[1])));
}

// =================================================================
// unified prep kernel: xpose | wprep | wc | bias, 256 threads
// =================================================================
#define NB_XPOSE (512 * 12 * 4)                  // 24576
#define NB_WPREP ((QKVC * CDIM) / 256)           // 1728
#define NB_WC    ((CDIM * CDIM) / 256)           // 576
#define NB_BIAS  225
#define NB_PREP  (NB_XPOSE + NB_WPREP + NB_WC + NB_BIAS)

__global__ void __launch_bounds__(256) prep_kernel(
        const float* __restrict__ x,
        const float* __restrict__ w_qk, const float* __restrict__ b_qk,
        const float* __restrict__ w_v,  const float* __restrict__ b_v,
        const float* __restrict__ w_proj, const float* __restrict__ w_po,
        const float* __restrict__ pcw, const float* __restrict__ psc,
        const float* __restrict__ mw1, const float* __restrict__ mb1,
        const float* __restrict__ mw2, const float* __restrict__ mb2) {
    __shared__ __align__(16) float tile[32][33];
    __shared__ __align__(16) float rel[CDIM];
    __shared__ __align__(16) float hid[128];
    __shared__ float part[256];
    int blk = blockIdx.x;
    int t = threadIdx.x;

    if (blk < NB_XPOSE) {
        // -------- transpose + fp16 --------
        int bx = blk & 511, by = (blk >> 9) % 12, bz = blk / (512 * 12);
        int tx = t & 31, ty = t >> 5;
        const float* src = x + ((size_t)(bz * CDIM + by * 32)) * HWPIX + bx * 32;
        #pragma unroll
        for (int i = 0; i < 32; i += 8)
            tile[ty + i][tx] = src[(size_t)(ty + i) * HWPIX + tx];
        __syncthreads();
        __half* dst = g_xTh + ((size_t)(bz * HWPIX + bx * 32)) * CDIM + by * 32;
        #pragma unroll
        for (int i = 0; i < 32; i += 8)
            dst[(size_t)(ty + i) * CDIM + tx] = __float2half_rn(tile[tx][ty + i]);
        return;
    }
    blk -= NB_XPOSE;
    if (blk < NB_WPREP) {
        int i = blk * 256 + t;
        float v = (i < 2 * CDIM * CDIM) ? w_qk[i] : w_v[i - 2 * CDIM * CDIM];
        g_wbh[i] = __float2half_rn(v);
        if (i < QKVC)
            g_bqkv[i] = (i < 2 * CDIM) ? b_qk[i] : b_v[i - 2 * CDIM];
        return;
    }
    blk -= NB_WPREP;
    if (blk < NB_WC) {
        int idx = blk * 256 + t;
        int o = idx / CDIM, c = idx - o * CDIM;
        const float* pr = w_proj + o * CDIM;
        float a0 = 0.f, a1 = 0.f, a2 = 0.f, a3 = 0.f;
        for (int k = 0; k < CDIM; k += 4) {
            a0 += pr[k] * w_po[k * CDIM + c];
            a1 += pr[k + 1] * w_po[(k + 1) * CDIM + c];
            a2 += pr[k + 2] * w_po[(k + 2) * CDIM + c];
            a3 += pr[k + 3] * w_po[(k + 3) * CDIM + c];
        }
        g_Wch[o * CDIM + c] = __float2half_rn((a0 + a1) + (a2 + a3));
        return;
    }
    blk -= NB_WC;
    {
        // -------- position bias --------
        int idx = blk;
        float dx = (float)((idx % 15) - 7) * (2.0f / 7.0f);
        float dy = (float)((idx / 15) - 7) * (2.0f / 7.0f);
        int u = t & 127, hv2 = t >> 7;
        float sc = psc[0];
        for (int c = t; c < CDIM; c += 256)
            rel[c] = sc * (pcw[2 * c] * dx + pcw[2 * c + 1] * dy);
        __syncthreads();
        {
            float a0 = 0.f, a1 = 0.f, a2 = 0.f, a3 = 0.f;
            const float4* w = (const float4*)(mw1 + u * CDIM + hv2 * 192);
            const float4* r = (const float4*)(rel + hv2 * 192);
            #pragma unroll 4
            for (int c = 0; c < 48; c++) {
                float4 wv = w[c], rv = r[c];
                a0 += wv.x * rv.x; a1 += wv.y * rv.y;
                a2 += wv.z * rv.z; a3 += wv.w * rv.w;
            }
            part[t] = (a0 + a1) + (a2 + a3);
        }
        __syncthreads();
        if (t < 128) {
            float s = mb1[t] + part[t] + part[t + 128];
            hid[t] = 0.5f * s * (1.0f + erff(s * 0.70710678118654752f));
        }
        __syncthreads();
        if (t < HEADS) {
            float a0 = 0.f, a1 = 0.f, a2 = 0.f, a3 = 0.f;
            const float4* w2 = (const float4*)(mw2 + t * 128);
            const float4* hh = (const float4*)hid;
            #pragma unroll 4
            for (int j = 0; j < 32; j++) {
                float4 wv = w2[j], hvv = hh[j];
                a0 += wv.x * hvv.x; a1 += wv.y * hvv.y;
                a2 += wv.z * hvv.z; a3 += wv.w * hvv.w;
            }
            g_bias[t * 225 + idx] = mb2[t] + (a0 + a1) + (a2 + a3);
        }
    }
}

// =================================================================
// fp16 mma.sync GEMM (unchanged)
// =================================================================
#define HP   72
#define KCH  64
#define NCH  6
#define GEMM_SMEM (4 * 128 * HP * 2)

template <int MODE>
__global__ void __launch_bounds__(256) gemm_mma(
        const __half* __restrict__ Aptr, const __half* __restrict__ Bptr,
        const float* __restrict__ biasptr, void* __restrict__ outp) {
    extern __shared__ __align__(16) __half smh[];
    __half* AsB[2] = { smh, smh + 128 * HP };
    __half* BsB[2] = { smh + 2 * 128 * HP, smh + 3 * 128 * HP };

    int tid = threadIdx.x;
    int n0 = blockIdx.x * 128;
    int m0 = blockIdx.y * 128;
    int lane = tid & 31, wid = tid >> 5;
    int wm = (wid & 3) * 32;
    int wn = (wid >> 2) * 64;

    const __half* Arow = Aptr + (size_t)m0 * CDIM;
    const __half* Brow = Bptr + (size_t)n0 * CDIM;
    uint32_t aU[2] = { smem_u32(AsB[0]), smem_u32(AsB[1]) };
    uint32_t bU[2] = { smem_u32(BsB[0]), smem_u32(BsB[1]) };

    int ldrow = tid >> 3, ldseg = tid & 7;
    auto load_chunk = [&](int k0, int buf) {
        #pragma unroll
        for (int i = 0; i < 4; i++) {
            int row = ldrow + i * 32;
            uint32_t so = (uint32_t)(row * HP + ldseg * 8) * 2;
            cp16(aU[buf] + so, Arow + (size_t)row * CDIM + k0 + ldseg * 8);
            cp16(bU[buf] + so, Brow + (size_t)row * CDIM + k0 + ldseg * 8);
        }
        CP_COMMIT();
    };

    float acc[2][8][4];
    #pragma unroll
    for (int mt = 0; mt < 2; mt++)
        #pragma unroll
        for (int nt = 0; nt < 8; nt++)
            #pragma unroll
            for (int j = 0; j < 4; j++) acc[mt][nt][j] = 0.f;

    load_chunk(0, 0);

    int r4 = lane >> 2, c4 = lane & 3;
    for (int i = 0; i < NCH; i++) {
        if (i + 1 < NCH) { load_chunk((i + 1) * KCH, (i + 1) & 1); CP_WAIT1(); }
        else             { CP_WAIT0(); }
        __syncthreads();
        const __half* Ab = AsB[i & 1];
        const __half* Bb = BsB[i & 1];
        #pragma unroll
        for (int kk = 0; kk < 4; kk++) {
            int kb = kk * 16;
            uint32_t a[2][4];
            #pragma unroll
            for (int mt = 0; mt < 2; mt++) {
                int row = wm + mt * 16 + r4;
                a[mt][0] = *(const uint32_t*)&Ab[row * HP + kb + 2 * c4];
                a[mt][1] = *(const uint32_t*)&Ab[(row + 8) * HP + kb + 2 * c4];
                a[mt][2] = *(const uint32_t*)&Ab[row * HP + kb + 2 * c4 + 8];
                a[mt][3] = *(const uint32_t*)&Ab[(row + 8) * HP + kb + 2 * c4 + 8];
            }
            uint32_t b[8][2];
            #pragma unroll
            for (int nt = 0; nt < 8; nt++) {
                int nrow = wn + nt * 8 + r4;
                b[nt][0] = *(const uint32_t*)&Bb[nrow * HP + kb + 2 * c4];
                b[nt][1] = *(const uint32_t*)&Bb[nrow * HP + kb + 2 * c4 + 8];
            }
            #pragma unroll
            for (int mt = 0; mt < 2; mt++)
                #pragma unroll
                for (int nt = 0; nt < 8; nt++)
                    mma16(acc[mt][nt], a[mt], b[nt]);
        }
        __syncthreads();
    }

    int cb = c4 * 2;
    if (MODE == 0) {
        __half* oph = (__half*)outp;
        #pragma unroll
        for (int mt = 0; mt < 2; mt++)
            #pragma unroll
            for (int half = 0; half < 2; half++) {
                int m = m0 + wm + mt * 16 + r4 + half * 8;
                __half* dst = oph + (size_t)m * QKVC + n0 + wn;
                #pragma unroll
                for (int nt = 0; nt < 8; nt++) {
                    int o = n0 + wn + nt * 8 + cb;
                    *(__half2*)(dst + nt * 8 + cb) = __floats2half2_rn(
                        acc[mt][nt][half * 2 + 0] + biasptr[o],
                        acc[mt][nt][half * 2 + 1] + biasptr[o + 1]);
                }
            }
    } else {
        float* opf = (float*)outp;
        int b = m0 >> 14;
        int ppb = m0 & (HWPIX - 1);
        #pragma unroll
        for (int mt = 0; mt < 2; mt++)
            #pragma unroll
            for (int half = 0; half < 2; half++) {
                int pp = ppb + wm + mt * 16 + r4 + half * 8;
                #pragma unroll
                for (int nt = 0; nt < 8; nt++)
                    #pragma unroll
                    for (int j = 0; j < 2; j++) {
                        int o = n0 + wn + nt * 8 + cb + j;
                        opf[((size_t)(b * CDIM + o)) * HWPIX + pp] =
                            acc[mt][nt][half * 2 + j] + biasptr[o];
                    }
            }
    }
}

// =================================================================
// PDSCA conv helper: row-register depthwise 3x3, outputs in o8[8]
// =================================================================
__device__ __forceinline__ void conv33(
        const float* xs, const float* __restrict__ dw_w,
        const float* __restrict__ dw_b, int it, float* o8) {
    int c = it >> 3, sy = it & 7;
    float rm[10], rc[10], rp[10];
    #pragma unroll
    for (int i = 0; i < 10; i++) { rm[i] = 0.f; rc[i] = 0.f; rp[i] = 0.f; }
    {
        const float* base = xs + (2 * c + (sy >> 2)) * 36 + (sy & 3) * 8;
        float4 v0 = *(const float4*)base, v1 = *(const float4*)(base + 4);
        rc[1] = v0.x; rc[2] = v0.y; rc[3] = v0.z; rc[4] = v0.w;
        rc[5] = v1.x; rc[6] = v1.y; rc[7] = v1.z; rc[8] = v1.w;
    }
    if (sy > 0) {
        int r = sy - 1;
        const float* base = xs + (2 * c + (r >> 2)) * 36 + (r & 3) * 8;
        float4 v0 = *(const float4*)base, v1 = *(const float4*)(base + 4);
        rm[1] = v0.x; rm[2] = v0.y; rm[3] = v0.z; rm[4] = v0.w;
        rm[5] = v1.x; rm[6] = v1.y; rm[7] = v1.z; rm[8] = v1.w;
    }
    if (sy < 7) {
        int r = sy + 1;
        const float* base = xs + (2 * c + (r >> 2)) * 36 + (r & 3) * 8;
        float4 v0 = *(const float4*)base, v1 = *(const float4*)(base + 4);
        rp[1] = v0.x; rp[2] = v0.y; rp[3] = v0.z; rp[4] = v0.w;
        rp[5] = v1.x; rp[6] = v1.y; rp[7] = v1.z; rp[8] = v1.w;
    }
    const float* wp = dw_w + c * 9;
    float w0 = wp[0], w1 = wp[1], w2 = wp[2];
    float w3 = wp[3], w4 = wp[4], w5 = wp[5];
    float w6 = wp[6], w7 = wp[7], w8 = wp[8];
    float bias = dw_b[c];
    #pragma unroll
    for (int ix = 0; ix < 8; ix++) {
        float s = bias;
        s += w0 * rm[ix] + w1 * rm[ix + 1] + w2 * rm[ix + 2];
        s += w3 * rc[ix] + w4 * rc[ix + 1] + w5 * rc[ix + 2];
        s += w6 * rp[ix] + w7 * rp[ix + 1] + w8 * rp[ix + 2];
        o8[ix] = s;
    }
}

__device__ __forceinline__ void gate_apply(
        float* xs, const float* o8, float cav, int it) {
    int c = it >> 3, sy = it & 7;
    float* base = xs + (2 * c + (sy >> 2)) * 36 + (sy & 3) * 8;
    float4 x0 = *(float4*)base, x1 = *(float4*)(base + 4);
    x0.x = rn_tf32(x0.x / (1.0f + __expf(-(o8[0] + cav))));
    x0.y = rn_tf32(x0.y / (1.0f + __expf(-(o8[1] + cav))));
    x0.z = rn_tf32(x0.z / (1.0f + __expf(-(o8[2] + cav))));
    x0.w = rn_tf32(x0.w / (1.0f + __expf(-(o8[3] + cav))));
    x1.x = rn_tf32(x1.x / (1.0f + __expf(-(o8[4] + cav))));
    x1.y = rn_tf32(x1.y / (1.0f + __expf(-(o8[5] + cav))));
    x1.z = rn_tf32(x1.z / (1.0f + __expf(-(o8[6] + cav))));
    x1.w = rn_tf32(x1.w / (1.0f + __expf(-(o8[7] + cav))));
    *(float4*)base = x0;
    *(float4*)(base + 4) = x1;
}

// =================================================================
// per-(window, head) merged PDSCA(Q,K) + attention
// =================================================================
#define ATP 68
#define VP  68

__global__ void __launch_bounds__(128) attn_kernel(
        const float* __restrict__ log_temp,
        const float* __restrict__ pqw,  const float* __restrict__ pqb,
        const float* __restrict__ pqf1w, const float* __restrict__ pqf1b,
        const float* __restrict__ pqf2w, const float* __restrict__ pqf2b,
        const float* __restrict__ pkw,  const float* __restrict__ pkb,
        const float* __restrict__ pkf1w, const float* __restrict__ pkf1b,
        const float* __restrict__ pkf2w, const float* __restrict__ pkf2b) {
    __shared__ __align__(16) float qs[NTOK * 36];
    __shared__ __align__(16) float ks[NTOK * 36];
    __shared__ __align__(16) float vsT[HD * VP];
    __shared__ __align__(16) float at[NTOK * ATP];
    __shared__ float gapq[32], gapk[32], hidq[8], hidk[8], caq[32], cak[32];

    int bi  = blockIdx.x;
    int win = bi / HEADS;
    int h   = bi - win * HEADS;
    int t   = threadIdx.x;
    int b   = win >> 8, hb = (win >> 4) & 15, wb = win & 15;
    int pbase = b * HWPIX + hb * 8 * WDIM + wb * 8;

    for (int tt = t; tt < 256; tt += 128) {
        int n = tt >> 2, d8 = (tt & 3) * 8;
        int p = pbase + (n >> 3) * WDIM + (n & 7);
        const __half* src = g_qkvh + (size_t)p * QKVC + h * HD + d8;
        union { int4 i; __half2 h[4]; } uq, uk, uv;
        uq.i = *(const int4*)(src);
        uk.i = *(const int4*)(src + CDIM);
        uv.i = *(const int4*)(src + 2 * CDIM);
        float2 q0 = __half22float2(uq.h[0]), q1 = __half22float2(uq.h[1]);
        float2 q2 = __half22float2(uq.h[2]), q3 = __half22float2(uq.h[3]);
        float2 k0 = __half22float2(uk.h[0]), k1 = __half22float2(uk.h[1]);
        float2 k2 = __half22float2(uk.h[2]), k3 = __half22float2(uk.h[3]);
        float2 v0 = __half22float2(uv.h[0]), v1 = __half22float2(uv.h[1]);
        float2 v2 = __half22float2(uv.h[2]), v3 = __half22float2(uv.h[3]);
        *(float4*)&qs[n * 36 + d8]     = make_float4(q0.x, q0.y, q1.x, q1.y);
        *(float4*)&qs[n * 36 + d8 + 4] = make_float4(q2.x, q2.y, q3.x, q3.y);
        *(float4*)&ks[n * 36 + d8]     = make_float4(k0.x, k0.y, k1.x, k1.y);
        *(float4*)&ks[n * 36 + d8 + 4] = make_float4(k2.x, k2.y, k3.x, k3.y);
        vsT[(d8 + 0) * VP + n] = v0.x;
        vsT[(d8 + 1) * VP + n] = v0.y;
        vsT[(d8 + 2) * VP + n] = v1.x;
        vsT[(d8 + 3) * VP + n] = v1.y;
        vsT[(d8 + 4) * VP + n] = v2.x;
        vsT[(d8 + 5) * VP + n] = v2.y;
        vsT[(d8 + 6) * VP + n] = v3.x;
        vsT[(d8 + 7) * VP + n] = v3.y;
    }
    __syncthreads();

    // ===== merged PDSCA for Q and K =====
    float ocq[2][8], ock[2][8];
    conv33(qs, pqw, pqb, t, ocq[0]);
    conv33(qs, pqw, pqb, t + 128, ocq[1]);
    conv33(ks, pkw, pkb, t, ock[0]);
    conv33(ks, pkw, pkb, t + 128, ock[1]);
    if (t < 32) {
        const float4* p0 = (const float4*)(qs + (2 * t) * 36);
        const float4* p1 = (const float4*)(qs + (2 * t + 1) * 36);
        float4 s4 = make_float4(0.f, 0.f, 0.f, 0.f);
        #pragma unroll
        for (int i = 0; i < 8; i++) {
            float4 a = p0[i], bb2 = p1[i];
            s4.x += a.x + bb2.x; s4.y += a.y + bb2.y;
            s4.z += a.z + bb2.z; s4.w += a.w + bb2.w;
        }
        gapq[t] = (s4.x + s4.y + s4.z + s4.w) * (1.0f / 64.0f);
    } else if (t >= 64 && t < 96) {
        int c = t - 64;
        const float4* p0 = (const float4*)(ks + (2 * c) * 36);
        const float4* p1 = (const float4*)(ks + (2 * c + 1) * 36);
        float4 s4 = make_float4(0.f, 0.f, 0.f, 0.f);
        #pragma unroll
        for (int i = 0; i < 8; i++) {
            float4 a = p0[i], bb2 = p1[i];
            s4.x += a.x + bb2.x; s4.y += a.y + bb2.y;
            s4.z += a.z + bb2.z; s4.w += a.w + bb2.w;
        }
        gapk[c] = (s4.x + s4.y + s4.z + s4.w) * (1.0f / 64.0f);
    }
    __syncthreads();
    if (t < 8) {
        float s = pqf1b[t];
        #pragma unroll
        for (int c = 0; c < 32; c++) s += gapq[c] * pqf1w[t * 32 + c];
        hidq[t] = fmaxf(s, 0.f);
    } else if (t >= 64 && t < 72) {
        int u = t - 64;
        float s = pkf1b[u];
        #pragma unroll
        for (int c = 0; c < 32; c++) s += gapk[c] * pkf1w[u * 32 + c];
        hidk[u] = fmaxf(s, 0.f);
    }
    __syncthreads();
    if (t < 32) {
        float s = pqf2b[t];
        #pragma unroll
        for (int j = 0; j < 8; j++) s += hidq[j] * pqf2w[t * 8 + j];
        caq[t] = s;
    } else if (t >= 64 && t < 96) {
        int c = t - 64;
        float s = pkf2b[c];
        #pragma unroll
        for (int j = 0; j < 8; j++) s += hidk[j] * pkf2w[c * 8 + j];
        cak[c] = s;
    }
    __syncthreads();
    gate_apply(qs, ocq[0], caq[t >> 3], t);
    gate_apply(qs, ocq[1], caq[(t + 128) >> 3], t + 128);
    gate_apply(ks, ock[0], cak[t >> 3], t);
    gate_apply(ks, ock[1], cak[(t + 128) >> 3], t + 128);
    __syncthreads();

    // ===== attention =====
    int lane = t & 31, w = t >> 5;
    int r4 = lane >> 2, c4 = lane & 3;
    int m0 = w * 16;

    float sacc[8][4];
    #pragma unroll
    for (int nt = 0; nt < 8; nt++)
        #pragma unroll
        for (int j = 0; j < 4; j++) sacc[nt][j] = 0.f;

    #pragma unroll
    for (int kt = 0; kt < 4; kt++) {
        int kb = kt * 8;
        float a[4];
        a[0] = qs[(m0 + r4) * 36 + kb + c4];
        a[1] = qs[(m0 + r4 + 8) * 36 + kb + c4];
        a[2] = qs[(m0 + r4) * 36 + kb + 4 + c4];
        a[3] = qs[(m0 + r4 + 8) * 36 + kb + 4 + c4];
        #pragma unroll
        for (int nt = 0; nt < 8; nt++) {
            float bfr[2];
            bfr[0] = ks[(nt * 8 + r4) * 36 + kb + c4];
            bfr[1] = ks[(nt * 8 + r4) * 36 + kb + 4 + c4];
            mma8(sacc[nt], a, bfr);
        }
    }

    float temp = __expf(log_temp[0]);
    const float* brow = g_bias + h * 225;
    int r_lo = m0 + r4, r_hi = r_lo + 8;
    int ylo = r_lo >> 3, xlo = r_lo & 7;
    int yhi = r_hi >> 3, xhi = r_hi & 7;

    float mlo = -1e30f, mhi = -1e30f;
    #pragma unroll
    for (int nt = 0; nt < 8; nt++)
        #pragma unroll
        for (int j = 0; j < 2; j++) {
            int col = nt * 8 + 2 * c4 + j;
            int cy = col >> 3, cx = col & 7;
            float blo = brow[(ylo - cy + 7) * 15 + (xlo - cx + 7)];
            float bhi = brow[(yhi - cy + 7) * 15 + (xhi - cx + 7)];
            sacc[nt][j]     = sacc[nt][j] * temp + blo;
            sacc[nt][2 + j] = sacc[nt][2 + j] * temp + bhi;
            mlo = fmaxf(mlo, sacc[nt][j]);
            mhi = fmaxf(mhi, sacc[nt][2 + j]);
        }
    mlo = fmaxf(mlo, __shfl_xor_sync(0xffffffffu, mlo, 1));
    mlo = fmaxf(mlo, __shfl_xor_sync(0xffffffffu, mlo, 2));
    mhi = fmaxf(mhi, __shfl_xor_sync(0xffffffffu, mhi, 1));
    mhi = fmaxf(mhi, __shfl_xor_sync(0xffffffffu, mhi, 2));

    float slo = 0.f, shi = 0.f;
    #pragma unroll
    for (int nt = 0; nt < 8; nt++)
        #pragma unroll
        for (int j = 0; j < 2; j++) {
            float e0 = __expf(sacc[nt][j] - mlo);
            float e1 = __expf(sacc[nt][2 + j] - mhi);
            sacc[nt][j] = e0; sacc[nt][2 + j] = e1;
            slo += e0; shi += e1;
        }
    slo += __shfl_xor_sync(0xffffffffu, slo, 1);
    slo += __shfl_xor_sync(0xffffffffu, slo, 2);
    shi += __shfl_xor_sync(0xffffffffu, shi, 1);
    shi += __shfl_xor_sync(0xffffffffu, shi, 2);
    float ilo = 1.0f / slo, ihi = 1.0f / shi;

    #pragma unroll
    for (int nt = 0; nt < 8; nt++) {
        int col = nt * 8 + 2 * c4;
        float2 vlo, vhi;
        vlo.x = rn_tf32(sacc[nt][0] * ilo);
        vlo.y = rn_tf32(sacc[nt][1] * ilo);
        vhi.x = rn_tf32(sacc[nt][2] * ihi);
        vhi.y = rn_tf32(sacc[nt][3] * ihi);
        *(float2*)&at[r_lo * ATP + col] = vlo;
        *(float2*)&at[r_hi * ATP + col] = vhi;
    }
    __syncwarp();

    float oacc[4][4];
    #pragma unroll
    for (int nt = 0; nt < 4; nt++)
        #pragma unroll
        for (int j = 0; j < 4; j++) oacc[nt][j] = 0.f;

    #pragma unroll
    for (int k8 = 0; k8 < 8; k8++) {
        int kb = k8 * 8;
        float a[4];
        a[0] = at[(m0 + r4) * ATP + kb + c4];
        a[1] = at[(m0 + r4 + 8) * ATP + kb + c4];
        a[2] = at[(m0 + r4) * ATP + kb + 4 + c4];
        a[3] = at[(m0 + r4 + 8) * ATP + kb + 4 + c4];
        #pragma unroll
        for (int nt = 0; nt < 4; nt++) {
            float bfr[2];
            bfr[0] = vsT[(nt * 8 + r4) * VP + kb + c4];
            bfr[1] = vsT[(nt * 8 + r4) * VP + kb + 4 + c4];
            mma8(oacc[nt], a, bfr);
        }
    }

    #pragma unroll
    for (int half = 0; half < 2; half++) {
        int row = (half == 0) ? r_lo : r_hi;
        int p = pbase + (row >> 3) * WDIM + (row & 7);
        __half2* dst = (__half2*)(g_aoh + (size_t)p * CDIM + h * HD);
        #pragma unroll
        for (int nt = 0; nt < 4; nt++)
            dst[(nt * 8 + 2 * c4) >> 1] =
                __floats2half2_rn(oacc[nt][half * 2 + 0], oacc[nt][half * 2 + 1]);
    }
}

// =================================================================
// launch
// =================================================================
extern "C" void kernel_launch(void* const* d_in, const int* in_sizes, int n_in,
                              void* d_out, int out_size) {
    const float* x        = (const float*)d_in[0];
    const float* w_qk     = (const float*)d_in[1];
    const float* b_qk     = (const float*)d_in[2];
    const float* w_v      = (const float*)d_in[3];
    const float* b_v      = (const float*)d_in[4];
    const float* log_temp = (const float*)d_in[5];
    const float* pq_dw_w  = (const float*)d_in[6];
    const float* pq_dw_b  = (const float*)d_in[7];
    const float* pq_f1w   = (const float*)d_in[8];
    const float* pq_f1b   = (const float*)d_in[9];
    const float* pq_f2w   = (const float*)d_in[10];
    const float* pq_f2b   = (const float*)d_in[11];
    const float* pk_dw_w  = (const float*)d_in[12];
    const float* pk_dw_b  = (const float*)d_in[13];
    const float* pk_f1w   = (const float*)d_in[14];
    const float* pk_f1b   = (const float*)d_in[15];
    const float* pk_f2w   = (const float*)d_in[16];
    const float* pk_f2b   = (const float*)d_in[17];
    const float* pos_w    = (const float*)d_in[18];
    const float* pos_sc   = (const float*)d_in[20];
    const float* meta_w1  = (const float*)d_in[21];
    const float* meta_b1  = (const float*)d_in[22];
    const float* meta_w2  = (const float*)d_in[23];
    const float* meta_b2  = (const float*)d_in[24];
    const float* w_po     = (const float*)d_in[25];
    const float* w_proj   = (const float*)d_in[26];
    const float* b_proj   = (const float*)d_in[27];
    float* out = (float*)d_out;

    cudaFuncSetAttribute(gemm_mma<0>, cudaFuncAttributeMaxDynamicSharedMemorySize, GEMM_SMEM);
    cudaFuncSetAttribute(gemm_mma<1>, cudaFuncAttributeMaxDynamicSharedMemorySize, GEMM_SMEM);

    prep_kernel<<<NB_PREP, 256>>>(x, w_qk, b_qk, w_v, b_v, w_proj, w_po,
                                  pos_w, pos_sc, meta_w1, meta_b1, meta_w2, meta_b2);

    {
        const __half* A; cudaGetSymbolAddress((void**)&A, g_xTh);
        const __half* Bp; cudaGetSymbolAddress((void**)&Bp, g_wbh);
        const float* bb; cudaGetSymbolAddress((void**)&bb, g_bqkv);
        void* op; cudaGetSymbolAddress(&op, g_qkvh);
        gemm_mma<0><<<dim3(QKVC / 128, NPIX / 128), 256, GEMM_SMEM>>>(A, Bp, bb, op);
    }

    attn_kernel<<<NWIN * HEADS, 128>>>(log_temp,
        pq_dw_w, pq_dw_b, pq_f1w, pq_f1b, pq_f2w, pq_f2b,
        pk_dw_w, pk_dw_b, pk_f1w, pk_f1b, pk_f2w, pk_f2b);

    {
        const __half* A; cudaGetSymbolAddress((void**)&A, g_aoh);
        const __half* Bp; cudaGetSymbolAddress((void**)&Bp, g_Wch);
        gemm_mma<1><<<dim3(CDIM / 128, NPIX / 128), 256, GEMM_SMEM>>>(A, Bp, b_proj, (void*)out);
    }
}

// round 10
// speedup vs baseline: 5.3581x; 1.1318x over previous
#include <cuda_runtime.h>
#include <cuda_fp16.h>
#include <cstdint>
#include <math.h>

// ---------------- problem constants ----------------
#define BATCH 4
#define CDIM  384
#define HDIM  128
#define WDIM  128
#define HWPIX 16384
#define NPIX  65536
#define HEADS 12
#define HD    32
#define WS    8
#define NTOK  64
#define NWIN  1024
#define QKVC  1152

// ---------------- device scratch ----------------
__device__ __half g_qkvh[(size_t)NPIX * QKVC];
__device__ __half g_aoh[(size_t)NPIX * CDIM];
__device__ __half g_xTh[(size_t)NPIX * CDIM];
__device__ __half g_wbh[QKVC * CDIM];
__device__ float  g_bqkv[QKVC];
__device__ float  g_bias[HEADS * 225];
__device__ __half g_Wch[CDIM * CDIM];

// ---------------- helpers ----------------
__device__ __forceinline__ uint32_t smem_u32(const void* p) {
    uint32_t a;
    asm("{ .reg .u64 t; cvta.to.shared.u64 t, %1; cvt.u32.u64 %0, t; }" : "=r"(a) : "l"(p));
    return a;
}
__device__ __forceinline__ float rn_tf32(float v) {
    uint32_t u;
    asm("cvt.rna.tf32.f32 %0, %1;" : "=r"(u) : "f"(v));
    return __uint_as_float(u);
}
__device__ __forceinline__ void cp16(uint32_t saddr, const void* g) {
    asm volatile("cp.async.cg.shared.global [%0], [%1], 16;" :: "r"(saddr), "l"(g));
}
#define CP_COMMIT() asm volatile("cp.async.commit_group;" ::: "memory")
#define CP_WAIT0()  asm volatile("cp.async.wait_group 0;" ::: "memory")
#define CP_WAIT1()  asm volatile("cp.async.wait_group 1;" ::: "memory")

__device__ __forceinline__ void ldm4(uint32_t* r, uint32_t addr) {
    asm volatile("ldmatrix.sync.aligned.m8n8.x4.shared.b16 {%0,%1,%2,%3}, [%4];"
        : "=r"(r[0]), "=r"(r[1]), "=r"(r[2]), "=r"(r[3]) : "r"(addr));
}

__device__ __forceinline__ void mma16(float* c, const uint32_t* a, const uint32_t* b) {
    asm volatile(
        "mma.sync.aligned.m16n8k16.row.col.f32.f16.f16.f32 "
        "{%0,%1,%2,%3}, {%4,%5,%6,%7}, {%8,%9}, {%0,%1,%2,%3};"
        : "+f"(c[0]), "+f"(c[1]), "+f"(c[2]), "+f"(c[3])
        : "r"(a[0]), "r"(a[1]), "r"(a[2]), "r"(a[3]),
          "r"(b[0]), "r"(b[1]));
}

__device__ __forceinline__ void mma8(float* c, const float* a, const float* b) {
    asm volatile(
        "mma.sync.aligned.m16n8k8.row.col.f32.tf32.tf32.f32 "
        "{%0,%1,%2,%3}, {%4,%5,%6,%7}, {%8,%9}, {%0,%1,%2,%3};"
        : "+f"(c[0]), "+f"(c[1]), "+f"(c[2]), "+f"(c[3])
        : "r"(__float_as_uint(a[0])), "r"(__float_as_uint(a[1])),
          "r"(__float_as_uint(a[2])), "r"(__float_as_uint(a[3])),
          "r"(__float_as_uint(b[0])), "r"(__float_as_uint(b[1])));
}

// =================================================================
// unified prep kernel: xpose | wprep | wc | bias, 256 threads
// =================================================================
#define NB_XPOSE (512 * 12 * 4)
#define NB_WPREP ((QKVC * CDIM) / 256)
#define NB_WC    ((CDIM * CDIM) / 256)
#define NB_BIAS  225
#define NB_PREP  (NB_XPOSE + NB_WPREP + NB_WC + NB_BIAS)

__global__ void __launch_bounds__(256) prep_kernel(
        const float* __restrict__ x,
        const float* __restrict__ w_qk, const float* __restrict__ b_qk,
        const float* __restrict__ w_v,  const float* __restrict__ b_v,
        const float* __restrict__ w_proj, const float* __restrict__ w_po,
        const float* __restrict__ pcw, const float* __restrict__ psc,
        const float* __restrict__ mw1, const float* __restrict__ mb1,
        const float* __restrict__ mw2, const float* __restrict__ mb2) {
    __shared__ __align__(16) float tile[32][33];
    __shared__ __align__(16) float rel[CDIM];
    __shared__ __align__(16) float hid[128];
    __shared__ float part[256];
    int blk = blockIdx.x;
    int t = threadIdx.x;

    if (blk < NB_XPOSE) {
        int bx = blk & 511, by = (blk >> 9) % 12, bz = blk / (512 * 12);
        int tx = t & 31, ty = t >> 5;
        const float* src = x + ((size_t)(bz * CDIM + by * 32)) * HWPIX + bx * 32;
        #pragma unroll
        for (int i = 0; i < 32; i += 8)
            tile[ty + i][tx] = src[(size_t)(ty + i) * HWPIX + tx];
        __syncthreads();
        __half* dst = g_xTh + ((size_t)(bz * HWPIX + bx * 32)) * CDIM + by * 32;
        #pragma unroll
        for (int i = 0; i < 32; i += 8)
            dst[(size_t)(ty + i) * CDIM + tx] = __float2half_rn(tile[tx][ty + i]);
        return;
    }
    blk -= NB_XPOSE;
    if (blk < NB_WPREP) {
        int i = blk * 256 + t;
        float v = (i < 2 * CDIM * CDIM) ? w_qk[i] : w_v[i - 2 * CDIM * CDIM];
        g_wbh[i] = __float2half_rn(v);
        if (i < QKVC)
            g_bqkv[i] = (i < 2 * CDIM) ? b_qk[i] : b_v[i - 2 * CDIM];
        return;
    }
    blk -= NB_WPREP;
    if (blk < NB_WC) {
        int idx = blk * 256 + t;
        int o = idx / CDIM, c = idx - o * CDIM;
        const float* pr = w_proj + o * CDIM;
        float a0 = 0.f, a1 = 0.f, a2 = 0.f, a3 = 0.f;
        for (int k = 0; k < CDIM; k += 4) {
            a0 += pr[k] * w_po[k * CDIM + c];
            a1 += pr[k + 1] * w_po[(k + 1) * CDIM + c];
            a2 += pr[k + 2] * w_po[(k + 2) * CDIM + c];
            a3 += pr[k + 3] * w_po[(k + 3) * CDIM + c];
        }
        g_Wch[o * CDIM + c] = __float2half_rn((a0 + a1) + (a2 + a3));
        return;
    }
    blk -= NB_WC;
    {
        int idx = blk;
        float dx = (float)((idx % 15) - 7) * (2.0f / 7.0f);
        float dy = (float)((idx / 15) - 7) * (2.0f / 7.0f);
        int u = t & 127, hv2 = t >> 7;
        float sc = psc[0];
        for (int c = t; c < CDIM; c += 256)
            rel[c] = sc * (pcw[2 * c] * dx + pcw[2 * c + 1] * dy);
        __syncthreads();
        {
            float a0 = 0.f, a1 = 0.f, a2 = 0.f, a3 = 0.f;
            const float4* w = (const float4*)(mw1 + u * CDIM + hv2 * 192);
            const float4* r = (const float4*)(rel + hv2 * 192);
            #pragma unroll 4
            for (int c = 0; c < 48; c++) {
                float4 wv = w[c], rv = r[c];
                a0 += wv.x * rv.x; a1 += wv.y * rv.y;
                a2 += wv.z * rv.z; a3 += wv.w * rv.w;
            }
            part[t] = (a0 + a1) + (a2 + a3);
        }
        __syncthreads();
        if (t < 128) {
            float s = mb1[t] + part[t] + part[t + 128];
            hid[t] = 0.5f * s * (1.0f + erff(s * 0.70710678118654752f));
        }
        __syncthreads();
        if (t < HEADS) {
            float a0 = 0.f, a1 = 0.f, a2 = 0.f, a3 = 0.f;
            const float4* w2 = (const float4*)(mw2 + t * 128);
            const float4* hh = (const float4*)hid;
            #pragma unroll 4
            for (int j = 0; j < 32; j++) {
                float4 wv = w2[j], hvv = hh[j];
                a0 += wv.x * hvv.x; a1 += wv.y * hvv.y;
                a2 += wv.z * hvv.z; a3 += wv.w * hvv.w;
            }
            g_bias[t * 225 + idx] = mb2[t] + (a0 + a1) + (a2 + a3);
        }
    }
}

// =================================================================
// fp16 mma.sync GEMM with ldmatrix fragment loads
// =================================================================
#define HP   72
#define KCH  64
#define NCH  6
#define GEMM_SMEM (4 * 128 * HP * 2)

template <int MODE>
__global__ void __launch_bounds__(256) gemm_mma(
        const __half* __restrict__ Aptr, const __half* __restrict__ Bptr,
        const float* __restrict__ biasptr, void* __restrict__ outp) {
    extern __shared__ __align__(16) __half smh[];
    __half* AsB[2] = { smh, smh + 128 * HP };
    __half* BsB[2] = { smh + 2 * 128 * HP, smh + 3 * 128 * HP };

    int tid = threadIdx.x;
    int n0 = blockIdx.x * 128;
    int m0 = blockIdx.y * 128;
    int lane = tid & 31, wid = tid >> 5;
    int wm = (wid & 3) * 32;
    int wn = (wid >> 2) * 64;

    const __half* Arow = Aptr + (size_t)m0 * CDIM;
    const __half* Brow = Bptr + (size_t)n0 * CDIM;
    uint32_t aU[2] = { smem_u32(AsB[0]), smem_u32(AsB[1]) };
    uint32_t bU[2] = { smem_u32(BsB[0]), smem_u32(BsB[1]) };

    int ldrow = tid >> 3, ldseg = tid & 7;
    auto load_chunk = [&](int k0, int buf) {
        #pragma unroll
        for (int i = 0; i < 4; i++) {
            int row = ldrow + i * 32;
            uint32_t so = (uint32_t)(row * HP + ldseg * 8) * 2;
            cp16(aU[buf] + so, Arow + (size_t)row * CDIM + k0 + ldseg * 8);
            cp16(bU[buf] + so, Brow + (size_t)row * CDIM + k0 + ldseg * 8);
        }
        CP_COMMIT();
    };

    float acc[2][8][4];
    #pragma unroll
    for (int mt = 0; mt < 2; mt++)
        #pragma unroll
        for (int nt = 0; nt < 8; nt++)
            #pragma unroll
            for (int j = 0; j < 4; j++) acc[mt][nt][j] = 0.f;

    load_chunk(0, 0);

    // ldmatrix lane-address precompute
    int lr = lane & 7, g = lane >> 3;
    // A: matrices (rows lo k-lo, rows hi k-lo, rows lo k-hi, rows hi k-hi)
    int arow[2];
    arow[0] = wm + (g & 1) * 8 + lr;
    arow[1] = wm + 16 + (g & 1) * 8 + lr;
    int akoff = (g >> 1) * 8;
    // B: per q: matrices (nt0 k-lo, nt0 k-hi, nt1 k-lo, nt1 k-hi)
    int brow[4];
    #pragma unroll
    for (int q = 0; q < 4; q++)
        brow[q] = wn + (2 * q + (g >> 1)) * 8 + lr;
    int bkoff = (g & 1) * 8;

    int r4 = lane >> 2, c4 = lane & 3;
    for (int i = 0; i < NCH; i++) {
        if (i + 1 < NCH) { load_chunk((i + 1) * KCH, (i + 1) & 1); CP_WAIT1(); }
        else             { CP_WAIT0(); }
        __syncthreads();
        uint32_t aBase = aU[i & 1];
        uint32_t bBase = bU[i & 1];
        #pragma unroll
        for (int kk = 0; kk < 4; kk++) {
            int kb = kk * 16;
            uint32_t a[2][4];
            #pragma unroll
            for (int mt = 0; mt < 2; mt++)
                ldm4(a[mt], aBase + (uint32_t)(arow[mt] * HP + kb + akoff) * 2);
            uint32_t b[8][2];
            #pragma unroll
            for (int q = 0; q < 4; q++) {
                uint32_t r[4];
                ldm4(r, bBase + (uint32_t)(brow[q] * HP + kb + bkoff) * 2);
                b[2 * q][0] = r[0]; b[2 * q][1] = r[1];
                b[2 * q + 1][0] = r[2]; b[2 * q + 1][1] = r[3];
            }
            #pragma unroll
            for (int mt = 0; mt < 2; mt++)
                #pragma unroll
                for (int nt = 0; nt < 8; nt++)
                    mma16(acc[mt][nt], a[mt], b[nt]);
        }
        __syncthreads();
    }

    int cb = c4 * 2;
    if (MODE == 0) {
        __half* oph = (__half*)outp;
        #pragma unroll
        for (int mt = 0; mt < 2; mt++)
            #pragma unroll
            for (int half = 0; half < 2; half++) {
                int m = m0 + wm + mt * 16 + r4 + half * 8;
                __half* dst = oph + (size_t)m * QKVC + n0 + wn;
                #pragma unroll
                for (int nt = 0; nt < 8; nt++) {
                    int o = n0 + wn + nt * 8 + cb;
                    *(__half2*)(dst + nt * 8 + cb) = __floats2half2_rn(
                        acc[mt][nt][half * 2 + 0] + biasptr[o],
                        acc[mt][nt][half * 2 + 1] + biasptr[o + 1]);
                }
            }
    } else {
        float* opf = (float*)outp;
        int b = m0 >> 14;
        int ppb = m0 & (HWPIX - 1);
        #pragma unroll
        for (int mt = 0; mt < 2; mt++)
            #pragma unroll
            for (int half = 0; half < 2; half++) {
                int pp = ppb + wm + mt * 16 + r4 + half * 8;
                #pragma unroll
                for (int nt = 0; nt < 8; nt++)
                    #pragma unroll
                    for (int j = 0; j < 2; j++) {
                        int o = n0 + wn + nt * 8 + cb + j;
                        opf[((size_t)(b * CDIM + o)) * HWPIX + pp] =
                            acc[mt][nt][half * 2 + j] + biasptr[o];
                    }
            }
    }
}

// =================================================================
// PDSCA conv helper (unchanged)
// =================================================================
__device__ __forceinline__ void conv33(
        const float* xs, const float* __restrict__ dw_w,
        const float* __restrict__ dw_b, int it, float* o8) {
    int c = it >> 3, sy = it & 7;
    float rm[10], rc[10], rp[10];
    #pragma unroll
    for (int i = 0; i < 10; i++) { rm[i] = 0.f; rc[i] = 0.f; rp[i] = 0.f; }
    {
        const float* base = xs + (2 * c + (sy >> 2)) * 36 + (sy & 3) * 8;
        float4 v0 = *(const float4*)base, v1 = *(const float4*)(base + 4);
        rc[1] = v0.x; rc[2] = v0.y; rc[3] = v0.z; rc[4] = v0.w;
        rc[5] = v1.x; rc[6] = v1.y; rc[7] = v1.z; rc[8] = v1.w;
    }
    if (sy > 0) {
        int r = sy - 1;
        const float* base = xs + (2 * c + (r >> 2)) * 36 + (r & 3) * 8;
        float4 v0 = *(const float4*)base, v1 = *(const float4*)(base + 4);
        rm[1] = v0.x; rm[2] = v0.y; rm[3] = v0.z; rm[4] = v0.w;
        rm[5] = v1.x; rm[6] = v1.y; rm[7] = v1.z; rm[8] = v1.w;
    }
    if (sy < 7) {
        int r = sy + 1;
        const float* base = xs + (2 * c + (r >> 2)) * 36 + (r & 3) * 8;
        float4 v0 = *(const float4*)base, v1 = *(const float4*)(base + 4);
        rp[1] = v0.x; rp[2] = v0.y; rp[3] = v0.z; rp[4] = v0.w;
        rp[5] = v1.x; rp[6] = v1.y; rp[7] = v1.z; rp[8] = v1.w;
    }
    const float* wp = dw_w + c * 9;
    float w0 = wp[0], w1 = wp[1], w2 = wp[2];
    float w3 = wp[3], w4 = wp[4], w5 = wp[5];
    float w6 = wp[6], w7 = wp[7], w8 = wp[8];
    float bias = dw_b[c];
    #pragma unroll
    for (int ix = 0; ix < 8; ix++) {
        float s = bias;
        s += w0 * rm[ix] + w1 * rm[ix + 1] + w2 * rm[ix + 2];
        s += w3 * rc[ix] + w4 * rc[ix + 1] + w5 * rc[ix + 2];
        s += w6 * rp[ix] + w7 * rp[ix + 1] + w8 * rp[ix + 2];
        o8[ix] = s;
    }
}

__device__ __forceinline__ void gate_apply(
        float* xs, const float* o8, float cav, int it) {
    int c = it >> 3, sy = it & 7;
    float* base = xs + (2 * c + (sy >> 2)) * 36 + (sy & 3) * 8;
    float4 x0 = *(float4*)base, x1 = *(float4*)(base + 4);
    x0.x = rn_tf32(x0.x / (1.0f + __expf(-(o8[0] + cav))));
    x0.y = rn_tf32(x0.y / (1.0f + __expf(-(o8[1] + cav))));
    x0.z = rn_tf32(x0.z / (1.0f + __expf(-(o8[2] + cav))));
    x0.w = rn_tf32(x0.w / (1.0f + __expf(-(o8[3] + cav))));
    x1.x = rn_tf32(x1.x / (1.0f + __expf(-(o8[4] + cav))));
    x1.y = rn_tf32(x1.y / (1.0f + __expf(-(o8[5] + cav))));
    x1.z = rn_tf32(x1.z / (1.0f + __expf(-(o8[6] + cav))));
    x1.w = rn_tf32(x1.w / (1.0f + __expf(-(o8[7] + cav))));
    *(float4*)base = x0;
    *(float4*)(base + 4) = x1;
}

// =================================================================
// per-(window, head) merged PDSCA(Q,K) + attention (unchanged)
// =================================================================
#define ATP 68
#define VP  68

__global__ void __launch_bounds__(128) attn_kernel(
        const float* __restrict__ log_temp,
        const float* __restrict__ pqw,  const float* __restrict__ pqb,
        const float* __restrict__ pqf1w, const float* __restrict__ pqf1b,
        const float* __restrict__ pqf2w, const float* __restrict__ pqf2b,
        const float* __restrict__ pkw,  const float* __restrict__ pkb,
        const float* __restrict__ pkf1w, const float* __restrict__ pkf1b,
        const float* __restrict__ pkf2w, const float* __restrict__ pkf2b) {
    __shared__ __align__(16) float qs[NTOK * 36];
    __shared__ __align__(16) float ks[NTOK * 36];
    __shared__ __align__(16) float vsT[HD * VP];
    __shared__ __align__(16) float at[NTOK * ATP];
    __shared__ float gapq[32], gapk[32], hidq[8], hidk[8], caq[32], cak[32];

    int bi  = blockIdx.x;
    int win = bi / HEADS;
    int h   = bi - win * HEADS;
    int t   = threadIdx.x;
    int b   = win >> 8, hb = (win >> 4) & 15, wb = win & 15;
    int pbase = b * HWPIX + hb * 8 * WDIM + wb * 8;

    for (int tt = t; tt < 256; tt += 128) {
        int n = tt >> 2, d8 = (tt & 3) * 8;
        int p = pbase + (n >> 3) * WDIM + (n & 7);
        const __half* src = g_qkvh + (size_t)p * QKVC + h * HD + d8;
        union { int4 i; __half2 h[4]; } uq, uk, uv;
        uq.i = *(const int4*)(src);
        uk.i = *(const int4*)(src + CDIM);
        uv.i = *(const int4*)(src + 2 * CDIM);
        float2 q0 = __half22float2(uq.h[0]), q1 = __half22float2(uq.h[1]);
        float2 q2 = __half22float2(uq.h[2]), q3 = __half22float2(uq.h[3]);
        float2 k0 = __half22float2(uk.h[0]), k1 = __half22float2(uk.h[1]);
        float2 k2 = __half22float2(uk.h[2]), k3 = __half22float2(uk.h[3]);
        float2 v0 = __half22float2(uv.h[0]), v1 = __half22float2(uv.h[1]);
        float2 v2 = __half22float2(uv.h[2]), v3 = __half22float2(uv.h[3]);
        *(float4*)&qs[n * 36 + d8]     = make_float4(q0.x, q0.y, q1.x, q1.y);
        *(float4*)&qs[n * 36 + d8 + 4] = make_float4(q2.x, q2.y, q3.x, q3.y);
        *(float4*)&ks[n * 36 + d8]     = make_float4(k0.x, k0.y, k1.x, k1.y);
        *(float4*)&ks[n * 36 + d8 + 4] = make_float4(k2.x, k2.y, k3.x, k3.y);
        vsT[(d8 + 0) * VP + n] = v0.x;
        vsT[(d8 + 1) * VP + n] = v0.y;
        vsT[(d8 + 2) * VP + n] = v1.x;
        vsT[(d8 + 3) * VP + n] = v1.y;
        vsT[(d8 + 4) * VP + n] = v2.x;
        vsT[(d8 + 5) * VP + n] = v2.y;
        vsT[(d8 + 6) * VP + n] = v3.x;
        vsT[(d8 + 7) * VP + n] = v3.y;
    }
    __syncthreads();

    float ocq[2][8], ock[2][8];
    conv33(qs, pqw, pqb, t, ocq[0]);
    conv33(qs, pqw, pqb, t + 128, ocq[1]);
    conv33(ks, pkw, pkb, t, ock[0]);
    conv33(ks, pkw, pkb, t + 128, ock[1]);
    if (t < 32) {
        const float4* p0 = (const float4*)(qs + (2 * t) * 36);
        const float4* p1 = (const float4*)(qs + (2 * t + 1) * 36);
        float4 s4 = make_float4(0.f, 0.f, 0.f, 0.f);
        #pragma unroll
        for (int i = 0; i < 8; i++) {
            float4 a = p0[i], bb2 = p1[i];
            s4.x += a.x + bb2.x; s4.y += a.y + bb2.y;
            s4.z += a.z + bb2.z; s4.w += a.w + bb2.w;
        }
        gapq[t] = (s4.x + s4.y + s4.z + s4.w) * (1.0f / 64.0f);
    } else if (t >= 64 && t < 96) {
        int c = t - 64;
        const float4* p0 = (const float4*)(ks + (2 * c) * 36);
        const float4* p1 = (const float4*)(ks + (2 * c + 1) * 36);
        float4 s4 = make_float4(0.f, 0.f, 0.f, 0.f);
        #pragma unroll
        for (int i = 0; i < 8; i++) {
            float4 a = p0[i], bb2 = p1[i];
            s4.x += a.x + bb2.x; s4.y += a.y + bb2.y;
            s4.z += a.z + bb2.z; s4.w += a.w + bb2.w;
        }
        gapk[c] = (s4.x + s4.y + s4.z + s4.w) * (1.0f / 64.0f);
    }
    __syncthreads();
    if (t < 8) {
        float s = pqf1b[t];
        #pragma unroll
        for (int c = 0; c < 32; c++) s += gapq[c] * pqf1w[t * 32 + c];
        hidq[t] = fmaxf(s, 0.f);
    } else if (t >= 64 && t < 72) {
        int u = t - 64;
        float s = pkf1b[u];
        #pragma unroll
        for (int c = 0; c < 32; c++) s += gapk[c] * pkf1w[u * 32 + c];
        hidk[u] = fmaxf(s, 0.f);
    }
    __syncthreads();
    if (t < 32) {
        float s = pqf2b[t];
        #pragma unroll
        for (int j = 0; j < 8; j++) s += hidq[j] * pqf2w[t * 8 + j];
        caq[t] = s;
    } else if (t >= 64 && t < 96) {
        int c = t - 64;
        float s = pkf2b[c];
        #pragma unroll
        for (int j = 0; j < 8; j++) s += hidk[j] * pkf2w[c * 8 + j];
        cak[c] = s;
    }
    __syncthreads();
    gate_apply(qs, ocq[0], caq[t >> 3], t);
    gate_apply(qs, ocq[1], caq[(t + 128) >> 3], t + 128);
    gate_apply(ks, ock[0], cak[t >> 3], t);
    gate_apply(ks, ock[1], cak[(t + 128) >> 3], t + 128);
    __syncthreads();

    int lane = t & 31, w = t >> 5;
    int r4 = lane >> 2, c4 = lane & 3;
    int m0 = w * 16;

    float sacc[8][4];
    #pragma unroll
    for (int nt = 0; nt < 8; nt++)
        #pragma unroll
        for (int j = 0; j < 4; j++) sacc[nt][j] = 0.f;

    #pragma unroll
    for (int kt = 0; kt < 4; kt++) {
        int kb = kt * 8;
        float a[4];
        a[0] = qs[(m0 + r4) * 36 + kb + c4];
        a[1] = qs[(m0 + r4 + 8) * 36 + kb + c4];
        a[2] = qs[(m0 + r4) * 36 + kb + 4 + c4];
        a[3] = qs[(m0 + r4 + 8) * 36 + kb + 4 + c4];
        #pragma unroll
        for (int nt = 0; nt < 8; nt++) {
            float bfr[2];
            bfr[0] = ks[(nt * 8 + r4) * 36 + kb + c4];
            bfr[1] = ks[(nt * 8 + r4) * 36 + kb + 4 + c4];
            mma8(sacc[nt], a, bfr);
        }
    }

    float temp = __expf(log_temp[0]);
    const float* brow = g_bias + h * 225;
    int r_lo = m0 + r4, r_hi = r_lo + 8;
    int ylo = r_lo >> 3, xlo = r_lo & 7;
    int yhi = r_hi >> 3, xhi = r_hi & 7;

    float mlo = -1e30f, mhi = -1e30f;
    #pragma unroll
    for (int nt = 0; nt < 8; nt++)
        #pragma unroll
        for (int j = 0; j < 2; j++) {
            int col = nt * 8 + 2 * c4 + j;
            int cy = col >> 3, cx = col & 7;
            float blo = brow[(ylo - cy + 7) * 15 + (xlo - cx + 7)];
            float bhi = brow[(yhi - cy + 7) * 15 + (xhi - cx + 7)];
            sacc[nt][j]     = sacc[nt][j] * temp + blo;
            sacc[nt][2 + j] = sacc[nt][2 + j] * temp + bhi;
            mlo = fmaxf(mlo, sacc[nt][j]);
            mhi = fmaxf(mhi, sacc[nt][2 + j]);
        }
    mlo = fmaxf(mlo, __shfl_xor_sync(0xffffffffu, mlo, 1));
    mlo = fmaxf(mlo, __shfl_xor_sync(0xffffffffu, mlo, 2));
    mhi = fmaxf(mhi, __shfl_xor_sync(0xffffffffu, mhi, 1));
    mhi = fmaxf(mhi, __shfl_xor_sync(0xffffffffu, mhi, 2));

    float slo = 0.f, shi = 0.f;
    #pragma unroll
    for (int nt = 0; nt < 8; nt++)
        #pragma unroll
        for (int j = 0; j < 2; j++) {
            float e0 = __expf(sacc[nt][j] - mlo);
            float e1 = __expf(sacc[nt][2 + j] - mhi);
            sacc[nt][j] = e0; sacc[nt][2 + j] = e1;
            slo += e0; shi += e1;
        }
    slo += __shfl_xor_sync(0xffffffffu, slo, 1);
    slo += __shfl_xor_sync(0xffffffffu, slo, 2);
    shi += __shfl_xor_sync(0xffffffffu, shi, 1);
    shi += __shfl_xor_sync(0xffffffffu, shi, 2);
    float ilo = 1.0f / slo, ihi = 1.0f / shi;

    #pragma unroll
    for (int nt = 0; nt < 8; nt++) {
        int col = nt * 8 + 2 * c4;
        float2 vlo, vhi;
        vlo.x = rn_tf32(sacc[nt][0] * ilo);
        vlo.y = rn_tf32(sacc[nt][1] * ilo);
        vhi.x = rn_tf32(sacc[nt][2] * ihi);
        vhi.y = rn_tf32(sacc[nt][3] * ihi);
        *(float2*)&at[r_lo * ATP + col] = vlo;
        *(float2*)&at[r_hi * ATP + col] = vhi;
    }
    __syncwarp();

    float oacc[4][4];
    #pragma unroll
    for (int nt = 0; nt < 4; nt++)
        #pragma unroll
        for (int j = 0; j < 4; j++) oacc[nt][j] = 0.f;

    #pragma unroll
    for (int k8 = 0; k8 < 8; k8++) {
        int kb = k8 * 8;
        float a[4];
        a[0] = at[(m0 + r4) * ATP + kb + c4];
        a[1] = at[(m0 + r4 + 8) * ATP + kb + c4];
        a[2] = at[(m0 + r4) * ATP + kb + 4 + c4];
        a[3] = at[(m0 + r4 + 8) * ATP + kb + 4 + c4];
        #pragma unroll
        for (int nt = 0; nt < 4; nt++) {
            float bfr[2];
            bfr[0] = vsT[(nt * 8 + r4) * VP + kb + c4];
            bfr[1] = vsT[(nt * 8 + r4) * VP + kb + 4 + c4];
            mma8(oacc[nt], a, bfr);
        }
    }

    #pragma unroll
    for (int half = 0; half < 2; half++) {
        int row = (half == 0) ? r_lo : r_hi;
        int p = pbase + (row >> 3) * WDIM + (row & 7);
        __half2* dst = (__half2*)(g_aoh + (size_t)p * CDIM + h * HD);
        #pragma unroll
        for (int nt = 0; nt < 4; nt++)
            dst[(nt * 8 + 2 * c4) >> 1] =
                __floats2half2_rn(oacc[nt][half * 2 + 0], oacc[nt][half * 2 + 1]);
    }
}

// =================================================================
// launch
// =================================================================
extern "C" void kernel_launch(void* const* d_in, const int* in_sizes, int n_in,
                              void* d_out, int out_size) {
    const float* x        = (const float*)d_in[0];
    const float* w_qk     = (const float*)d_in[1];
    const float* b_qk     = (const float*)d_in[2];
    const float* w_v      = (const float*)d_in[3];
    const float* b_v      = (const float*)d_in[4];
    const float* log_temp = (const float*)d_in[5];
    const float* pq_dw_w  = (const float*)d_in[6];
    const float* pq_dw_b  = (const float*)d_in[7];
    const float* pq_f1w   = (const float*)d_in[8];
    const float* pq_f1b   = (const float*)d_in[9];
    const float* pq_f2w   = (const float*)d_in[10];
    const float* pq_f2b   = (const float*)d_in[11];
    const float* pk_dw_w  = (const float*)d_in[12];
    const float* pk_dw_b  = (const float*)d_in[13];
    const float* pk_f1w   = (const float*)d_in[14];
    const float* pk_f1b   = (const float*)d_in[15];
    const float* pk_f2w   = (const float*)d_in[16];
    const float* pk_f2b   = (const float*)d_in[17];
    const float* pos_w    = (const float*)d_in[18];
    const float* pos_sc   = (const float*)d_in[20];
    const float* meta_w1  = (const float*)d_in[21];
    const float* meta_b1  = (const float*)d_in[22];
    const float* meta_w2  = (const float*)d_in[23];
    const float* meta_b2  = (const float*)d_in[24];
    const float* w_po     = (const float*)d_in[25];
    const float* w_proj   = (const float*)d_in[26];
    const float* b_proj   = (const float*)d_in[27];
    float* out = (float*)d_out;

    cudaFuncSetAttribute(gemm_mma<0>, cudaFuncAttributeMaxDynamicSharedMemorySize, GEMM_SMEM);
    cudaFuncSetAttribute(gemm_mma<1>, cudaFuncAttributeMaxDynamicSharedMemorySize, GEMM_SMEM);

    prep_kernel<<<NB_PREP, 256>>>(x, w_qk, b_qk, w_v, b_v, w_proj, w_po,
                                  pos_w, pos_sc, meta_w1, meta_b1, meta_w2, meta_b2);

    {
        const __half* A; cudaGetSymbolAddress((void**)&A, g_xTh);
        const __half* Bp; cudaGetSymbolAddress((void**)&Bp, g_wbh);
        const float* bb; cudaGetSymbolAddress((void**)&bb, g_bqkv);
        void* op; cudaGetSymbolAddress(&op, g_qkvh);
        gemm_mma<0><<<dim3(QKVC / 128, NPIX / 128), 256, GEMM_SMEM>>>(A, Bp, bb, op);
    }

    attn_kernel<<<NWIN * HEADS, 128>>>(log_temp,
        pq_dw_w, pq_dw_b, pq_f1w, pq_f1b, pq_f2w, pq_f2b,
        pk_dw_w, pk_dw_b, pk_f1w, pk_f1b, pk_f2w, pk_f2b);

    {
        const __half* A; cudaGetSymbolAddress((void**)&A, g_aoh);
        const __half* Bp; cudaGetSymbolAddress((void**)&Bp, g_Wch);
        gemm_mma<1><<<dim3(CDIM / 128, NPIX / 128), 256, GEMM_SMEM>>>(A, Bp, b_proj, (void*)out);
    }
}

// round 11
// speedup vs baseline: 5.4093x; 1.0096x over previous
#include <cuda_runtime.h>
#include <cuda_fp16.h>
#include <cstdint>
#include <math.h>

// ---------------- problem constants ----------------
#define BATCH 4
#define CDIM  384
#define HDIM  128
#define WDIM  128
#define HWPIX 16384
#define NPIX  65536
#define HEADS 12
#define HD    32
#define WS    8
#define NTOK  64
#define NWIN  1024
#define QKVC  1152

// ---------------- device scratch ----------------
__device__ __half g_qkvh[(size_t)NPIX * QKVC];
__device__ __half g_aoh[(size_t)NPIX * CDIM];
__device__ __half g_xTh[(size_t)NPIX * CDIM];
__device__ __half g_wbh[QKVC * CDIM];
__device__ float  g_bqkv[QKVC];
__device__ float  g_bias[HEADS * 225];
__device__ __half g_Wch[CDIM * CDIM];

// ---------------- helpers ----------------
__device__ __forceinline__ uint32_t smem_u32(const void* p) {
    uint32_t a;
    asm("{ .reg .u64 t; cvta.to.shared.u64 t, %1; cvt.u32.u64 %0, t; }" : "=r"(a) : "l"(p));
    return a;
}
__device__ __forceinline__ void cp16(uint32_t saddr, const void* g) {
    asm volatile("cp.async.cg.shared.global [%0], [%1], 16;" :: "r"(saddr), "l"(g));
}
#define CP_COMMIT() asm volatile("cp.async.commit_group;" ::: "memory")
#define CP_WAIT0()  asm volatile("cp.async.wait_group 0;" ::: "memory")
#define CP_WAIT1()  asm volatile("cp.async.wait_group 1;" ::: "memory")

__device__ __forceinline__ void ldm4(uint32_t* r, uint32_t addr) {
    asm volatile("ldmatrix.sync.aligned.m8n8.x4.shared.b16 {%0,%1,%2,%3}, [%4];"
        : "=r"(r[0]), "=r"(r[1]), "=r"(r[2]), "=r"(r[3]) : "r"(addr));
}

__device__ __forceinline__ void mma16(float* c, const uint32_t* a, const uint32_t* b) {
    asm volatile(
        "mma.sync.aligned.m16n8k16.row.col.f32.f16.f16.f32 "
        "{%0,%1,%2,%3}, {%4,%5,%6,%7}, {%8,%9}, {%0,%1,%2,%3};"
        : "+f"(c[0]), "+f"(c[1]), "+f"(c[2]), "+f"(c[3])
        : "r"(a[0]), "r"(a[1]), "r"(a[2]), "r"(a[3]),
          "r"(b[0]), "r"(b[1]));
}

// =================================================================
// unified prep kernel: xpose | wprep | wc | bias, 256 threads
// =================================================================
#define NB_XPOSE (512 * 12 * 4)
#define NB_WPREP ((QKVC * CDIM) / 256)
#define NB_WC    ((CDIM * CDIM) / 256)
#define NB_BIAS  225
#define NB_PREP  (NB_XPOSE + NB_WPREP + NB_WC + NB_BIAS)

__global__ void __launch_bounds__(256) prep_kernel(
        const float* __restrict__ x,
        const float* __restrict__ w_qk, const float* __restrict__ b_qk,
        const float* __restrict__ w_v,  const float* __restrict__ b_v,
        const float* __restrict__ w_proj, const float* __restrict__ w_po,
        const float* __restrict__ pcw, const float* __restrict__ psc,
        const float* __restrict__ mw1, const float* __restrict__ mb1,
        const float* __restrict__ mw2, const float* __restrict__ mb2) {
    __shared__ __align__(16) float tile[32][33];
    __shared__ __align__(16) float rel[CDIM];
    __shared__ __align__(16) float hid[128];
    __shared__ float part[256];
    int blk = blockIdx.x;
    int t = threadIdx.x;

    if (blk < NB_XPOSE) {
        int bx = blk & 511, by = (blk >> 9) % 12, bz = blk / (512 * 12);
        int tx = t & 31, ty = t >> 5;
        const float* src = x + ((size_t)(bz * CDIM + by * 32)) * HWPIX + bx * 32;
        #pragma unroll
        for (int i = 0; i < 32; i += 8)
            tile[ty + i][tx] = src[(size_t)(ty + i) * HWPIX + tx];
        __syncthreads();
        __half* dst = g_xTh + ((size_t)(bz * HWPIX + bx * 32)) * CDIM + by * 32;
        #pragma unroll
        for (int i = 0; i < 32; i += 8)
            dst[(size_t)(ty + i) * CDIM + tx] = __float2half_rn(tile[tx][ty + i]);
        return;
    }
    blk -= NB_XPOSE;
    if (blk < NB_WPREP) {
        int i = blk * 256 + t;
        float v = (i < 2 * CDIM * CDIM) ? w_qk[i] : w_v[i - 2 * CDIM * CDIM];
        g_wbh[i] = __float2half_rn(v);
        if (i < QKVC)
            g_bqkv[i] = (i < 2 * CDIM) ? b_qk[i] : b_v[i - 2 * CDIM];
        return;
    }
    blk -= NB_WPREP;
    if (blk < NB_WC) {
        int idx = blk * 256 + t;
        int o = idx / CDIM, c = idx - o * CDIM;
        const float* pr = w_proj + o * CDIM;
        float a0 = 0.f, a1 = 0.f, a2 = 0.f, a3 = 0.f;
        for (int k = 0; k < CDIM; k += 4) {
            a0 += pr[k] * w_po[k * CDIM + c];
            a1 += pr[k + 1] * w_po[(k + 1) * CDIM + c];
            a2 += pr[k + 2] * w_po[(k + 2) * CDIM + c];
            a3 += pr[k + 3] * w_po[(k + 3) * CDIM + c];
        }
        g_Wch[o * CDIM + c] = __float2half_rn((a0 + a1) + (a2 + a3));
        return;
    }
    blk -= NB_WC;
    {
        int idx = blk;
        float dx = (float)((idx % 15) - 7) * (2.0f / 7.0f);
        float dy = (float)((idx / 15) - 7) * (2.0f / 7.0f);
        int u = t & 127, hv2 = t >> 7;
        float sc = psc[0];
        for (int c = t; c < CDIM; c += 256)
            rel[c] = sc * (pcw[2 * c] * dx + pcw[2 * c + 1] * dy);
        __syncthreads();
        {
            float a0 = 0.f, a1 = 0.f, a2 = 0.f, a3 = 0.f;
            const float4* w = (const float4*)(mw1 + u * CDIM + hv2 * 192);
            const float4* r = (const float4*)(rel + hv2 * 192);
            #pragma unroll 4
            for (int c = 0; c < 48; c++) {
                float4 wv = w[c], rv = r[c];
                a0 += wv.x * rv.x; a1 += wv.y * rv.y;
                a2 += wv.z * rv.z; a3 += wv.w * rv.w;
            }
            part[t] = (a0 + a1) + (a2 + a3);
        }
        __syncthreads();
        if (t < 128) {
            float s = mb1[t] + part[t] + part[t + 128];
            hid[t] = 0.5f * s * (1.0f + erff(s * 0.70710678118654752f));
        }
        __syncthreads();
        if (t < HEADS) {
            float a0 = 0.f, a1 = 0.f, a2 = 0.f, a3 = 0.f;
            const float4* w2 = (const float4*)(mw2 + t * 128);
            const float4* hh = (const float4*)hid;
            #pragma unroll 4
            for (int j = 0; j < 32; j++) {
                float4 wv = w2[j], hvv = hh[j];
                a0 += wv.x * hvv.x; a1 += wv.y * hvv.y;
                a2 += wv.z * hvv.z; a3 += wv.w * hvv.w;
            }
            g_bias[t * 225 + idx] = mb2[t] + (a0 + a1) + (a2 + a3);
        }
    }
}

// =================================================================
// fp16 mma.sync GEMM with ldmatrix; MODE1 epilogue staged via smem
// =================================================================
#define HP   72
#define KCH  64
#define NCH  6
#define GEMM_SMEM (4 * 128 * HP * 2)   // 73728 B; MODE1 staging needs 66048 B

template <int MODE>
__global__ void __launch_bounds__(256) gemm_mma(
        const __half* __restrict__ Aptr, const __half* __restrict__ Bptr,
        const float* __restrict__ biasptr, void* __restrict__ outp) {
    extern __shared__ __align__(16) __half smh[];
    __half* AsB[2] = { smh, smh + 128 * HP };
    __half* BsB[2] = { smh + 2 * 128 * HP, smh + 3 * 128 * HP };

    int tid = threadIdx.x;
    int n0 = blockIdx.x * 128;
    int m0 = blockIdx.y * 128;
    int lane = tid & 31, wid = tid >> 5;
    int wm = (wid & 3) * 32;
    int wn = (wid >> 2) * 64;

    const __half* Arow = Aptr + (size_t)m0 * CDIM;
    const __half* Brow = Bptr + (size_t)n0 * CDIM;
    uint32_t aU[2] = { smem_u32(AsB[0]), smem_u32(AsB[1]) };
    uint32_t bU[2] = { smem_u32(BsB[0]), smem_u32(BsB[1]) };

    int ldrow = tid >> 3, ldseg = tid & 7;
    auto load_chunk = [&](int k0, int buf) {
        #pragma unroll
        for (int i = 0; i < 4; i++) {
            int row = ldrow + i * 32;
            uint32_t so = (uint32_t)(row * HP + ldseg * 8) * 2;
            cp16(aU[buf] + so, Arow + (size_t)row * CDIM + k0 + ldseg * 8);
            cp16(bU[buf] + so, Brow + (size_t)row * CDIM + k0 + ldseg * 8);
        }
        CP_COMMIT();
    };

    float acc[2][8][4];
    #pragma unroll
    for (int mt = 0; mt < 2; mt++)
        #pragma unroll
        for (int nt = 0; nt < 8; nt++)
            #pragma unroll
            for (int j = 0; j < 4; j++) acc[mt][nt][j] = 0.f;

    load_chunk(0, 0);

    int lr = lane & 7, g = lane >> 3;
    int arow[2];
    arow[0] = wm + (g & 1) * 8 + lr;
    arow[1] = wm + 16 + (g & 1) * 8 + lr;
    int akoff = (g >> 1) * 8;
    int brow[4];
    #pragma unroll
    for (int q = 0; q < 4; q++)
        brow[q] = wn + (2 * q + (g >> 1)) * 8 + lr;
    int bkoff = (g & 1) * 8;

    int r4 = lane >> 2, c4 = lane & 3;
    for (int i = 0; i < NCH; i++) {
        if (i + 1 < NCH) { load_chunk((i + 1) * KCH, (i + 1) & 1); CP_WAIT1(); }
        else             { CP_WAIT0(); }
        __syncthreads();
        uint32_t aBase = aU[i & 1];
        uint32_t bBase = bU[i & 1];
        #pragma unroll
        for (int kk = 0; kk < 4; kk++) {
            int kb = kk * 16;
            uint32_t a[2][4];
            #pragma unroll
            for (int mt = 0; mt < 2; mt++)
                ldm4(a[mt], aBase + (uint32_t)(arow[mt] * HP + kb + akoff) * 2);
            uint32_t b[8][2];
            #pragma unroll
            for (int q = 0; q < 4; q++) {
                uint32_t r[4];
                ldm4(r, bBase + (uint32_t)(brow[q] * HP + kb + bkoff) * 2);
                b[2 * q][0] = r[0]; b[2 * q][1] = r[1];
                b[2 * q + 1][0] = r[2]; b[2 * q + 1][1] = r[3];
            }
            #pragma unroll
            for (int mt = 0; mt < 2; mt++)
                #pragma unroll
                for (int nt = 0; nt < 8; nt++)
                    mma16(acc[mt][nt], a[mt], b[nt]);
        }
        __syncthreads();
    }

    int cb = c4 * 2;
    if (MODE == 0) {
        __half* oph = (__half*)outp;
        #pragma unroll
        for (int mt = 0; mt < 2; mt++)
            #pragma unroll
            for (int half = 0; half < 2; half++) {
                int m = m0 + wm + mt * 16 + r4 + half * 8;
                __half* dst = oph + (size_t)m * QKVC + n0 + wn;
                #pragma unroll
                for (int nt = 0; nt < 8; nt++) {
                    int o = n0 + wn + nt * 8 + cb;
                    *(__half2*)(dst + nt * 8 + cb) = __floats2half2_rn(
                        acc[mt][nt][half * 2 + 0] + biasptr[o],
                        acc[mt][nt][half * 2 + 1] + biasptr[o + 1]);
                }
            }
    } else {
        // stage C through smem for coalesced channel-major stores
        float* smf = (float*)smh;       // 128 x 129 floats = 66048 B
        #pragma unroll
        for (int mt = 0; mt < 2; mt++)
            #pragma unroll
            for (int half = 0; half < 2; half++) {
                int ml = wm + mt * 16 + r4 + half * 8;
                #pragma unroll
                for (int nt = 0; nt < 8; nt++) {
                    int ol = wn + nt * 8 + cb;
                    smf[ml * 129 + ol]     = acc[mt][nt][half * 2 + 0];
                    smf[ml * 129 + ol + 1] = acc[mt][nt][half * 2 + 1];
                }
            }
        __syncthreads();
        float* opf = (float*)outp;
        int b = m0 >> 14;
        int ppb = m0 & (HWPIX - 1);
        int obase = tid >> 5;           // 0..7
        int m4 = (tid & 31) * 4;
        #pragma unroll
        for (int it2 = 0; it2 < 16; it2++) {
            int o = obase + it2 * 8;
            float bp = biasptr[n0 + o];
            float4 v;
            v.x = smf[(m4 + 0) * 129 + o] + bp;
            v.y = smf[(m4 + 1) * 129 + o] + bp;
            v.z = smf[(m4 + 2) * 129 + o] + bp;
            v.w = smf[(m4 + 3) * 129 + o] + bp;
            *(float4*)&opf[((size_t)(b * CDIM + n0 + o)) * HWPIX + ppb + m4] = v;
        }
    }
}

// =================================================================
// PDSCA helpers on half tiles (pitch 40 halves per token row)
// =================================================================
__device__ __forceinline__ void ld8h(const __half* base, float* r) {
    union { int4 i; __half2 h[4]; } u;
    u.i = *(const int4*)base;
    float2 f0 = __half22float2(u.h[0]), f1 = __half22float2(u.h[1]);
    float2 f2 = __half22float2(u.h[2]), f3 = __half22float2(u.h[3]);
    r[0] = f0.x; r[1] = f0.y; r[2] = f1.x; r[3] = f1.y;
    r[4] = f2.x; r[5] = f2.y; r[6] = f3.x; r[7] = f3.y;
}

__device__ __forceinline__ void conv33h(
        const __half* xs, const float* __restrict__ dw_w,
        const float* __restrict__ dw_b, int it, float* o8) {
    int c = it >> 3, sy = it & 7;
    float rm[10], rc[10], rp[10];
    #pragma unroll
    for (int i = 0; i < 10; i++) { rm[i] = 0.f; rc[i] = 0.f; rp[i] = 0.f; }
    ld8h(xs + (2 * c + (sy >> 2)) * 40 + (sy & 3) * 8, rc + 1);
    if (sy > 0) {
        int r = sy - 1;
        ld8h(xs + (2 * c + (r >> 2)) * 40 + (r & 3) * 8, rm + 1);
    }
    if (sy < 7) {
        int r = sy + 1;
        ld8h(xs + (2 * c + (r >> 2)) * 40 + (r & 3) * 8, rp + 1);
    }
    const float* wp = dw_w + c * 9;
    float w0 = wp[0], w1 = wp[1], w2 = wp[2];
    float w3 = wp[3], w4 = wp[4], w5 = wp[5];
    float w6 = wp[6], w7 = wp[7], w8 = wp[8];
    float bias = dw_b[c];
    #pragma unroll
    for (int ix = 0; ix < 8; ix++) {
        float s = bias;
        s += w0 * rm[ix] + w1 * rm[ix + 1] + w2 * rm[ix + 2];
        s += w3 * rc[ix] + w4 * rc[ix + 1] + w5 * rc[ix + 2];
        s += w6 * rp[ix] + w7 * rp[ix + 1] + w8 * rp[ix + 2];
        o8[ix] = s;
    }
}

__device__ __forceinline__ void gate_apply_h(
        __half* xs, const float* o8, float cav, int it) {
    int c = it >> 3, sy = it & 7;
    __half* base = xs + (2 * c + (sy >> 2)) * 40 + (sy & 3) * 8;
    float xv[8];
    ld8h(base, xv);
    union { int4 i; __half2 h[4]; } u;
    #pragma unroll
    for (int p = 0; p < 4; p++) {
        float g0 = 1.0f / (1.0f + __expf(-(o8[2 * p] + cav)));
        float g1 = 1.0f / (1.0f + __expf(-(o8[2 * p + 1] + cav)));
        u.h[p] = __floats2half2_rn(xv[2 * p] * g0, xv[2 * p + 1] * g1);
    }
    *(int4*)base = u.i;
}

// =================================================================
// per-(window, head) merged PDSCA(Q,K) + attention — all-fp16 tiles
// qsh/ksh: [64 tok][40 halves]; vsTh: [32 dim][72 tok]; ath(P): [64][72]
// =================================================================
__global__ void __launch_bounds__(128) attn_kernel(
        const float* __restrict__ log_temp,
        const float* __restrict__ pqw,  const float* __restrict__ pqb,
        const float* __restrict__ pqf1w, const float* __restrict__ pqf1b,
        const float* __restrict__ pqf2w, const float* __restrict__ pqf2b,
        const float* __restrict__ pkw,  const float* __restrict__ pkb,
        const float* __restrict__ pkf1w, const float* __restrict__ pkf1b,
        const float* __restrict__ pkf2w, const float* __restrict__ pkf2b) {
    __shared__ __align__(16) __half qsh[NTOK * 40];
    __shared__ __align__(16) __half ksh[NTOK * 40];
    __shared__ __align__(16) __half vsTh[HD * 72];
    __shared__ __align__(16) __half ath[NTOK * 72];
    __shared__ float gapq[32], gapk[32], hidq[8], hidk[8], caq[32], cak[32];

    int bi  = blockIdx.x;
    int win = bi / HEADS;
    int h   = bi - win * HEADS;
    int t   = threadIdx.x;
    int b   = win >> 8, hb = (win >> 4) & 15, wb = win & 15;
    int pbase = b * HWPIX + hb * 8 * WDIM + wb * 8;

    // ---- load q,k raw halves; v transposed ----
    for (int tt = t; tt < 256; tt += 128) {
        int n = tt >> 2, d8 = (tt & 3) * 8;
        int p = pbase + (n >> 3) * WDIM + (n & 7);
        const __half* src = g_qkvh + (size_t)p * QKVC + h * HD + d8;
        int4 qi = *(const int4*)(src);
        int4 ki = *(const int4*)(src + CDIM);
        union { int4 i; __half hh[8]; } uv;
        uv.i = *(const int4*)(src + 2 * CDIM);
        *(int4*)&qsh[n * 40 + d8] = qi;
        *(int4*)&ksh[n * 40 + d8] = ki;
        #pragma unroll
        for (int i = 0; i < 8; i++)
            vsTh[(d8 + i) * 72 + n] = uv.hh[i];
    }
    __syncthreads();

    // ---- merged PDSCA for Q and K ----
    float ocq[2][8], ock[2][8];
    conv33h(qsh, pqw, pqb, t, ocq[0]);
    conv33h(qsh, pqw, pqb, t + 128, ocq[1]);
    conv33h(ksh, pkw, pkb, t, ock[0]);
    conv33h(ksh, pkw, pkb, t + 128, ock[1]);
    if (t < 32) {
        float r0[8], r1[8], s = 0.f;
        #pragma unroll
        for (int i = 0; i < 4; i++) {
            ld8h(qsh + (2 * t) * 40 + i * 8, r0);
            ld8h(qsh + (2 * t + 1) * 40 + i * 8, r1);
            #pragma unroll
            for (int j = 0; j < 8; j++) s += r0[j] + r1[j];
        }
        gapq[t] = s * (1.0f / 64.0f);
    } else if (t >= 64 && t < 96) {
        int c = t - 64;
        float r0[8], r1[8], s = 0.f;
        #pragma unroll
        for (int i = 0; i < 4; i++) {
            ld8h(ksh + (2 * c) * 40 + i * 8, r0);
            ld8h(ksh + (2 * c + 1) * 40 + i * 8, r1);
            #pragma unroll
            for (int j = 0; j < 8; j++) s += r0[j] + r1[j];
        }
        gapk[c] = s * (1.0f / 64.0f);
    }
    __syncthreads();
    if (t < 8) {
        float s = pqf1b[t];
        #pragma unroll
        for (int c = 0; c < 32; c++) s += gapq[c] * pqf1w[t * 32 + c];
        hidq[t] = fmaxf(s, 0.f);
    } else if (t >= 64 && t < 72) {
        int u = t - 64;
        float s = pkf1b[u];
        #pragma unroll
        for (int c = 0; c < 32; c++) s += gapk[c] * pkf1w[u * 32 + c];
        hidk[u] = fmaxf(s, 0.f);
    }
    __syncthreads();
    if (t < 32) {
        float s = pqf2b[t];
        #pragma unroll
        for (int j = 0; j < 8; j++) s += hidq[j] * pqf2w[t * 8 + j];
        caq[t] = s;
    } else if (t >= 64 && t < 96) {
        int c = t - 64;
        float s = pkf2b[c];
        #pragma unroll
        for (int j = 0; j < 8; j++) s += hidk[j] * pkf2w[c * 8 + j];
        cak[c] = s;
    }
    __syncthreads();
    gate_apply_h(qsh, ocq[0], caq[t >> 3], t);
    gate_apply_h(qsh, ocq[1], caq[(t + 128) >> 3], t + 128);
    gate_apply_h(ksh, ock[0], cak[t >> 3], t);
    gate_apply_h(ksh, ock[1], cak[(t + 128) >> 3], t + 128);
    __syncthreads();

    // ---- S = Q K^T via fp16 mma (warp tile 16x64, k=32) ----
    int lane = t & 31, w = t >> 5;
    int r4 = lane >> 2, c4 = lane & 3;
    int m0 = w * 16;
    int lr = lane & 7, g = lane >> 3;
    int arow = m0 + (g & 1) * 8 + lr;
    int akoff = (g >> 1) * 8;
    int bkoff = (g & 1) * 8;
    uint32_t qB = smem_u32(qsh), kB = smem_u32(ksh);
    uint32_t vB = smem_u32(vsTh), pB = smem_u32(ath);

    float sacc[8][4];
    #pragma unroll
    for (int nt = 0; nt < 8; nt++)
        #pragma unroll
        for (int j = 0; j < 4; j++) sacc[nt][j] = 0.f;

    #pragma unroll
    for (int kk = 0; kk < 2; kk++) {
        int kb = kk * 16;
        uint32_t a[4];
        ldm4(a, qB + (uint32_t)(arow * 40 + kb + akoff) * 2);
        #pragma unroll
        for (int q = 0; q < 4; q++) {
            int nrow = (2 * q + (g >> 1)) * 8 + lr;
            uint32_t r[4];
            ldm4(r, kB + (uint32_t)(nrow * 40 + kb + bkoff) * 2);
            mma16(sacc[2 * q], a, r);
            mma16(sacc[2 * q + 1], a, r + 2);
        }
    }

    // ---- bias + temp + softmax ----
    float temp = __expf(log_temp[0]);
    const float* brow2 = g_bias + h * 225;
    int r_lo = m0 + r4, r_hi = r_lo + 8;
    int ylo = r_lo >> 3, xlo = r_lo & 7;
    int yhi = r_hi >> 3, xhi = r_hi & 7;

    float mlo = -1e30f, mhi = -1e30f;
    #pragma unroll
    for (int nt = 0; nt < 8; nt++)
        #pragma unroll
        for (int j = 0; j < 2; j++) {
            int col = nt * 8 + 2 * c4 + j;
            int cy = col >> 3, cx = col & 7;
            float blo = brow2[(ylo - cy + 7) * 15 + (xlo - cx + 7)];
            float bhi = brow2[(yhi - cy + 7) * 15 + (xhi - cx + 7)];
            sacc[nt][j]     = sacc[nt][j] * temp + blo;
            sacc[nt][2 + j] = sacc[nt][2 + j] * temp + bhi;
            mlo = fmaxf(mlo, sacc[nt][j]);
            mhi = fmaxf(mhi, sacc[nt][2 + j]);
        }
    mlo = fmaxf(mlo, __shfl_xor_sync(0xffffffffu, mlo, 1));
    mlo = fmaxf(mlo, __shfl_xor_sync(0xffffffffu, mlo, 2));
    mhi = fmaxf(mhi, __shfl_xor_sync(0xffffffffu, mhi, 1));
    mhi = fmaxf(mhi, __shfl_xor_sync(0xffffffffu, mhi, 2));

    float slo = 0.f, shi = 0.f;
    #pragma unroll
    for (int nt = 0; nt < 8; nt++)
        #pragma unroll
        for (int j = 0; j < 2; j++) {
            float e0 = __expf(sacc[nt][j] - mlo);
            float e1 = __expf(sacc[nt][2 + j] - mhi);
            sacc[nt][j] = e0; sacc[nt][2 + j] = e1;
            slo += e0; shi += e1;
        }
    slo += __shfl_xor_sync(0xffffffffu, slo, 1);
    slo += __shfl_xor_sync(0xffffffffu, slo, 2);
    shi += __shfl_xor_sync(0xffffffffu, shi, 1);
    shi += __shfl_xor_sync(0xffffffffu, shi, 2);
    float ilo = 1.0f / slo, ihi = 1.0f / shi;

    // ---- stage P (fp16) ----
    #pragma unroll
    for (int nt = 0; nt < 8; nt++) {
        int col = nt * 8 + 2 * c4;
        *(__half2*)&ath[r_lo * 72 + col] =
            __floats2half2_rn(sacc[nt][0] * ilo, sacc[nt][1] * ilo);
        *(__half2*)&ath[r_hi * 72 + col] =
            __floats2half2_rn(sacc[nt][2] * ihi, sacc[nt][3] * ihi);
    }
    __syncwarp();

    // ---- O = P V via fp16 mma (warp tile 16x32, k=64) ----
    float oacc[4][4];
    #pragma unroll
    for (int nt = 0; nt < 4; nt++)
        #pragma unroll
        for (int j = 0; j < 4; j++) oacc[nt][j] = 0.f;

    #pragma unroll
    for (int kk = 0; kk < 4; kk++) {
        int kb = kk * 16;
        uint32_t a[4];
        ldm4(a, pB + (uint32_t)(arow * 72 + kb + akoff) * 2);
        #pragma unroll
        for (int q = 0; q < 2; q++) {
            int nrow = (2 * q + (g >> 1)) * 8 + lr;
            uint32_t r[4];
            ldm4(r, vB + (uint32_t)(nrow * 72 + kb + bkoff) * 2);
            mma16(oacc[2 * q], a, r);
            mma16(oacc[2 * q + 1], a, r + 2);
        }
    }

    // ---- store O ----
    #pragma unroll
    for (int half = 0; half < 2; half++) {
        int row = (half == 0) ? r_lo : r_hi;
        int p = pbase + (row >> 3) * WDIM + (row & 7);
        __half2* dst = (__half2*)(g_aoh + (size_t)p * CDIM + h * HD);
        #pragma unroll
        for (int nt = 0; nt < 4; nt++)
            dst[(nt * 8 + 2 * c4) >> 1] =
                __floats2half2_rn(oacc[nt][half * 2 + 0], oacc[nt][half * 2 + 1]);
    }
}

// =================================================================
// launch
// =================================================================
extern "C" void kernel_launch(void* const* d_in, const int* in_sizes, int n_in,
                              void* d_out, int out_size) {
    const float* x        = (const float*)d_in[0];
    const float* w_qk     = (const float*)d_in[1];
    const float* b_qk     = (const float*)d_in[2];
    const float* w_v      = (const float*)d_in[3];
    const float* b_v      = (const float*)d_in[4];
    const float* log_temp = (const float*)d_in[5];
    const float* pq_dw_w  = (const float*)d_in[6];
    const float* pq_dw_b  = (const float*)d_in[7];
    const float* pq_f1w   = (const float*)d_in[8];
    const float* pq_f1b   = (const float*)d_in[9];
    const float* pq_f2w   = (const float*)d_in[10];
    const float* pq_f2b   = (const float*)d_in[11];
    const float* pk_dw_w  = (const float*)d_in[12];
    const float* pk_dw_b  = (const float*)d_in[13];
    const float* pk_f1w   = (const float*)d_in[14];
    const float* pk_f1b   = (const float*)d_in[15];
    const float* pk_f2w   = (const float*)d_in[16];
    const float* pk_f2b   = (const float*)d_in[17];
    const float* pos_w    = (const float*)d_in[18];
    const float* pos_sc   = (const float*)d_in[20];
    const float* meta_w1  = (const float*)d_in[21];
    const float* meta_b1  = (const float*)d_in[22];
    const float* meta_w2  = (const float*)d_in[23];
    const float* meta_b2  = (const float*)d_in[24];
    const float* w_po     = (const float*)d_in[25];
    const float* w_proj   = (const float*)d_in[26];
    const float* b_proj   = (const float*)d_in[27];
    float* out = (float*)d_out;

    cudaFuncSetAttribute(gemm_mma<0>, cudaFuncAttributeMaxDynamicSharedMemorySize, GEMM_SMEM);
    cudaFuncSetAttribute(gemm_mma<1>, cudaFuncAttributeMaxDynamicSharedMemorySize, GEMM_SMEM);

    prep_kernel<<<NB_PREP, 256>>>(x, w_qk, b_qk, w_v, b_v, w_proj, w_po,
                                  pos_w, pos_sc, meta_w1, meta_b1, meta_w2, meta_b2);

    {
        const __half* A; cudaGetSymbolAddress((void**)&A, g_xTh);
        const __half* Bp; cudaGetSymbolAddress((void**)&Bp, g_wbh);
        const float* bb; cudaGetSymbolAddress((void**)&bb, g_bqkv);
        void* op; cudaGetSymbolAddress(&op, g_qkvh);
        gemm_mma<0><<<dim3(QKVC / 128, NPIX / 128), 256, GEMM_SMEM>>>(A, Bp, bb, op);
    }

    attn_kernel<<<NWIN * HEADS, 128>>>(log_temp,
        pq_dw_w, pq_dw_b, pq_f1w, pq_f1b, pq_f2w, pq_f2b,
        pk_dw_w, pk_dw_b, pk_f1w, pk_f1b, pk_f2w, pk_f2b);

    {
        const __half* A; cudaGetSymbolAddress((void**)&A, g_aoh);
        const __half* Bp; cudaGetSymbolAddress((void**)&Bp, g_Wch);
        gemm_mma<1><<<dim3(CDIM / 128, NPIX / 128), 256, GEMM_SMEM>>>(A, Bp, b_proj, (void*)out);
    }
}

// round 12
// speedup vs baseline: 5.7544x; 1.0638x over previous
#include <cuda_runtime.h>
#include <cuda_fp16.h>
#include <cstdint>
#include <math.h>

// ---------------- problem constants ----------------
#define BATCH 4
#define CDIM  384
#define HDIM  128
#define WDIM  128
#define HWPIX 16384
#define NPIX  65536
#define HEADS 12
#define HD    32
#define WS    8
#define NTOK  64
#define NWIN  1024
#define QKVC  1152

// ---------------- device scratch ----------------
__device__ __half g_qkvh[(size_t)NPIX * QKVC];
__device__ __half g_aoh[(size_t)NPIX * CDIM];
__device__ __half g_xTh[(size_t)NPIX * CDIM];
__device__ __half g_wbh[QKVC * CDIM];
__device__ float  g_bqkv[QKVC];
__device__ float  g_bias[HEADS * 225];
__device__ __half g_Wch[CDIM * CDIM];

// ---------------- helpers ----------------
__device__ __forceinline__ uint32_t smem_u32(const void* p) {
    uint32_t a;
    asm("{ .reg .u64 t; cvta.to.shared.u64 t, %1; cvt.u32.u64 %0, t; }" : "=r"(a) : "l"(p));
    return a;
}
__device__ __forceinline__ void cp16(uint32_t saddr, const void* g) {
    asm volatile("cp.async.cg.shared.global [%0], [%1], 16;" :: "r"(saddr), "l"(g));
}
#define CP_COMMIT() asm volatile("cp.async.commit_group;" ::: "memory")
#define CP_WAIT0()  asm volatile("cp.async.wait_group 0;" ::: "memory")
#define CP_WAIT1()  asm volatile("cp.async.wait_group 1;" ::: "memory")

__device__ __forceinline__ void ldm4(uint32_t* r, uint32_t addr) {
    asm volatile("ldmatrix.sync.aligned.m8n8.x4.shared.b16 {%0,%1,%2,%3}, [%4];"
        : "=r"(r[0]), "=r"(r[1]), "=r"(r[2]), "=r"(r[3]) : "r"(addr));
}

__device__ __forceinline__ void mma16(float* c, const uint32_t* a, const uint32_t* b) {
    asm volatile(
        "mma.sync.aligned.m16n8k16.row.col.f32.f16.f16.f32 "
        "{%0,%1,%2,%3}, {%4,%5,%6,%7}, {%8,%9}, {%0,%1,%2,%3};"
        : "+f"(c[0]), "+f"(c[1]), "+f"(c[2]), "+f"(c[3])
        : "r"(a[0]), "r"(a[1]), "r"(a[2]), "r"(a[3]),
          "r"(b[0]), "r"(b[1]));
}

// =================================================================
// unified prep kernel: xpose | wprep | wc | bias, 256 threads
// =================================================================
#define NB_XPOSE (512 * 12 * 4)
#define NB_WPREP ((QKVC * CDIM) / 256)
#define NB_WC    ((CDIM * CDIM) / 256)
#define NB_BIAS  225
#define NB_PREP  (NB_XPOSE + NB_WPREP + NB_WC + NB_BIAS)

__global__ void __launch_bounds__(256) prep_kernel(
        const float* __restrict__ x,
        const float* __restrict__ w_qk, const float* __restrict__ b_qk,
        const float* __restrict__ w_v,  const float* __restrict__ b_v,
        const float* __restrict__ w_proj, const float* __restrict__ w_po,
        const float* __restrict__ pcw, const float* __restrict__ psc,
        const float* __restrict__ mw1, const float* __restrict__ mb1,
        const float* __restrict__ mw2, const float* __restrict__ mb2) {
    __shared__ __align__(16) float tile[32][33];
    __shared__ __align__(16) float rel[CDIM];
    __shared__ __align__(16) float hid[128];
    __shared__ float part[256];
    int blk = blockIdx.x;
    int t = threadIdx.x;

    if (blk < NB_XPOSE) {
        int bx = blk & 511, by = (blk >> 9) % 12, bz = blk / (512 * 12);
        int tx = t & 31, ty = t >> 5;
        const float* src = x + ((size_t)(bz * CDIM + by * 32)) * HWPIX + bx * 32;
        #pragma unroll
        for (int i = 0; i < 32; i += 8)
            tile[ty + i][tx] = src[(size_t)(ty + i) * HWPIX + tx];
        __syncthreads();
        __half* dst = g_xTh + ((size_t)(bz * HWPIX + bx * 32)) * CDIM + by * 32;
        #pragma unroll
        for (int i = 0; i < 32; i += 8)
            dst[(size_t)(ty + i) * CDIM + tx] = __float2half_rn(tile[tx][ty + i]);
        return;
    }
    blk -= NB_XPOSE;
    if (blk < NB_WPREP) {
        int i = blk * 256 + t;
        float v = (i < 2 * CDIM * CDIM) ? w_qk[i] : w_v[i - 2 * CDIM * CDIM];
        g_wbh[i] = __float2half_rn(v);
        if (i < QKVC)
            g_bqkv[i] = (i < 2 * CDIM) ? b_qk[i] : b_v[i - 2 * CDIM];
        return;
    }
    blk -= NB_WPREP;
    if (blk < NB_WC) {
        int idx = blk * 256 + t;
        int o = idx / CDIM, c = idx - o * CDIM;
        const float* pr = w_proj + o * CDIM;
        float a0 = 0.f, a1 = 0.f, a2 = 0.f, a3 = 0.f;
        for (int k = 0; k < CDIM; k += 4) {
            a0 += pr[k] * w_po[k * CDIM + c];
            a1 += pr[k + 1] * w_po[(k + 1) * CDIM + c];
            a2 += pr[k + 2] * w_po[(k + 2) * CDIM + c];
            a3 += pr[k + 3] * w_po[(k + 3) * CDIM + c];
        }
        g_Wch[o * CDIM + c] = __float2half_rn((a0 + a1) + (a2 + a3));
        return;
    }
    blk -= NB_WC;
    {
        int idx = blk;
        float dx = (float)((idx % 15) - 7) * (2.0f / 7.0f);
        float dy = (float)((idx / 15) - 7) * (2.0f / 7.0f);
        int u = t & 127, hv2 = t >> 7;
        float sc = psc[0];
        for (int c = t; c < CDIM; c += 256)
            rel[c] = sc * (pcw[2 * c] * dx + pcw[2 * c + 1] * dy);
        __syncthreads();
        {
            float a0 = 0.f, a1 = 0.f, a2 = 0.f, a3 = 0.f;
            const float4* w = (const float4*)(mw1 + u * CDIM + hv2 * 192);
            const float4* r = (const float4*)(rel + hv2 * 192);
            #pragma unroll 4
            for (int c = 0; c < 48; c++) {
                float4 wv = w[c], rv = r[c];
                a0 += wv.x * rv.x; a1 += wv.y * rv.y;
                a2 += wv.z * rv.z; a3 += wv.w * rv.w;
            }
            part[t] = (a0 + a1) + (a2 + a3);
        }
        __syncthreads();
        if (t < 128) {
            float s = mb1[t] + part[t] + part[t + 128];
            hid[t] = 0.5f * s * (1.0f + erff(s * 0.70710678118654752f));
        }
        __syncthreads();
        if (t < HEADS) {
            float a0 = 0.f, a1 = 0.f, a2 = 0.f, a3 = 0.f;
            const float4* w2 = (const float4*)(mw2 + t * 128);
            const float4* hh = (const float4*)hid;
            #pragma unroll 4
            for (int j = 0; j < 32; j++) {
                float4 wv = w2[j], hvv = hh[j];
                a0 += wv.x * hvv.x; a1 += wv.y * hvv.y;
                a2 += wv.z * hvv.z; a3 += wv.w * hvv.w;
            }
            g_bias[t * 225 + idx] = mb2[t] + (a0 + a1) + (a2 + a3);
        }
    }
}

// =================================================================
// fp16 mma.sync GEMM with ldmatrix (round-10 epilogues)
// =================================================================
#define HP   72
#define KCH  64
#define NCH  6
#define GEMM_SMEM (4 * 128 * HP * 2)

template <int MODE>
__global__ void __launch_bounds__(256) gemm_mma(
        const __half* __restrict__ Aptr, const __half* __restrict__ Bptr,
        const float* __restrict__ biasptr, void* __restrict__ outp) {
    extern __shared__ __align__(16) __half smh[];
    __half* AsB[2] = { smh, smh + 128 * HP };
    __half* BsB[2] = { smh + 2 * 128 * HP, smh + 3 * 128 * HP };

    int tid = threadIdx.x;
    int n0 = blockIdx.x * 128;
    int m0 = blockIdx.y * 128;
    int lane = tid & 31, wid = tid >> 5;
    int wm = (wid & 3) * 32;
    int wn = (wid >> 2) * 64;

    const __half* Arow = Aptr + (size_t)m0 * CDIM;
    const __half* Brow = Bptr + (size_t)n0 * CDIM;
    uint32_t aU[2] = { smem_u32(AsB[0]), smem_u32(AsB[1]) };
    uint32_t bU[2] = { smem_u32(BsB[0]), smem_u32(BsB[1]) };

    int ldrow = tid >> 3, ldseg = tid & 7;
    auto load_chunk = [&](int k0, int buf) {
        #pragma unroll
        for (int i = 0; i < 4; i++) {
            int row = ldrow + i * 32;
            uint32_t so = (uint32_t)(row * HP + ldseg * 8) * 2;
            cp16(aU[buf] + so, Arow + (size_t)row * CDIM + k0 + ldseg * 8);
            cp16(bU[buf] + so, Brow + (size_t)row * CDIM + k0 + ldseg * 8);
        }
        CP_COMMIT();
    };

    float acc[2][8][4];
    #pragma unroll
    for (int mt = 0; mt < 2; mt++)
        #pragma unroll
        for (int nt = 0; nt < 8; nt++)
            #pragma unroll
            for (int j = 0; j < 4; j++) acc[mt][nt][j] = 0.f;

    load_chunk(0, 0);

    int lr = lane & 7, g = lane >> 3;
    int arow[2];
    arow[0] = wm + (g & 1) * 8 + lr;
    arow[1] = wm + 16 + (g & 1) * 8 + lr;
    int akoff = (g >> 1) * 8;
    int brow[4];
    #pragma unroll
    for (int q = 0; q < 4; q++)
        brow[q] = wn + (2 * q + (g >> 1)) * 8 + lr;
    int bkoff = (g & 1) * 8;

    int r4 = lane >> 2, c4 = lane & 3;
    for (int i = 0; i < NCH; i++) {
        if (i + 1 < NCH) { load_chunk((i + 1) * KCH, (i + 1) & 1); CP_WAIT1(); }
        else             { CP_WAIT0(); }
        __syncthreads();
        uint32_t aBase = aU[i & 1];
        uint32_t bBase = bU[i & 1];
        #pragma unroll
        for (int kk = 0; kk < 4; kk++) {
            int kb = kk * 16;
            uint32_t a[2][4];
            #pragma unroll
            for (int mt = 0; mt < 2; mt++)
                ldm4(a[mt], aBase + (uint32_t)(arow[mt] * HP + kb + akoff) * 2);
            uint32_t b[8][2];
            #pragma unroll
            for (int q = 0; q < 4; q++) {
                uint32_t r[4];
                ldm4(r, bBase + (uint32_t)(brow[q] * HP + kb + bkoff) * 2);
                b[2 * q][0] = r[0]; b[2 * q][1] = r[1];
                b[2 * q + 1][0] = r[2]; b[2 * q + 1][1] = r[3];
            }
            #pragma unroll
            for (int mt = 0; mt < 2; mt++)
                #pragma unroll
                for (int nt = 0; nt < 8; nt++)
                    mma16(acc[mt][nt], a[mt], b[nt]);
        }
        __syncthreads();
    }

    int cb = c4 * 2;
    if (MODE == 0) {
        __half* oph = (__half*)outp;
        #pragma unroll
        for (int mt = 0; mt < 2; mt++)
            #pragma unroll
            for (int half = 0; half < 2; half++) {
                int m = m0 + wm + mt * 16 + r4 + half * 8;
                __half* dst = oph + (size_t)m * QKVC + n0 + wn;
                #pragma unroll
                for (int nt = 0; nt < 8; nt++) {
                    int o = n0 + wn + nt * 8 + cb;
                    *(__half2*)(dst + nt * 8 + cb) = __floats2half2_rn(
                        acc[mt][nt][half * 2 + 0] + biasptr[o],
                        acc[mt][nt][half * 2 + 1] + biasptr[o + 1]);
                }
            }
    } else {
        float* opf = (float*)outp;
        int b = m0 >> 14;
        int ppb = m0 & (HWPIX - 1);
        #pragma unroll
        for (int mt = 0; mt < 2; mt++)
            #pragma unroll
            for (int half = 0; half < 2; half++) {
                int pp = ppb + wm + mt * 16 + r4 + half * 8;
                #pragma unroll
                for (int nt = 0; nt < 8; nt++)
                    #pragma unroll
                    for (int j = 0; j < 2; j++) {
                        int o = n0 + wn + nt * 8 + cb + j;
                        opf[((size_t)(b * CDIM + o)) * HWPIX + pp] =
                            acc[mt][nt][half * 2 + j] + biasptr[o];
                    }
            }
    }
}

// =================================================================
// PDSCA helpers on half tiles (pitch 40 halves per token row)
// =================================================================
__device__ __forceinline__ void ld8h(const __half* base, float* r) {
    union { int4 i; __half2 h[4]; } u;
    u.i = *(const int4*)base;
    float2 f0 = __half22float2(u.h[0]), f1 = __half22float2(u.h[1]);
    float2 f2 = __half22float2(u.h[2]), f3 = __half22float2(u.h[3]);
    r[0] = f0.x; r[1] = f0.y; r[2] = f1.x; r[3] = f1.y;
    r[4] = f2.x; r[5] = f2.y; r[6] = f3.x; r[7] = f3.y;
}

__device__ __forceinline__ void conv33h(
        const __half* xs, const float* __restrict__ dw_w,
        const float* __restrict__ dw_b, int it, float* o8) {
    int c = it >> 3, sy = it & 7;
    float rm[10], rc[10], rp[10];
    #pragma unroll
    for (int i = 0; i < 10; i++) { rm[i] = 0.f; rc[i] = 0.f; rp[i] = 0.f; }
    ld8h(xs + (2 * c + (sy >> 2)) * 40 + (sy & 3) * 8, rc + 1);
    if (sy > 0) {
        int r = sy - 1;
        ld8h(xs + (2 * c + (r >> 2)) * 40 + (r & 3) * 8, rm + 1);
    }
    if (sy < 7) {
        int r = sy + 1;
        ld8h(xs + (2 * c + (r >> 2)) * 40 + (r & 3) * 8, rp + 1);
    }
    const float* wp = dw_w + c * 9;
    float w0 = wp[0], w1 = wp[1], w2 = wp[2];
    float w3 = wp[3], w4 = wp[4], w5 = wp[5];
    float w6 = wp[6], w7 = wp[7], w8 = wp[8];
    float bias = dw_b[c];
    #pragma unroll
    for (int ix = 0; ix < 8; ix++) {
        float s = bias;
        s += w0 * rm[ix] + w1 * rm[ix + 1] + w2 * rm[ix + 2];
        s += w3 * rc[ix] + w4 * rc[ix + 1] + w5 * rc[ix + 2];
        s += w6 * rp[ix] + w7 * rp[ix + 1] + w8 * rp[ix + 2];
        o8[ix] = s;
    }
}

__device__ __forceinline__ void gate_apply_h(
        __half* xs, const float* o8, float cav, int it) {
    int c = it >> 3, sy = it & 7;
    __half* base = xs + (2 * c + (sy >> 2)) * 40 + (sy & 3) * 8;
    float xv[8];
    ld8h(base, xv);
    union { int4 i; __half2 h[4]; } u;
    #pragma unroll
    for (int p = 0; p < 4; p++) {
        float g0 = 1.0f / (1.0f + __expf(-(o8[2 * p] + cav)));
        float g1 = 1.0f / (1.0f + __expf(-(o8[2 * p + 1] + cav)));
        u.h[p] = __floats2half2_rn(xv[2 * p] * g0, xv[2 * p + 1] * g1);
    }
    *(int4*)base = u.i;
}

// =================================================================
// per-(window, head) merged PDSCA(Q,K) + attention — all-fp16 tiles
// =================================================================
__global__ void __launch_bounds__(128) attn_kernel(
        const float* __restrict__ log_temp,
        const float* __restrict__ pqw,  const float* __restrict__ pqb,
        const float* __restrict__ pqf1w, const float* __restrict__ pqf1b,
        const float* __restrict__ pqf2w, const float* __restrict__ pqf2b,
        const float* __restrict__ pkw,  const float* __restrict__ pkb,
        const float* __restrict__ pkf1w, const float* __restrict__ pkf1b,
        const float* __restrict__ pkf2w, const float* __restrict__ pkf2b) {
    __shared__ __align__(16) __half qsh[NTOK * 40];
    __shared__ __align__(16) __half ksh[NTOK * 40];
    __shared__ __align__(16) __half vsTh[HD * 72];
    __shared__ __align__(16) __half ath[NTOK * 72];
    __shared__ float gapq[32], gapk[32], hidq[8], hidk[8], caq[32], cak[32];

    int bi  = blockIdx.x;
    int win = bi / HEADS;
    int h   = bi - win * HEADS;
    int t   = threadIdx.x;
    int b   = win >> 8, hb = (win >> 4) & 15, wb = win & 15;
    int pbase = b * HWPIX + hb * 8 * WDIM + wb * 8;

    for (int tt = t; tt < 256; tt += 128) {
        int n = tt >> 2, d8 = (tt & 3) * 8;
        int p = pbase + (n >> 3) * WDIM + (n & 7);
        const __half* src = g_qkvh + (size_t)p * QKVC + h * HD + d8;
        int4 qi = *(const int4*)(src);
        int4 ki = *(const int4*)(src + CDIM);
        union { int4 i; __half hh[8]; } uv;
        uv.i = *(const int4*)(src + 2 * CDIM);
        *(int4*)&qsh[n * 40 + d8] = qi;
        *(int4*)&ksh[n * 40 + d8] = ki;
        #pragma unroll
        for (int i = 0; i < 8; i++)
            vsTh[(d8 + i) * 72 + n] = uv.hh[i];
    }
    __syncthreads();

    float ocq[2][8], ock[2][8];
    conv33h(qsh, pqw, pqb, t, ocq[0]);
    conv33h(qsh, pqw, pqb, t + 128, ocq[1]);
    conv33h(ksh, pkw, pkb, t, ock[0]);
    conv33h(ksh, pkw, pkb, t + 128, ock[1]);
    if (t < 32) {
        float r0[8], r1[8], s = 0.f;
        #pragma unroll
        for (int i = 0; i < 4; i++) {
            ld8h(qsh + (2 * t) * 40 + i * 8, r0);
            ld8h(qsh + (2 * t + 1) * 40 + i * 8, r1);
            #pragma unroll
            for (int j = 0; j < 8; j++) s += r0[j] + r1[j];
        }
        gapq[t] = s * (1.0f / 64.0f);
    } else if (t >= 64 && t < 96) {
        int c = t - 64;
        float r0[8], r1[8], s = 0.f;
        #pragma unroll
        for (int i = 0; i < 4; i++) {
            ld8h(ksh + (2 * c) * 40 + i * 8, r0);
            ld8h(ksh + (2 * c + 1) * 40 + i * 8, r1);
            #pragma unroll
            for (int j = 0; j < 8; j++) s += r0[j] + r1[j];
        }
        gapk[c] = s * (1.0f / 64.0f);
    }
    __syncthreads();
    if (t < 8) {
        float s = pqf1b[t];
        #pragma unroll
        for (int c = 0; c < 32; c++) s += gapq[c] * pqf1w[t * 32 + c];
        hidq[t] = fmaxf(s, 0.f);
    } else if (t >= 64 && t < 72) {
        int u = t - 64;
        float s = pkf1b[u];
        #pragma unroll
        for (int c = 0; c < 32; c++) s += gapk[c] * pkf1w[u * 32 + c];
        hidk[u] = fmaxf(s, 0.f);
    }
    __syncthreads();
    if (t < 32) {
        float s = pqf2b[t];
        #pragma unroll
        for (int j = 0; j < 8; j++) s += hidq[j] * pqf2w[t * 8 + j];
        caq[t] = s;
    } else if (t >= 64 && t < 96) {
        int c = t - 64;
        float s = pkf2b[c];
        #pragma unroll
        for (int j = 0; j < 8; j++) s += hidk[j] * pkf2w[c * 8 + j];
        cak[c] = s;
    }
    __syncthreads();
    gate_apply_h(qsh, ocq[0], caq[t >> 3], t);
    gate_apply_h(qsh, ocq[1], caq[(t + 128) >> 3], t + 128);
    gate_apply_h(ksh, ock[0], cak[t >> 3], t);
    gate_apply_h(ksh, ock[1], cak[(t + 128) >> 3], t + 128);
    __syncthreads();

    int lane = t & 31, w = t >> 5;
    int r4 = lane >> 2, c4 = lane & 3;
    int m0 = w * 16;
    int lr = lane & 7, g = lane >> 3;
    int arow = m0 + (g & 1) * 8 + lr;
    int akoff = (g >> 1) * 8;
    int bkoff = (g & 1) * 8;
    uint32_t qB = smem_u32(qsh), kB = smem_u32(ksh);
    uint32_t vB = smem_u32(vsTh), pB = smem_u32(ath);

    float sacc[8][4];
    #pragma unroll
    for (int nt = 0; nt < 8; nt++)
        #pragma unroll
        for (int j = 0; j < 4; j++) sacc[nt][j] = 0.f;

    #pragma unroll
    for (int kk = 0; kk < 2; kk++) {
        int kb = kk * 16;
        uint32_t a[4];
        ldm4(a, qB + (uint32_t)(arow * 40 + kb + akoff) * 2);
        #pragma unroll
        for (int q = 0; q < 4; q++) {
            int nrow = (2 * q + (g >> 1)) * 8 + lr;
            uint32_t r[4];
            ldm4(r, kB + (uint32_t)(nrow * 40 + kb + bkoff) * 2);
            mma16(sacc[2 * q], a, r);
            mma16(sacc[2 * q + 1], a, r + 2);
        }
    }

    float temp = __expf(log_temp[0]);
    const float* brow2 = g_bias + h * 225;
    int r_lo = m0 + r4, r_hi = r_lo + 8;
    int ylo = r_lo >> 3, xlo = r_lo & 7;
    int yhi = r_hi >> 3, xhi = r_hi & 7;

    float mlo = -1e30f, mhi = -1e30f;
    #pragma unroll
    for (int nt = 0; nt < 8; nt++)
        #pragma unroll
        for (int j = 0; j < 2; j++) {
            int col = nt * 8 + 2 * c4 + j;
            int cy = col >> 3, cx = col & 7;
            float blo = brow2[(ylo - cy + 7) * 15 + (xlo - cx + 7)];
            float bhi = brow2[(yhi - cy + 7) * 15 + (xhi - cx + 7)];
            sacc[nt][j]     = sacc[nt][j] * temp + blo;
            sacc[nt][2 + j] = sacc[nt][2 + j] * temp + bhi;
            mlo = fmaxf(mlo, sacc[nt][j]);
            mhi = fmaxf(mhi, sacc[nt][2 + j]);
        }
    mlo = fmaxf(mlo, __shfl_xor_sync(0xffffffffu, mlo, 1));
    mlo = fmaxf(mlo, __shfl_xor_sync(0xffffffffu, mlo, 2));
    mhi = fmaxf(mhi, __shfl_xor_sync(0xffffffffu, mhi, 1));
    mhi = fmaxf(mhi, __shfl_xor_sync(0xffffffffu, mhi, 2));

    float slo = 0.f, shi = 0.f;
    #pragma unroll
    for (int nt = 0; nt < 8; nt++)
        #pragma unroll
        for (int j = 0; j < 2; j++) {
            float e0 = __expf(sacc[nt][j] - mlo);
            float e1 = __expf(sacc[nt][2 + j] - mhi);
            sacc[nt][j] = e0; sacc[nt][2 + j] = e1;
            slo += e0; shi += e1;
        }
    slo += __shfl_xor_sync(0xffffffffu, slo, 1);
    slo += __shfl_xor_sync(0xffffffffu, slo, 2);
    shi += __shfl_xor_sync(0xffffffffu, shi, 1);
    shi += __shfl_xor_sync(0xffffffffu, shi, 2);
    float ilo = 1.0f / slo, ihi = 1.0f / shi;

    #pragma unroll
    for (int nt = 0; nt < 8; nt++) {
        int col = nt * 8 + 2 * c4;
        *(__half2*)&ath[r_lo * 72 + col] =
            __floats2half2_rn(sacc[nt][0] * ilo, sacc[nt][1] * ilo);
        *(__half2*)&ath[r_hi * 72 + col] =
            __floats2half2_rn(sacc[nt][2] * ihi, sacc[nt][3] * ihi);
    }
    __syncwarp();

    float oacc[4][4];
    #pragma unroll
    for (int nt = 0; nt < 4; nt++)
        #pragma unroll
        for (int j = 0; j < 4; j++) oacc[nt][j] = 0.f;

    #pragma unroll
    for (int kk = 0; kk < 4; kk++) {
        int kb = kk * 16;
        uint32_t a[4];
        ldm4(a, pB + (uint32_t)(arow * 72 + kb + akoff) * 2);
        #pragma unroll
        for (int q = 0; q < 2; q++) {
            int nrow = (2 * q + (g >> 1)) * 8 + lr;
            uint32_t r[4];
            ldm4(r, vB + (uint32_t)(nrow * 72 + kb + bkoff) * 2);
            mma16(oacc[2 * q], a, r);
            mma16(oacc[2 * q + 1], a, r + 2);
        }
    }

    #pragma unroll
    for (int half = 0; half < 2; half++) {
        int row = (half == 0) ? r_lo : r_hi;
        int p = pbase + (row >> 3) * WDIM + (row & 7);
        __half2* dst = (__half2*)(g_aoh + (size_t)p * CDIM + h * HD);
        #pragma unroll
        for (int nt = 0; nt < 4; nt++)
            dst[(nt * 8 + 2 * c4) >> 1] =
                __floats2half2_rn(oacc[nt][half * 2 + 0], oacc[nt][half * 2 + 1]);
    }
}

// =================================================================
// launch
// =================================================================
extern "C" void kernel_launch(void* const* d_in, const int* in_sizes, int n_in,
                              void* d_out, int out_size) {
    const float* x        = (const float*)d_in[0];
    const float* w_qk     = (const float*)d_in[1];
    const float* b_qk     = (const float*)d_in[2];
    const float* w_v      = (const float*)d_in[3];
    const float* b_v      = (const float*)d_in[4];
    const float* log_temp = (const float*)d_in[5];
    const float* pq_dw_w  = (const float*)d_in[6];
    const float* pq_dw_b  = (const float*)d_in[7];
    const float* pq_f1w   = (const float*)d_in[8];
    const float* pq_f1b   = (const float*)d_in[9];
    const float* pq_f2w   = (const float*)d_in[10];
    const float* pq_f2b   = (const float*)d_in[11];
    const float* pk_dw_w  = (const float*)d_in[12];
    const float* pk_dw_b  = (const float*)d_in[13];
    const float* pk_f1w   = (const float*)d_in[14];
    const float* pk_f1b   = (const float*)d_in[15];
    const float* pk_f2w   = (const float*)d_in[16];
    const float* pk_f2b   = (const float*)d_in[17];
    const float* pos_w    = (const float*)d_in[18];
    const float* pos_sc   = (const float*)d_in[20];
    const float* meta_w1  = (const float*)d_in[21];
    const float* meta_b1  = (const float*)d_in[22];
    const float* meta_w2  = (const float*)d_in[23];
    const float* meta_b2  = (const float*)d_in[24];
    const float* w_po     = (const float*)d_in[25];
    const float* w_proj   = (const float*)d_in[26];
    const float* b_proj   = (const float*)d_in[27];
    float* out = (float*)d_out;

    cudaFuncSetAttribute(gemm_mma<0>, cudaFuncAttributeMaxDynamicSharedMemorySize, GEMM_SMEM);
    cudaFuncSetAttribute(gemm_mma<1>, cudaFuncAttributeMaxDynamicSharedMemorySize, GEMM_SMEM);

    prep_kernel<<<NB_PREP, 256>>>(x, w_qk, b_qk, w_v, b_v, w_proj, w_po,
                                  pos_w, pos_sc, meta_w1, meta_b1, meta_w2, meta_b2);

    {
        const __half* A; cudaGetSymbolAddress((void**)&A, g_xTh);
        const __half* Bp; cudaGetSymbolAddress((void**)&Bp, g_wbh);
        const float* bb; cudaGetSymbolAddress((void**)&bb, g_bqkv);
        void* op; cudaGetSymbolAddress(&op, g_qkvh);
        gemm_mma<0><<<dim3(QKVC / 128, NPIX / 128), 256, GEMM_SMEM>>>(A, Bp, bb, op);
    }

    attn_kernel<<<NWIN * HEADS, 128>>>(log_temp,
        pq_dw_w, pq_dw_b, pq_f1w, pq_f1b, pq_f2w, pq_f2b,
        pk_dw_w, pk_dw_b, pk_f1w, pk_f1b, pk_f2w, pk_f2b);

    {
        const __half* A; cudaGetSymbolAddress((void**)&A, g_aoh);
        const __half* Bp; cudaGetSymbolAddress((void**)&Bp, g_Wch);
        gemm_mma<1><<<dim3(CDIM / 128, NPIX / 128), 256, GEMM_SMEM>>>(A, Bp, b_proj, (void*)out);
    }
}

// round 13
// speedup vs baseline: 5.8485x; 1.0163x over previous
#include <cuda_runtime.h>
#include <cuda_fp16.h>
#include <cstdint>
#include <math.h>

// ---------------- problem constants ----------------
#define BATCH 4
#define CDIM  384
#define HDIM  128
#define WDIM  128
#define HWPIX 16384
#define NPIX  65536
#define HEADS 12
#define HD    32
#define WS    8
#define NTOK  64
#define NWIN  1024
#define QKVC  1152

// ---------------- device scratch ----------------
__device__ __half g_qkvh[(size_t)NPIX * QKVC];
__device__ __half g_aoh[(size_t)NPIX * CDIM];
__device__ __half g_xTh[(size_t)NPIX * CDIM];
__device__ __half g_wbh[QKVC * CDIM];
__device__ float  g_bqkv[QKVC];
__device__ float  g_bias[HEADS * 225];
__device__ __half g_Wch[CDIM * CDIM];

// ---------------- helpers ----------------
__device__ __forceinline__ uint32_t smem_u32(const void* p) {
    uint32_t a;
    asm("{ .reg .u64 t; cvta.to.shared.u64 t, %1; cvt.u32.u64 %0, t; }" : "=r"(a) : "l"(p));
    return a;
}
__device__ __forceinline__ void cp16(uint32_t saddr, const void* g) {
    asm volatile("cp.async.cg.shared.global [%0], [%1], 16;" :: "r"(saddr), "l"(g));
}
#define CP_COMMIT() asm volatile("cp.async.commit_group;" ::: "memory")
#define CP_WAIT0()  asm volatile("cp.async.wait_group 0;" ::: "memory")
#define CP_WAIT1()  asm volatile("cp.async.wait_group 1;" ::: "memory")

__device__ __forceinline__ void ldm4(uint32_t* r, uint32_t addr) {
    asm volatile("ldmatrix.sync.aligned.m8n8.x4.shared.b16 {%0,%1,%2,%3}, [%4];"
        : "=r"(r[0]), "=r"(r[1]), "=r"(r[2]), "=r"(r[3]) : "r"(addr));
}

__device__ __forceinline__ void mma16(float* c, const uint32_t* a, const uint32_t* b) {
    asm volatile(
        "mma.sync.aligned.m16n8k16.row.col.f32.f16.f16.f32 "
        "{%0,%1,%2,%3}, {%4,%5,%6,%7}, {%8,%9}, {%0,%1,%2,%3};"
        : "+f"(c[0]), "+f"(c[1]), "+f"(c[2]), "+f"(c[3])
        : "r"(a[0]), "r"(a[1]), "r"(a[2]), "r"(a[3]),
          "r"(b[0]), "r"(b[1]));
}

// =================================================================
// unified prep kernel: xpose | wprep | wc | bias, 256 threads
// =================================================================
#define NB_XPOSE (512 * 12 * 4)
#define NB_WPREP ((QKVC * CDIM) / 256)
#define NB_WC    ((CDIM * CDIM) / 256)
#define NB_BIAS  225
#define NB_PREP  (NB_XPOSE + NB_WPREP + NB_WC + NB_BIAS)

__global__ void __launch_bounds__(256) prep_kernel(
        const float* __restrict__ x,
        const float* __restrict__ w_qk, const float* __restrict__ b_qk,
        const float* __restrict__ w_v,  const float* __restrict__ b_v,
        const float* __restrict__ w_proj, const float* __restrict__ w_po,
        const float* __restrict__ pcw, const float* __restrict__ psc,
        const float* __restrict__ mw1, const float* __restrict__ mb1,
        const float* __restrict__ mw2, const float* __restrict__ mb2) {
    __shared__ __align__(16) float tile[32][33];
    __shared__ __align__(16) float rel[CDIM];
    __shared__ __align__(16) float hid[128];
    __shared__ float part[256];
    int blk = blockIdx.x;
    int t = threadIdx.x;

    if (blk < NB_XPOSE) {
        int bx = blk & 511, by = (blk >> 9) % 12, bz = blk / (512 * 12);
        int tx = t & 31, ty = t >> 5;
        const float* src = x + ((size_t)(bz * CDIM + by * 32)) * HWPIX + bx * 32;
        #pragma unroll
        for (int i = 0; i < 32; i += 8)
            tile[ty + i][tx] = src[(size_t)(ty + i) * HWPIX + tx];
        __syncthreads();
        __half* dst = g_xTh + ((size_t)(bz * HWPIX + bx * 32)) * CDIM + by * 32;
        #pragma unroll
        for (int i = 0; i < 32; i += 8)
            dst[(size_t)(ty + i) * CDIM + tx] = __float2half_rn(tile[tx][ty + i]);
        return;
    }
    blk -= NB_XPOSE;
    if (blk < NB_WPREP) {
        int i = blk * 256 + t;
        float v = (i < 2 * CDIM * CDIM) ? w_qk[i] : w_v[i - 2 * CDIM * CDIM];
        g_wbh[i] = __float2half_rn(v);
        if (i < QKVC)
            g_bqkv[i] = (i < 2 * CDIM) ? b_qk[i] : b_v[i - 2 * CDIM];
        return;
    }
    blk -= NB_WPREP;
    if (blk < NB_WC) {
        int idx = blk * 256 + t;
        int o = idx / CDIM, c = idx - o * CDIM;
        const float* pr = w_proj + o * CDIM;
        float a0 = 0.f, a1 = 0.f, a2 = 0.f, a3 = 0.f;
        for (int k = 0; k < CDIM; k += 4) {
            a0 += pr[k] * w_po[k * CDIM + c];
            a1 += pr[k + 1] * w_po[(k + 1) * CDIM + c];
            a2 += pr[k + 2] * w_po[(k + 2) * CDIM + c];
            a3 += pr[k + 3] * w_po[(k + 3) * CDIM + c];
        }
        g_Wch[o * CDIM + c] = __float2half_rn((a0 + a1) + (a2 + a3));
        return;
    }
    blk -= NB_WC;
    {
        int idx = blk;
        float dx = (float)((idx % 15) - 7) * (2.0f / 7.0f);
        float dy = (float)((idx / 15) - 7) * (2.0f / 7.0f);
        int u = t & 127, hv2 = t >> 7;
        float sc = psc[0];
        for (int c = t; c < CDIM; c += 256)
            rel[c] = sc * (pcw[2 * c] * dx + pcw[2 * c + 1] * dy);
        __syncthreads();
        {
            float a0 = 0.f, a1 = 0.f, a2 = 0.f, a3 = 0.f;
            const float4* w = (const float4*)(mw1 + u * CDIM + hv2 * 192);
            const float4* r = (const float4*)(rel + hv2 * 192);
            #pragma unroll 4
            for (int c = 0; c < 48; c++) {
                float4 wv = w[c], rv = r[c];
                a0 += wv.x * rv.x; a1 += wv.y * rv.y;
                a2 += wv.z * rv.z; a3 += wv.w * rv.w;
            }
            part[t] = (a0 + a1) + (a2 + a3);
        }
        __syncthreads();
        if (t < 128) {
            float s = mb1[t] + part[t] + part[t + 128];
            hid[t] = 0.5f * s * (1.0f + erff(s * 0.70710678118654752f));
        }
        __syncthreads();
        if (t < HEADS) {
            float a0 = 0.f, a1 = 0.f, a2 = 0.f, a3 = 0.f;
            const float4* w2 = (const float4*)(mw2 + t * 128);
            const float4* hh = (const float4*)hid;
            #pragma unroll 4
            for (int j = 0; j < 32; j++) {
                float4 wv = w2[j], hvv = hh[j];
                a0 += wv.x * hvv.x; a1 += wv.y * hvv.y;
                a2 += wv.z * hvv.z; a3 += wv.w * hvv.w;
            }
            g_bias[t * 225 + idx] = mb2[t] + (a0 + a1) + (a2 + a3);
        }
    }
}

// =================================================================
// fp16 mma.sync GEMM with ldmatrix, 3-stage cp.async pipeline
// =================================================================
#define HP     72
#define KCH    64
#define NCH    6
#define NSTAGE 3
#define STAGE_H (2 * 128 * HP)                 // halves per stage (A+B)
#define GEMM_SMEM (NSTAGE * STAGE_H * 2)       // 110592 B

template <int MODE>
__global__ void __launch_bounds__(256) gemm_mma(
        const __half* __restrict__ Aptr, const __half* __restrict__ Bptr,
        const float* __restrict__ biasptr, void* __restrict__ outp) {
    extern __shared__ __align__(16) __half smh[];

    int tid = threadIdx.x;
    int n0 = blockIdx.x * 128;
    int m0 = blockIdx.y * 128;
    int lane = tid & 31, wid = tid >> 5;
    int wm = (wid & 3) * 32;
    int wn = (wid >> 2) * 64;

    const __half* Arow = Aptr + (size_t)m0 * CDIM;
    const __half* Brow = Bptr + (size_t)n0 * CDIM;
    uint32_t aU[NSTAGE], bU[NSTAGE];
    #pragma unroll
    for (int s = 0; s < NSTAGE; s++) {
        aU[s] = smem_u32(smh + s * STAGE_H);
        bU[s] = smem_u32(smh + s * STAGE_H + 128 * HP);
    }

    int ldrow = tid >> 3, ldseg = tid & 7;
    auto load_chunk = [&](int k0, int s) {
        #pragma unroll
        for (int i = 0; i < 4; i++) {
            int row = ldrow + i * 32;
            uint32_t so = (uint32_t)(row * HP + ldseg * 8) * 2;
            cp16(aU[s] + so, Arow + (size_t)row * CDIM + k0 + ldseg * 8);
            cp16(bU[s] + so, Brow + (size_t)row * CDIM + k0 + ldseg * 8);
        }
        CP_COMMIT();
    };

    float acc[2][8][4];
    #pragma unroll
    for (int mt = 0; mt < 2; mt++)
        #pragma unroll
        for (int nt = 0; nt < 8; nt++)
            #pragma unroll
            for (int j = 0; j < 4; j++) acc[mt][nt][j] = 0.f;

    load_chunk(0, 0);
    load_chunk(KCH, 1);

    int lr = lane & 7, g = lane >> 3;
    int arow[2];
    arow[0] = wm + (g & 1) * 8 + lr;
    arow[1] = wm + 16 + (g & 1) * 8 + lr;
    int akoff = (g >> 1) * 8;
    int brow[4];
    #pragma unroll
    for (int q = 0; q < 4; q++)
        brow[q] = wn + (2 * q + (g >> 1)) * 8 + lr;
    int bkoff = (g & 1) * 8;

    int r4 = lane >> 2, c4 = lane & 3;
    for (int i = 0; i < NCH; i++) {
        if (i + 1 < NCH) CP_WAIT1(); else CP_WAIT0();
        __syncthreads();
        if (i + 2 < NCH) load_chunk((i + 2) * KCH, (i + 2) % NSTAGE);
        int s = i % NSTAGE;
        uint32_t aBase = aU[s];
        uint32_t bBase = bU[s];
        #pragma unroll
        for (int kk = 0; kk < 4; kk++) {
            int kb = kk * 16;
            uint32_t a[2][4];
            #pragma unroll
            for (int mt = 0; mt < 2; mt++)
                ldm4(a[mt], aBase + (uint32_t)(arow[mt] * HP + kb + akoff) * 2);
            uint32_t b[8][2];
            #pragma unroll
            for (int q = 0; q < 4; q++) {
                uint32_t r[4];
                ldm4(r, bBase + (uint32_t)(brow[q] * HP + kb + bkoff) * 2);
                b[2 * q][0] = r[0]; b[2 * q][1] = r[1];
                b[2 * q + 1][0] = r[2]; b[2 * q + 1][1] = r[3];
            }
            #pragma unroll
            for (int mt = 0; mt < 2; mt++)
                #pragma unroll
                for (int nt = 0; nt < 8; nt++)
                    mma16(acc[mt][nt], a[mt], b[nt]);
        }
    }

    int cb = c4 * 2;
    if (MODE == 0) {
        __half* oph = (__half*)outp;
        #pragma unroll
        for (int mt = 0; mt < 2; mt++)
            #pragma unroll
            for (int half = 0; half < 2; half++) {
                int m = m0 + wm + mt * 16 + r4 + half * 8;
                __half* dst = oph + (size_t)m * QKVC + n0 + wn;
                #pragma unroll
                for (int nt = 0; nt < 8; nt++) {
                    int o = n0 + wn + nt * 8 + cb;
                    *(__half2*)(dst + nt * 8 + cb) = __floats2half2_rn(
                        acc[mt][nt][half * 2 + 0] + biasptr[o],
                        acc[mt][nt][half * 2 + 1] + biasptr[o + 1]);
                }
            }
    } else {
        float* opf = (float*)outp;
        int b = m0 >> 14;
        int ppb = m0 & (HWPIX - 1);
        #pragma unroll
        for (int mt = 0; mt < 2; mt++)
            #pragma unroll
            for (int half = 0; half < 2; half++) {
                int pp = ppb + wm + mt * 16 + r4 + half * 8;
                #pragma unroll
                for (int nt = 0; nt < 8; nt++)
                    #pragma unroll
                    for (int j = 0; j < 2; j++) {
                        int o = n0 + wn + nt * 8 + cb + j;
                        opf[((size_t)(b * CDIM + o)) * HWPIX + pp] =
                            acc[mt][nt][half * 2 + j] + biasptr[o];
                    }
            }
    }
}

// =================================================================
// PDSCA helpers on half tiles (pitch 40 halves per token row)
// =================================================================
__device__ __forceinline__ void ld8h(const __half* base, float* r) {
    union { int4 i; __half2 h[4]; } u;
    u.i = *(const int4*)base;
    float2 f0 = __half22float2(u.h[0]), f1 = __half22float2(u.h[1]);
    float2 f2 = __half22float2(u.h[2]), f3 = __half22float2(u.h[3]);
    r[0] = f0.x; r[1] = f0.y; r[2] = f1.x; r[3] = f1.y;
    r[4] = f2.x; r[5] = f2.y; r[6] = f3.x; r[7] = f3.y;
}

__device__ __forceinline__ void conv33h(
        const __half* xs, const float* __restrict__ dw_w,
        const float* __restrict__ dw_b, int it, float* o8) {
    int c = it >> 3, sy = it & 7;
    float rm[10], rc[10], rp[10];
    #pragma unroll
    for (int i = 0; i < 10; i++) { rm[i] = 0.f; rc[i] = 0.f; rp[i] = 0.f; }
    ld8h(xs + (2 * c + (sy >> 2)) * 40 + (sy & 3) * 8, rc + 1);
    if (sy > 0) {
        int r = sy - 1;
        ld8h(xs + (2 * c + (r >> 2)) * 40 + (r & 3) * 8, rm + 1);
    }
    if (sy < 7) {
        int r = sy + 1;
        ld8h(xs + (2 * c + (r >> 2)) * 40 + (r & 3) * 8, rp + 1);
    }
    const float* wp = dw_w + c * 9;
    float w0 = wp[0], w1 = wp[1], w2 = wp[2];
    float w3 = wp[3], w4 = wp[4], w5 = wp[5];
    float w6 = wp[6], w7 = wp[7], w8 = wp[8];
    float bias = dw_b[c];
    #pragma unroll
    for (int ix = 0; ix < 8; ix++) {
        float s = bias;
        s += w0 * rm[ix] + w1 * rm[ix + 1] + w2 * rm[ix + 2];
        s += w3 * rc[ix] + w4 * rc[ix + 1] + w5 * rc[ix + 2];
        s += w6 * rp[ix] + w7 * rp[ix + 1] + w8 * rp[ix + 2];
        o8[ix] = s;
    }
}

__device__ __forceinline__ void gate_apply_h(
        __half* xs, const float* o8, float cav, int it) {
    int c = it >> 3, sy = it & 7;
    __half* base = xs + (2 * c + (sy >> 2)) * 40 + (sy & 3) * 8;
    float xv[8];
    ld8h(base, xv);
    union { int4 i; __half2 h[4]; } u;
    #pragma unroll
    for (int p = 0; p < 4; p++) {
        float g0 = 1.0f / (1.0f + __expf(-(o8[2 * p] + cav)));
        float g1 = 1.0f / (1.0f + __expf(-(o8[2 * p + 1] + cav)));
        u.h[p] = __floats2half2_rn(xv[2 * p] * g0, xv[2 * p + 1] * g1);
    }
    *(int4*)base = u.i;
}

// =================================================================
// per-(window, head) merged PDSCA(Q,K) + attention — all-fp16 tiles
// =================================================================
__global__ void __launch_bounds__(128) attn_kernel(
        const float* __restrict__ log_temp,
        const float* __restrict__ pqw,  const float* __restrict__ pqb,
        const float* __restrict__ pqf1w, const float* __restrict__ pqf1b,
        const float* __restrict__ pqf2w, const float* __restrict__ pqf2b,
        const float* __restrict__ pkw,  const float* __restrict__ pkb,
        const float* __restrict__ pkf1w, const float* __restrict__ pkf1b,
        const float* __restrict__ pkf2w, const float* __restrict__ pkf2b) {
    __shared__ __align__(16) __half qsh[NTOK * 40];
    __shared__ __align__(16) __half ksh[NTOK * 40];
    __shared__ __align__(16) __half vsTh[HD * 72];
    __shared__ __align__(16) __half ath[NTOK * 72];
    __shared__ float gapq[32], gapk[32], hidq[8], hidk[8], caq[32], cak[32];

    int bi  = blockIdx.x;
    int win = bi / HEADS;
    int h   = bi - win * HEADS;
    int t   = threadIdx.x;
    int b   = win >> 8, hb = (win >> 4) & 15, wb = win & 15;
    int pbase = b * HWPIX + hb * 8 * WDIM + wb * 8;

    for (int tt = t; tt < 256; tt += 128) {
        int n = tt >> 2, d8 = (tt & 3) * 8;
        int p = pbase + (n >> 3) * WDIM + (n & 7);
        const __half* src = g_qkvh + (size_t)p * QKVC + h * HD + d8;
        int4 qi = *(const int4*)(src);
        int4 ki = *(const int4*)(src + CDIM);
        union { int4 i; __half hh[8]; } uv;
        uv.i = *(const int4*)(src + 2 * CDIM);
        *(int4*)&qsh[n * 40 + d8] = qi;
        *(int4*)&ksh[n * 40 + d8] = ki;
        #pragma unroll
        for (int i = 0; i < 8; i++)
            vsTh[(d8 + i) * 72 + n] = uv.hh[i];
    }
    __syncthreads();

    float ocq[2][8], ock[2][8];
    conv33h(qsh, pqw, pqb, t, ocq[0]);
    conv33h(qsh, pqw, pqb, t + 128, ocq[1]);
    conv33h(ksh, pkw, pkb, t, ock[0]);
    conv33h(ksh, pkw, pkb, t + 128, ock[1]);
    if (t < 32) {
        float r0[8], r1[8], s = 0.f;
        #pragma unroll
        for (int i = 0; i < 4; i++) {
            ld8h(qsh + (2 * t) * 40 + i * 8, r0);
            ld8h(qsh + (2 * t + 1) * 40 + i * 8, r1);
            #pragma unroll
            for (int j = 0; j < 8; j++) s += r0[j] + r1[j];
        }
        gapq[t] = s * (1.0f / 64.0f);
    } else if (t >= 64 && t < 96) {
        int c = t - 64;
        float r0[8], r1[8], s = 0.f;
        #pragma unroll
        for (int i = 0; i < 4; i++) {
            ld8h(ksh + (2 * c) * 40 + i * 8, r0);
            ld8h(ksh + (2 * c + 1) * 40 + i * 8, r1);
            #pragma unroll
            for (int j = 0; j < 8; j++) s += r0[j] + r1[j];
        }
        gapk[c] = s * (1.0f / 64.0f);
    }
    __syncthreads();
    if (t < 8) {
        float s = pqf1b[t];
        #pragma unroll
        for (int c = 0; c < 32; c++) s += gapq[c] * pqf1w[t * 32 + c];
        hidq[t] = fmaxf(s, 0.f);
    } else if (t >= 64 && t < 72) {
        int u = t - 64;
        float s = pkf1b[u];
        #pragma unroll
        for (int c = 0; c < 32; c++) s += gapk[c] * pkf1w[u * 32 + c];
        hidk[u] = fmaxf(s, 0.f);
    }
    __syncthreads();
    if (t < 32) {
        float s = pqf2b[t];
        #pragma unroll
        for (int j = 0; j < 8; j++) s += hidq[j] * pqf2w[t * 8 + j];
        caq[t] = s;
    } else if (t >= 64 && t < 96) {
        int c = t - 64;
        float s = pkf2b[c];
        #pragma unroll
        for (int j = 0; j < 8; j++) s += hidk[j] * pkf2w[c * 8 + j];
        cak[c] = s;
    }
    __syncthreads();
    gate_apply_h(qsh, ocq[0], caq[t >> 3], t);
    gate_apply_h(qsh, ocq[1], caq[(t + 128) >> 3], t + 128);
    gate_apply_h(ksh, ock[0], cak[t >> 3], t);
    gate_apply_h(ksh, ock[1], cak[(t + 128) >> 3], t + 128);
    __syncthreads();

    int lane = t & 31, w = t >> 5;
    int r4 = lane >> 2, c4 = lane & 3;
    int m0 = w * 16;
    int lr = lane & 7, g = lane >> 3;
    int arow = m0 + (g & 1) * 8 + lr;
    int akoff = (g >> 1) * 8;
    int bkoff = (g & 1) * 8;
    uint32_t qB = smem_u32(qsh), kB = smem_u32(ksh);
    uint32_t vB = smem_u32(vsTh), pB = smem_u32(ath);

    float sacc[8][4];
    #pragma unroll
    for (int nt = 0; nt < 8; nt++)
        #pragma unroll
        for (int j = 0; j < 4; j++) sacc[nt][j] = 0.f;

    #pragma unroll
    for (int kk = 0; kk < 2; kk++) {
        int kb = kk * 16;
        uint32_t a[4];
        ldm4(a, qB + (uint32_t)(arow * 40 + kb + akoff) * 2);
        #pragma unroll
        for (int q = 0; q < 4; q++) {
            int nrow = (2 * q + (g >> 1)) * 8 + lr;
            uint32_t r[4];
            ldm4(r, kB + (uint32_t)(nrow * 40 + kb + bkoff) * 2);
            mma16(sacc[2 * q], a, r);
            mma16(sacc[2 * q + 1], a, r + 2);
        }
    }

    float temp = __expf(log_temp[0]);
    const float* brow2 = g_bias + h * 225;
    int r_lo = m0 + r4, r_hi = r_lo + 8;
    int ylo = r_lo >> 3, xlo = r_lo & 7;
    int yhi = r_hi >> 3, xhi = r_hi & 7;

    float mlo = -1e30f, mhi = -1e30f;
    #pragma unroll
    for (int nt = 0; nt < 8; nt++)
        #pragma unroll
        for (int j = 0; j < 2; j++) {
            int col = nt * 8 + 2 * c4 + j;
            int cy = col >> 3, cx = col & 7;
            float blo = brow2[(ylo - cy + 7) * 15 + (xlo - cx + 7)];
            float bhi = brow2[(yhi - cy + 7) * 15 + (xhi - cx + 7)];
            sacc[nt][j]     = sacc[nt][j] * temp + blo;
            sacc[nt][2 + j] = sacc[nt][2 + j] * temp + bhi;
            mlo = fmaxf(mlo, sacc[nt][j]);
            mhi = fmaxf(mhi, sacc[nt][2 + j]);
        }
    mlo = fmaxf(mlo, __shfl_xor_sync(0xffffffffu, mlo, 1));
    mlo = fmaxf(mlo, __shfl_xor_sync(0xffffffffu, mlo, 2));
    mhi = fmaxf(mhi, __shfl_xor_sync(0xffffffffu, mhi, 1));
    mhi = fmaxf(mhi, __shfl_xor_sync(0xffffffffu, mhi, 2));

    float slo = 0.f, shi = 0.f;
    #pragma unroll
    for (int nt = 0; nt < 8; nt++)
        #pragma unroll
        for (int j = 0; j < 2; j++) {
            float e0 = __expf(sacc[nt][j] - mlo);
            float e1 = __expf(sacc[nt][2 + j] - mhi);
            sacc[nt][j] = e0; sacc[nt][2 + j] = e1;
            slo += e0; shi += e1;
        }
    slo += __shfl_xor_sync(0xffffffffu, slo, 1);
    slo += __shfl_xor_sync(0xffffffffu, slo, 2);
    shi += __shfl_xor_sync(0xffffffffu, shi, 1);
    shi += __shfl_xor_sync(0xffffffffu, shi, 2);
    float ilo = 1.0f / slo, ihi = 1.0f / shi;

    #pragma unroll
    for (int nt = 0; nt < 8; nt++) {
        int col = nt * 8 + 2 * c4;
        *(__half2*)&ath[r_lo * 72 + col] =
            __floats2half2_rn(sacc[nt][0] * ilo, sacc[nt][1] * ilo);
        *(__half2*)&ath[r_hi * 72 + col] =
            __floats2half2_rn(sacc[nt][2] * ihi, sacc[nt][3] * ihi);
    }
    __syncwarp();

    float oacc[4][4];
    #pragma unroll
    for (int nt = 0; nt < 4; nt++)
        #pragma unroll
        for (int j = 0; j < 4; j++) oacc[nt][j] = 0.f;

    #pragma unroll
    for (int kk = 0; kk < 4; kk++) {
        int kb = kk * 16;
        uint32_t a[4];
        ldm4(a, pB + (uint32_t)(arow * 72 + kb + akoff) * 2);
        #pragma unroll
        for (int q = 0; q < 2; q++) {
            int nrow = (2 * q + (g >> 1)) * 8 + lr;
            uint32_t r[4];
            ldm4(r, vB + (uint32_t)(nrow * 72 + kb + bkoff) * 2);
            mma16(oacc[2 * q], a, r);
            mma16(oacc[2 * q + 1], a, r + 2);
        }
    }

    #pragma unroll
    for (int half = 0; half < 2; half++) {
        int row = (half == 0) ? r_lo : r_hi;
        int p = pbase + (row >> 3) * WDIM + (row & 7);
        __half2* dst = (__half2*)(g_aoh + (size_t)p * CDIM + h * HD);
        #pragma unroll
        for (int nt = 0; nt < 4; nt++)
            dst[(nt * 8 + 2 * c4) >> 1] =
                __floats2half2_rn(oacc[nt][half * 2 + 0], oacc[nt][half * 2 + 1]);
    }
}

// =================================================================
// launch
// =================================================================
extern "C" void kernel_launch(void* const* d_in, const int* in_sizes, int n_in,
                              void* d_out, int out_size) {
    const float* x        = (const float*)d_in[0];
    const float* w_qk     = (const float*)d_in[1];
    const float* b_qk     = (const float*)d_in[2];
    const float* w_v      = (const float*)d_in[3];
    const float* b_v      = (const float*)d_in[4];
    const float* log_temp = (const float*)d_in[5];
    const float* pq_dw_w  = (const float*)d_in[6];
    const float* pq_dw_b  = (const float*)d_in[7];
    const float* pq_f1w   = (const float*)d_in[8];
    const float* pq_f1b   = (const float*)d_in[9];
    const float* pq_f2w   = (const float*)d_in[10];
    const float* pq_f2b   = (const float*)d_in[11];
    const float* pk_dw_w  = (const float*)d_in[12];
    const float* pk_dw_b  = (const float*)d_in[13];
    const float* pk_f1w   = (const float*)d_in[14];
    const float* pk_f1b   = (const float*)d_in[15];
    const float* pk_f2w   = (const float*)d_in[16];
    const float* pk_f2b   = (const float*)d_in[17];
    const float* pos_w    = (const float*)d_in[18];
    const float* pos_sc   = (const float*)d_in[20];
    const float* meta_w1  = (const float*)d_in[21];
    const float* meta_b1  = (const float*)d_in[22];
    const float* meta_w2  = (const float*)d_in[23];
    const float* meta_b2  = (const float*)d_in[24];
    const float* w_po     = (const float*)d_in[25];
    const float* w_proj   = (const float*)d_in[26];
    const float* b_proj   = (const float*)d_in[27];
    float* out = (float*)d_out;

    cudaFuncSetAttribute(gemm_mma<0>, cudaFuncAttributeMaxDynamicSharedMemorySize, GEMM_SMEM);
    cudaFuncSetAttribute(gemm_mma<1>, cudaFuncAttributeMaxDynamicSharedMemorySize, GEMM_SMEM);

    prep_kernel<<<NB_PREP, 256>>>(x, w_qk, b_qk, w_v, b_v, w_proj, w_po,
                                  pos_w, pos_sc, meta_w1, meta_b1, meta_w2, meta_b2);

    {
        const __half* A; cudaGetSymbolAddress((void**)&A, g_xTh);
        const __half* Bp; cudaGetSymbolAddress((void**)&Bp, g_wbh);
        const float* bb; cudaGetSymbolAddress((void**)&bb, g_bqkv);
        void* op; cudaGetSymbolAddress(&op, g_qkvh);
        gemm_mma<0><<<dim3(QKVC / 128, NPIX / 128), 256, GEMM_SMEM>>>(A, Bp, bb, op);
    }

    attn_kernel<<<NWIN * HEADS, 128>>>(log_temp,
        pq_dw_w, pq_dw_b, pq_f1w, pq_f1b, pq_f2w, pq_f2b,
        pk_dw_w, pk_dw_b, pk_f1w, pk_f1b, pk_f2w, pk_f2b);

    {
        const __half* A; cudaGetSymbolAddress((void**)&A, g_aoh);
        const __half* Bp; cudaGetSymbolAddress((void**)&Bp, g_Wch);
        gemm_mma<1><<<dim3(CDIM / 128, NPIX / 128), 256, GEMM_SMEM>>>(A, Bp, b_proj, (void*)out);
    }
}